// round 3
// baseline (speedup 1.0000x reference)
#include <cuda_runtime.h>
#include <math.h>

#define DEPTHL 12
#define DM     768
#define NT     1024
#define BT     2
#define RR     (BT*NT)      // 2048 rows
#define HIDF   3072
#define NHEADS 12
#define DHD    64

// ---------------- scratch (static device globals; no allocation) ----------------
__device__ float g_xp[RR*DM];
__device__ float g_t[RR*DM];
__device__ float g_h[RR*DM];
__device__ float g_qkv[RR*3*DM];
__device__ float g_attn[RR*DM];
__device__ float g_mlp[RR*HIDF];
__device__ float g_fpn[RR*DM];

// ---------------- patchify: x[B,3,512,512] -> xp[B*N, 768] ----------------
__global__ void patchify_kernel(const float* __restrict__ x, float* __restrict__ xp) {
    int idx = blockIdx.x * 256 + threadIdx.x;
    if (idx >= RR*DM) return;
    int col = idx % DM;
    int r   = idx / DM;
    int b   = r >> 10, n = r & 1023;
    int gy  = n >> 5,  gx = n & 31;
    int c   = col >> 8;
    int rem = col & 255;
    int py  = rem >> 4, px = rem & 15;
    // x[b][c][gy*16+py][gx*16+px]
    xp[idx] = x[((size_t)(b*3 + c)*512 + (gy*16 + py))*512 + (gx*16 + px)];
}

// ---------------- generic SGEMM: C = A[M,K] @ W[K,N] + bias, fused epilogues ----
// MODE 0: +bias    MODE 1: +bias+res[r,n]   MODE 2: +bias, exact GELU
// MODE 3: +bias + res[(r%1024), n]  (pos-embed broadcast over batch)
// BM=64, BN=128, BK=16, 128 threads, 8x8 per-thread tile, double-buffered smem.
template<int MODE>
__global__ void __launch_bounds__(128)
sgemm_kernel(const float* __restrict__ A, const float* __restrict__ W,
             const float* __restrict__ bias, const float* res, float* C,
             int M, int N, int K)
{
    __shared__ float As[2][16][64];
    __shared__ float Bs[2][16][128];
    const int tid = threadIdx.x;
    const int m0  = blockIdx.y * 64;
    const int n0  = blockIdx.x * 128;
    const int tx  = tid & 15, ty = tid >> 4;

    float acc[8][8];
#pragma unroll
    for (int i = 0; i < 8; i++)
#pragma unroll
        for (int j = 0; j < 8; j++) acc[i][j] = 0.f;

    const int KT = K >> 4;
    float4 aReg[2];
    float  bReg[16];

    auto loadG = [&](int kt) {
#pragma unroll
        for (int l = 0; l < 2; l++) {
            int lin = tid*2 + l;
            int arow = lin >> 2, kq = lin & 3;
            aReg[l] = *(const float4*)(A + (size_t)(m0 + arow)*K + kt*16 + kq*4);
        }
#pragma unroll
        for (int l = 0; l < 16; l++) {
            int lin = tid + l*128;
            int kr = lin >> 7, col = lin & 127;
            int n  = n0 + col;
            bReg[l] = (n < N) ? W[(size_t)(kt*16 + kr)*N + n] : 0.f;
        }
    };
    auto storeS = [&](int buf) {
#pragma unroll
        for (int l = 0; l < 2; l++) {
            int lin = tid*2 + l;
            int arow = lin >> 2, kq = lin & 3;
            As[buf][kq*4+0][arow] = aReg[l].x;
            As[buf][kq*4+1][arow] = aReg[l].y;
            As[buf][kq*4+2][arow] = aReg[l].z;
            As[buf][kq*4+3][arow] = aReg[l].w;
        }
#pragma unroll
        for (int l = 0; l < 16; l++) {
            int lin = tid + l*128;
            int kr = lin >> 7, col = lin & 127;
            Bs[buf][kr][col] = bReg[l];
        }
    };

    loadG(0);
    storeS(0);
    __syncthreads();
    int buf = 0;
    for (int kt = 0; kt < KT; kt++) {
        if (kt + 1 < KT) loadG(kt + 1);
#pragma unroll
        for (int k = 0; k < 16; k++) {
            float a[8], bb[8];
            float4 t0 = *(const float4*)&As[buf][k][ty*8];
            float4 t1 = *(const float4*)&As[buf][k][ty*8 + 4];
            a[0]=t0.x; a[1]=t0.y; a[2]=t0.z; a[3]=t0.w;
            a[4]=t1.x; a[5]=t1.y; a[6]=t1.z; a[7]=t1.w;
            float4 u0 = *(const float4*)&Bs[buf][k][tx*8];
            float4 u1 = *(const float4*)&Bs[buf][k][tx*8 + 4];
            bb[0]=u0.x; bb[1]=u0.y; bb[2]=u0.z; bb[3]=u0.w;
            bb[4]=u1.x; bb[5]=u1.y; bb[6]=u1.z; bb[7]=u1.w;
#pragma unroll
            for (int i = 0; i < 8; i++)
#pragma unroll
                for (int j = 0; j < 8; j++)
                    acc[i][j] += a[i]*bb[j];
        }
        if (kt + 1 < KT) storeS(buf ^ 1);
        __syncthreads();
        buf ^= 1;
    }

#pragma unroll
    for (int i = 0; i < 8; i++) {
        int r = m0 + ty*8 + i;
#pragma unroll
        for (int j = 0; j < 8; j++) {
            int n = n0 + tx*8 + j;
            if (n < N) {
                float v = acc[i][j] + bias[n];
                if (MODE == 1) v += res[(size_t)r*N + n];
                if (MODE == 3) v += res[(size_t)(r & (NT-1))*N + n];
                if (MODE == 2) v = 0.5f*v*(1.f + erff(v*0.70710678118654752f));
                C[(size_t)r*N + n] = v;
            }
        }
    }
}

// ---------------- layernorm: row length 768, one block per row ----------------
__global__ void __launch_bounds__(256)
ln_kernel(const float* __restrict__ x, const float* __restrict__ w,
          const float* __restrict__ b, float* __restrict__ y)
{
    __shared__ float red[8];
    __shared__ float sMean, sRstd;
    int r = blockIdx.x, tid = threadIdx.x;
    const float* xr = x + (size_t)r*DM;
    float v0 = xr[tid], v1 = xr[tid+256], v2 = xr[tid+512];

    float s = v0 + v1 + v2;
#pragma unroll
    for (int o = 16; o > 0; o >>= 1) s += __shfl_xor_sync(0xffffffffu, s, o);
    if ((tid & 31) == 0) red[tid >> 5] = s;
    __syncthreads();
    if (tid == 0) {
        float t = 0.f;
#pragma unroll
        for (int i = 0; i < 8; i++) t += red[i];
        sMean = t * (1.f/768.f);
    }
    __syncthreads();
    float mean = sMean;
    float d0 = v0-mean, d1 = v1-mean, d2 = v2-mean;

    float q = d0*d0 + d1*d1 + d2*d2;
#pragma unroll
    for (int o = 16; o > 0; o >>= 1) q += __shfl_xor_sync(0xffffffffu, q, o);
    if ((tid & 31) == 0) red[tid >> 5] = q;
    __syncthreads();
    if (tid == 0) {
        float t = 0.f;
#pragma unroll
        for (int i = 0; i < 8; i++) t += red[i];
        sRstd = rsqrtf(t * (1.f/768.f) + 1e-5f);
    }
    __syncthreads();
    float rstd = sRstd;
    float* yr = y + (size_t)r*DM;
    yr[tid]     = d0*rstd*w[tid]     + b[tid];
    yr[tid+256] = d1*rstd*w[tid+256] + b[tid+256];
    yr[tid+512] = d2*rstd*w[tid+512] + b[tid+512];
}

// ---------------- fused flash attention (fp32, online softmax) ----------------
// grid (B*H, N/64), block 64: 1 thread = 1 query row, K/V tiles in smem.
__global__ void __launch_bounds__(64)
flash_attn_kernel(const float* __restrict__ qkv, float* __restrict__ out)
{
    __shared__ float Ks[64][64];
    __shared__ float Vs[64][64];
    const int bh = blockIdx.x;
    const int b  = bh / NHEADS, h = bh % NHEADS;
    const int tid = threadIdx.x;
    const int row = b*NT + blockIdx.y*64 + tid;

    float q[64], o[64];
    const float4* qp = (const float4*)(qkv + (size_t)row*(3*DM) + h*DHD);
#pragma unroll
    for (int i = 0; i < 16; i++) {
        float4 v = qp[i];
        q[4*i]=v.x; q[4*i+1]=v.y; q[4*i+2]=v.z; q[4*i+3]=v.w;
    }
#pragma unroll
    for (int i = 0; i < 64; i++) o[i] = 0.f;
    float m = -3.0e38f, l = 0.f;

    for (int kt = 0; kt < NT/64; kt++) {
        __syncthreads();
        int base = b*NT + kt*64;
        for (int lin = tid; lin < 1024; lin += 64) {
            int j = lin >> 4, qd = lin & 15;
            const float* kr = qkv + (size_t)(base + j)*(3*DM) + h*DHD;
            *(float4*)&Ks[j][qd*4] = *(const float4*)(kr + DM   + qd*4);
            *(float4*)&Vs[j][qd*4] = *(const float4*)(kr + 2*DM + qd*4);
        }
        __syncthreads();
        for (int j = 0; j < 64; j++) {
            float s0=0.f, s1=0.f, s2=0.f, s3=0.f;
#pragma unroll
            for (int d = 0; d < 64; d += 4) {
                s0 += q[d  ]*Ks[j][d  ];
                s1 += q[d+1]*Ks[j][d+1];
                s2 += q[d+2]*Ks[j][d+2];
                s3 += q[d+3]*Ks[j][d+3];
            }
            float s = ((s0+s1)+(s2+s3)) * 0.125f;   // DH^-0.5
            if (s > m) {
                float c = __expf(m - s);
                m = s; l *= c;
#pragma unroll
                for (int d = 0; d < 64; d++) o[d] *= c;
            }
            float p = __expf(s - m);
            l += p;
#pragma unroll
            for (int d = 0; d < 64; d++) o[d] += p * Vs[j][d];
        }
    }
    float inv = 1.f / l;
    float4* op = (float4*)(out + (size_t)row*DM + h*DHD);
#pragma unroll
    for (int i = 0; i < 16; i++) {
        float4 v;
        v.x=o[4*i]*inv; v.y=o[4*i+1]*inv; v.z=o[4*i+2]*inv; v.w=o[4*i+3]*inv;
        op[i] = v;
    }
}

// ---------------- FPN transpose + clamped bilinear resize (JAX half-pixel) ----
// g is [B, 32, 32, C] row-major; out is [B, C, TS, TS].
__global__ void fpn_resize_kernel(const float* __restrict__ g, float* __restrict__ out,
                                  int C, int TS)
{
    int idx = blockIdx.x * 256 + threadIdx.x;
    int total = BT*C*TS*TS;
    if (idx >= total) return;
    int xq = idx % TS;
    int yq = (idx / TS) % TS;
    int c  = (idx / (TS*TS)) % C;
    int b  = idx / (TS*TS*C);
    float s  = 32.0f / (float)TS;
    float sy = ((float)yq + 0.5f)*s - 0.5f;
    float sx = ((float)xq + 0.5f)*s - 0.5f;
    int y0 = (int)floorf(sy); float fy = sy - (float)y0;
    int x0 = (int)floorf(sx); float fx = sx - (float)x0;
    int y0c = min(31, max(0, y0)),   y1c = min(31, max(0, y0+1));
    int x0c = min(31, max(0, x0)),   x1c = min(31, max(0, x0+1));
    const float* gb = g + (size_t)b*1024*C;
    float p00 = gb[(y0c*32 + x0c)*C + c];
    float p01 = gb[(y0c*32 + x1c)*C + c];
    float p10 = gb[(y1c*32 + x0c)*C + c];
    float p11 = gb[(y1c*32 + x1c)*C + c];
    out[idx] = (1.f-fy)*((1.f-fx)*p00 + fx*p01) + fy*((1.f-fx)*p10 + fx*p11);
}

// ---------------- host launcher ----------------
extern "C" void kernel_launch(void* const* d_in, const int* in_sizes, int n_in,
                              void* d_out, int out_size)
{
    (void)in_sizes; (void)n_in; (void)out_size;
    const float* x       = (const float*)d_in[0];
    const float* patch_w = (const float*)d_in[1];
    const float* patch_b = (const float*)d_in[2];
    const float* pos     = (const float*)d_in[3];
    const float* ln1_w   = (const float*)d_in[4];
    const float* ln1_b   = (const float*)d_in[5];
    const float* qkv_w   = (const float*)d_in[6];
    const float* qkv_b   = (const float*)d_in[7];
    const float* proj_w  = (const float*)d_in[8];
    const float* proj_b  = (const float*)d_in[9];
    const float* ln2_w   = (const float*)d_in[10];
    const float* ln2_b   = (const float*)d_in[11];
    const float* fc1_w   = (const float*)d_in[12];
    const float* fc1_b   = (const float*)d_in[13];
    const float* fc2_w   = (const float*)d_in[14];
    const float* fc2_b   = (const float*)d_in[15];
    const float* norm_w  = (const float*)d_in[16];
    const float* norm_b  = (const float*)d_in[17];
    const float* fpn_w[4] = {(const float*)d_in[18], (const float*)d_in[20],
                             (const float*)d_in[22], (const float*)d_in[24]};
    const float* fpn_b[4] = {(const float*)d_in[19], (const float*)d_in[21],
                             (const float*)d_in[23], (const float*)d_in[25]};
    float* out = (float*)d_out;

    static float *p_xp = nullptr, *p_t, *p_h, *p_qkv, *p_attn, *p_mlp, *p_fpn;
    if (!p_xp) {  // pointer lookup only; first call happens outside graph capture
        cudaGetSymbolAddress((void**)&p_xp,   g_xp);
        cudaGetSymbolAddress((void**)&p_t,    g_t);
        cudaGetSymbolAddress((void**)&p_h,    g_h);
        cudaGetSymbolAddress((void**)&p_qkv,  g_qkv);
        cudaGetSymbolAddress((void**)&p_attn, g_attn);
        cudaGetSymbolAddress((void**)&p_mlp,  g_mlp);
        cudaGetSymbolAddress((void**)&p_fpn,  g_fpn);
    }

    // patch embed: t = xp @ patch_w + patch_b + pos_embed
    patchify_kernel<<<(RR*DM + 255)/256, 256>>>(x, p_xp);
    sgemm_kernel<3><<<dim3(6, 32), 128>>>(p_xp, patch_w, patch_b, pos, p_t, RR, DM, DM);

    static const size_t off[4] = {0, 3145728, 4718592, 5505024};

    for (int i = 0; i < DEPTHL; i++) {
        ln_kernel<<<RR, 256>>>(p_t, ln1_w + i*DM, ln1_b + i*DM, p_h);
        sgemm_kernel<0><<<dim3(18, 32), 128>>>(p_h, qkv_w + (size_t)i*DM*3*DM,
                                               qkv_b + (size_t)i*3*DM, nullptr,
                                               p_qkv, RR, 3*DM, DM);
        flash_attn_kernel<<<dim3(BT*NHEADS, NT/64), 64>>>(p_qkv, p_attn);
        sgemm_kernel<1><<<dim3(6, 32), 128>>>(p_attn, proj_w + (size_t)i*DM*DM,
                                              proj_b + (size_t)i*DM, p_t, p_t, RR, DM, DM);
        ln_kernel<<<RR, 256>>>(p_t, ln2_w + i*DM, ln2_b + i*DM, p_h);
        sgemm_kernel<2><<<dim3(24, 32), 128>>>(p_h, fc1_w + (size_t)i*DM*HIDF,
                                               fc1_b + (size_t)i*HIDF, nullptr,
                                               p_mlp, RR, HIDF, DM);
        sgemm_kernel<1><<<dim3(6, 32), 128>>>(p_mlp, fc2_w + (size_t)i*HIDF*DM,
                                              fc2_b + (size_t)i*DM, p_t, p_t, RR, DM, HIDF);

        int e = (i == 3) ? 0 : (i == 6) ? 1 : (i == 9) ? 2 : (i == 11) ? 3 : -1;
        if (e >= 0) {
            int oc = 96 << e, ts = 128 >> e;
            ln_kernel<<<RR, 256>>>(p_t, norm_w, norm_b, p_h);
            sgemm_kernel<0><<<dim3((oc + 127)/128, 32), 128>>>(p_h, fpn_w[e], fpn_b[e],
                                                               nullptr, p_fpn, RR, oc, DM);
            int total = BT*oc*ts*ts;
            fpn_resize_kernel<<<(total + 255)/256, 256>>>(p_fpn, out + off[e], oc, ts);
        }
    }
}

// round 8
// speedup vs baseline: 1.7482x; 1.7482x over previous
#include <cuda_runtime.h>
#include <math.h>
#include <stdint.h>

#define DEPTHL 12
#define DM     768
#define NT     1024
#define BT     2
#define RR     (BT*NT)      // 2048 rows
#define HIDF   3072
#define NHEADS 12
#define DHD    64

// ---------------- scratch (static device globals; no allocation) ----------------
__device__ float g_xp[RR*DM];
__device__ float g_t[RR*DM];
__device__ float g_h[RR*DM];
__device__ float g_qkv[RR*3*DM];
__device__ float g_attn[RR*DM];
__device__ float g_mlp[RR*HIDF];
__device__ float g_fpn[RR*DM];

// ---------------- patchify: x[B,3,512,512] -> xp[B*N, 768] ----------------
__global__ void patchify_kernel(const float* __restrict__ x, float* __restrict__ xp) {
    int idx = blockIdx.x * 256 + threadIdx.x;
    if (idx >= RR*DM) return;
    int col = idx % DM;
    int r   = idx / DM;
    int b   = r >> 10, n = r & 1023;
    int gy  = n >> 5,  gx = n & 31;
    int c   = col >> 8;
    int rem = col & 255;
    int py  = rem >> 4, px = rem & 15;
    xp[idx] = x[((size_t)(b*3 + c)*512 + (gy*16 + py))*512 + (gx*16 + px)];
}

// ================= tf32 mma.sync GEMM: C = A[M,K] @ W[K,N] + epilogue =========
// 128x128 tile, BK=32, 256 threads (8 warps as 4x2), warp tile 32x64.
// m16n8k8 tf32 HMMA; smem row stride 36 floats -> conflict-free fragment loads.
// MODE 0: +bias   1: +bias+res[r,n]   2: +bias,GELU   3: +bias+res[r&1023,n]

__device__ __forceinline__ uint32_t f2tf32(float f) {
    uint32_t u;
    asm("cvt.rna.tf32.f32 %0, %1;" : "=r"(u) : "f"(f));
    return u;
}

__device__ __forceinline__ void mma_tf32(float* d, const uint32_t* a, const uint32_t* b) {
    asm volatile(
        "mma.sync.aligned.m16n8k8.row.col.f32.tf32.tf32.f32 "
        "{%0,%1,%2,%3}, {%4,%5,%6,%7}, {%8,%9}, {%0,%1,%2,%3};"
        : "+f"(d[0]), "+f"(d[1]), "+f"(d[2]), "+f"(d[3])
        : "r"(a[0]), "r"(a[1]), "r"(a[2]), "r"(a[3]), "r"(b[0]), "r"(b[1]));
}

#define TS_A  4608   // 128*36 u32 per buffer
#define SMEM_TC (4*4608*4)   // 73728 bytes

template<int MODE>
__global__ void __launch_bounds__(256, 1)
tcgemm(const float* __restrict__ A, const float* __restrict__ W,
       const float* __restrict__ bias, const float* __restrict__ res,
       float* __restrict__ C, int Nt, int K)
{
    extern __shared__ uint32_t dyn[];   // [A0|A1|B0|B1], each 128*36 u32
    const int tid = threadIdx.x;
    const int wid = tid >> 5;
    const int lane = tid & 31;
    const int warp_m = wid >> 1;        // 0..3 -> 32-row slices
    const int warp_n = wid & 1;         // 0..1 -> 64-col slices
    const int r = lane >> 2, cq = lane & 3;
    const int m0 = blockIdx.y * 128;
    const int n0 = blockIdx.x * 128;
    const int NC = K >> 5;

    float acc[2][8][4];
#pragma unroll
    for (int mf = 0; mf < 2; mf++)
#pragma unroll
        for (int nf = 0; nf < 8; nf++)
#pragma unroll
            for (int k = 0; k < 4; k++) acc[mf][nf][k] = 0.f;

    uint32_t avu[4][4], bvu[4][4];
    int am[4], ak[4], bn, bk[4];
#pragma unroll
    for (int i = 0; i < 4; i++) {
        int lin = tid + i*256;
        am[i] = lin >> 3;  ak[i] = (lin & 7)*4;
        bk[i] = (tid >> 7)*16 + i*4;
    }
    bn = tid & 127;

    auto loadG = [&](int kc) {
#pragma unroll
        for (int i = 0; i < 4; i++) {
            float4 v = *(const float4*)(A + (size_t)(m0 + am[i])*K + kc*32 + ak[i]);
            avu[i][0] = f2tf32(v.x); avu[i][1] = f2tf32(v.y);
            avu[i][2] = f2tf32(v.z); avu[i][3] = f2tf32(v.w);
        }
#pragma unroll
        for (int i = 0; i < 4; i++) {
            const float* wp = W + (size_t)(kc*32 + bk[i])*Nt + n0 + bn;
            bvu[i][0] = f2tf32(wp[0]);
            bvu[i][1] = f2tf32(wp[(size_t)Nt]);
            bvu[i][2] = f2tf32(wp[2*(size_t)Nt]);
            bvu[i][3] = f2tf32(wp[3*(size_t)Nt]);
        }
    };
    auto storeS = [&](int buf) {
        uint32_t* Ab = dyn + buf*TS_A;
        uint32_t* Bb = dyn + 2*TS_A + buf*TS_A;
#pragma unroll
        for (int i = 0; i < 4; i++)
            *(uint4*)(Ab + am[i]*36 + ak[i]) = *(uint4*)avu[i];
#pragma unroll
        for (int i = 0; i < 4; i++)
            *(uint4*)(Bb + bn*36 + bk[i]) = *(uint4*)bvu[i];
    };

    loadG(0);
    storeS(0);
    __syncthreads();
    int buf = 0;
    for (int kc = 0; kc < NC; kc++) {
        if (kc + 1 < NC) loadG(kc + 1);
        const uint32_t* Ab = dyn + buf*TS_A + (warp_m*32)*36;
        const uint32_t* Bb = dyn + 2*TS_A + buf*TS_A + (warp_n*64)*36;
#pragma unroll
        for (int kk = 0; kk < 4; kk++) {
            const int ko = kk*8;
            uint32_t afr[2][4];
#pragma unroll
            for (int mf = 0; mf < 2; mf++) {
                int base = (mf*16 + r)*36 + ko + cq;
                afr[mf][0] = Ab[base];
                afr[mf][1] = Ab[base + 8*36];
                afr[mf][2] = Ab[base + 4];
                afr[mf][3] = Ab[base + 8*36 + 4];
            }
            uint32_t bfr[8][2];
#pragma unroll
            for (int nf = 0; nf < 8; nf++) {
                int base = (nf*8 + r)*36 + ko + cq;
                bfr[nf][0] = Bb[base];
                bfr[nf][1] = Bb[base + 4];
            }
#pragma unroll
            for (int mf = 0; mf < 2; mf++)
#pragma unroll
                for (int nf = 0; nf < 8; nf++)
                    mma_tf32(acc[mf][nf], afr[mf], bfr[nf]);
        }
        if (kc + 1 < NC) storeS(buf ^ 1);
        __syncthreads();
        buf ^= 1;
    }

    // epilogue: c0,c1 at (row, col..col+1); c2,c3 at (row+8, ...)
    const int rb = m0 + warp_m*32;
    const int cb = n0 + warp_n*64;
#pragma unroll
    for (int mf = 0; mf < 2; mf++) {
#pragma unroll
        for (int half = 0; half < 2; half++) {
            int row = rb + mf*16 + r + half*8;
            const float* Rrow = nullptr;
            if (MODE == 1) Rrow = res + (size_t)row*Nt;
            if (MODE == 3) Rrow = res + (size_t)(row & (NT-1))*Nt;
            float* Crow = C + (size_t)row*Nt;
#pragma unroll
            for (int nf = 0; nf < 8; nf++) {
                int col = cb + nf*8 + cq*2;
                float v0 = acc[mf][nf][half*2 + 0] + bias[col];
                float v1 = acc[mf][nf][half*2 + 1] + bias[col + 1];
                if (MODE == 1 || MODE == 3) { v0 += Rrow[col]; v1 += Rrow[col+1]; }
                if (MODE == 2) {
                    v0 = 0.5f*v0*(1.f + erff(v0*0.70710678118654752f));
                    v1 = 0.5f*v1*(1.f + erff(v1*0.70710678118654752f));
                }
                float2 o; o.x = v0; o.y = v1;
                *(float2*)(Crow + col) = o;
            }
        }
    }
}

// ---------------- SIMT SGEMM (FPN heads only; N not multiple of 128) ----------
template<int MODE>
__global__ void __launch_bounds__(128)
sgemm_kernel(const float* __restrict__ A, const float* __restrict__ W,
             const float* __restrict__ bias, const float* res, float* C,
             int M, int N, int K)
{
    __shared__ float As[2][16][64];
    __shared__ float Bs[2][16][128];
    const int tid = threadIdx.x;
    const int m0  = blockIdx.y * 64;
    const int n0  = blockIdx.x * 128;
    const int tx  = tid & 15, ty = tid >> 4;

    float acc[8][8];
#pragma unroll
    for (int i = 0; i < 8; i++)
#pragma unroll
        for (int j = 0; j < 8; j++) acc[i][j] = 0.f;

    const int KT = K >> 4;
    float4 aReg[2];
    float  bReg[16];

    auto loadG = [&](int kt) {
#pragma unroll
        for (int l = 0; l < 2; l++) {
            int lin = tid*2 + l;
            int arow = lin >> 2, kq = lin & 3;
            aReg[l] = *(const float4*)(A + (size_t)(m0 + arow)*K + kt*16 + kq*4);
        }
#pragma unroll
        for (int l = 0; l < 16; l++) {
            int lin = tid + l*128;
            int kr = lin >> 7, col = lin & 127;
            int n  = n0 + col;
            bReg[l] = (n < N) ? W[(size_t)(kt*16 + kr)*N + n] : 0.f;
        }
    };
    auto storeS = [&](int buf) {
#pragma unroll
        for (int l = 0; l < 2; l++) {
            int lin = tid*2 + l;
            int arow = lin >> 2, kq = lin & 3;
            As[buf][kq*4+0][arow] = aReg[l].x;
            As[buf][kq*4+1][arow] = aReg[l].y;
            As[buf][kq*4+2][arow] = aReg[l].z;
            As[buf][kq*4+3][arow] = aReg[l].w;
        }
#pragma unroll
        for (int l = 0; l < 16; l++) {
            int lin = tid + l*128;
            int kr = lin >> 7, col = lin & 127;
            Bs[buf][kr][col] = bReg[l];
        }
    };

    loadG(0);
    storeS(0);
    __syncthreads();
    int buf = 0;
    for (int kt = 0; kt < KT; kt++) {
        if (kt + 1 < KT) loadG(kt + 1);
#pragma unroll
        for (int k = 0; k < 16; k++) {
            float a[8], bb[8];
            float4 t0 = *(const float4*)&As[buf][k][ty*8];
            float4 t1 = *(const float4*)&As[buf][k][ty*8 + 4];
            a[0]=t0.x; a[1]=t0.y; a[2]=t0.z; a[3]=t0.w;
            a[4]=t1.x; a[5]=t1.y; a[6]=t1.z; a[7]=t1.w;
            float4 u0 = *(const float4*)&Bs[buf][k][tx*8];
            float4 u1 = *(const float4*)&Bs[buf][k][tx*8 + 4];
            bb[0]=u0.x; bb[1]=u0.y; bb[2]=u0.z; bb[3]=u0.w;
            bb[4]=u1.x; bb[5]=u1.y; bb[6]=u1.z; bb[7]=u1.w;
#pragma unroll
            for (int i = 0; i < 8; i++)
#pragma unroll
                for (int j = 0; j < 8; j++)
                    acc[i][j] += a[i]*bb[j];
        }
        if (kt + 1 < KT) storeS(buf ^ 1);
        __syncthreads();
        buf ^= 1;
    }

#pragma unroll
    for (int i = 0; i < 8; i++) {
        int r = m0 + ty*8 + i;
#pragma unroll
        for (int j = 0; j < 8; j++) {
            int n = n0 + tx*8 + j;
            if (n < N) {
                float v = acc[i][j] + bias[n];
                if (MODE == 1) v += res[(size_t)r*N + n];
                if (MODE == 3) v += res[(size_t)(r & (NT-1))*N + n];
                if (MODE == 2) v = 0.5f*v*(1.f + erff(v*0.70710678118654752f));
                C[(size_t)r*N + n] = v;
            }
        }
    }
}

// ---------------- layernorm: row length 768, one block per row ----------------
__global__ void __launch_bounds__(256)
ln_kernel(const float* __restrict__ x, const float* __restrict__ w,
          const float* __restrict__ b, float* __restrict__ y)
{
    __shared__ float red[8];
    __shared__ float sMean, sRstd;
    int r = blockIdx.x, tid = threadIdx.x;
    const float* xr = x + (size_t)r*DM;
    float v0 = xr[tid], v1 = xr[tid+256], v2 = xr[tid+512];

    float s = v0 + v1 + v2;
#pragma unroll
    for (int o = 16; o > 0; o >>= 1) s += __shfl_xor_sync(0xffffffffu, s, o);
    if ((tid & 31) == 0) red[tid >> 5] = s;
    __syncthreads();
    if (tid == 0) {
        float t = 0.f;
#pragma unroll
        for (int i = 0; i < 8; i++) t += red[i];
        sMean = t * (1.f/768.f);
    }
    __syncthreads();
    float mean = sMean;
    float d0 = v0-mean, d1 = v1-mean, d2 = v2-mean;

    float q = d0*d0 + d1*d1 + d2*d2;
#pragma unroll
    for (int o = 16; o > 0; o >>= 1) q += __shfl_xor_sync(0xffffffffu, q, o);
    if ((tid & 31) == 0) red[tid >> 5] = q;
    __syncthreads();
    if (tid == 0) {
        float t = 0.f;
#pragma unroll
        for (int i = 0; i < 8; i++) t += red[i];
        sRstd = rsqrtf(t * (1.f/768.f) + 1e-5f);
    }
    __syncthreads();
    float rstd = sRstd;
    float* yr = y + (size_t)r*DM;
    yr[tid]     = d0*rstd*w[tid]     + b[tid];
    yr[tid+256] = d1*rstd*w[tid+256] + b[tid+256];
    yr[tid+512] = d2*rstd*w[tid+512] + b[tid+512];
}

// ---------------- fused flash attention (fp32, online softmax, 4-key step) ----
__global__ void __launch_bounds__(64)
flash_attn_kernel(const float* __restrict__ qkv, float* __restrict__ out)
{
    __shared__ float Ks[64][64];
    __shared__ float Vs[64][64];
    const int bh = blockIdx.x;
    const int b  = bh / NHEADS, h = bh % NHEADS;
    const int tid = threadIdx.x;
    const int row = b*NT + blockIdx.y*64 + tid;

    float q[64], o[64];
    const float4* qp = (const float4*)(qkv + (size_t)row*(3*DM) + h*DHD);
#pragma unroll
    for (int i = 0; i < 16; i++) {
        float4 v = qp[i];
        q[4*i]=v.x; q[4*i+1]=v.y; q[4*i+2]=v.z; q[4*i+3]=v.w;
    }
#pragma unroll
    for (int i = 0; i < 64; i++) o[i] = 0.f;
    float m = -3.0e38f, l = 0.f;

    for (int kt = 0; kt < NT/64; kt++) {
        __syncthreads();
        int base = b*NT + kt*64;
        for (int lin = tid; lin < 1024; lin += 64) {
            int j = lin >> 4, qd = lin & 15;
            const float* kr = qkv + (size_t)(base + j)*(3*DM) + h*DHD;
            *(float4*)&Ks[j][qd*4] = *(const float4*)(kr + DM   + qd*4);
            *(float4*)&Vs[j][qd*4] = *(const float4*)(kr + 2*DM + qd*4);
        }
        __syncthreads();
        for (int j0 = 0; j0 < 64; j0 += 4) {
            float s[4];
#pragma unroll
            for (int jj = 0; jj < 4; jj++) {
                float a0=0.f, a1=0.f, a2=0.f, a3=0.f;
#pragma unroll
                for (int d4 = 0; d4 < 16; d4++) {
                    float4 kv = *(const float4*)&Ks[j0+jj][d4*4];
                    a0 += q[d4*4+0]*kv.x;
                    a1 += q[d4*4+1]*kv.y;
                    a2 += q[d4*4+2]*kv.z;
                    a3 += q[d4*4+3]*kv.w;
                }
                s[jj] = ((a0+a1)+(a2+a3)) * 0.125f;
            }
            float smax = fmaxf(fmaxf(s[0],s[1]), fmaxf(s[2],s[3]));
            if (smax > m) {
                float cc = __expf(m - smax);
                m = smax; l *= cc;
#pragma unroll
                for (int d = 0; d < 64; d++) o[d] *= cc;
            }
            float p0 = __expf(s[0]-m), p1 = __expf(s[1]-m);
            float p2 = __expf(s[2]-m), p3 = __expf(s[3]-m);
            l += (p0+p1)+(p2+p3);
#pragma unroll
            for (int d4 = 0; d4 < 16; d4++) {
                float4 v0 = *(const float4*)&Vs[j0  ][d4*4];
                float4 v1 = *(const float4*)&Vs[j0+1][d4*4];
                float4 v2 = *(const float4*)&Vs[j0+2][d4*4];
                float4 v3 = *(const float4*)&Vs[j0+3][d4*4];
                o[d4*4+0] += p0*v0.x + p1*v1.x + p2*v2.x + p3*v3.x;
                o[d4*4+1] += p0*v0.y + p1*v1.y + p2*v2.y + p3*v3.y;
                o[d4*4+2] += p0*v0.z + p1*v1.z + p2*v2.z + p3*v3.z;
                o[d4*4+3] += p0*v0.w + p1*v1.w + p2*v2.w + p3*v3.w;
            }
        }
    }
    float inv = 1.f / l;
    float4* op = (float4*)(out + (size_t)row*DM + h*DHD);
#pragma unroll
    for (int i = 0; i < 16; i++) {
        float4 v;
        v.x=o[4*i]*inv; v.y=o[4*i+1]*inv; v.z=o[4*i+2]*inv; v.w=o[4*i+3]*inv;
        op[i] = v;
    }
}

// ---------------- FPN transpose + clamped bilinear resize (JAX half-pixel) ----
__global__ void fpn_resize_kernel(const float* __restrict__ g, float* __restrict__ out,
                                  int C, int TS)
{
    int idx = blockIdx.x * 256 + threadIdx.x;
    int total = BT*C*TS*TS;
    if (idx >= total) return;
    int xq = idx % TS;
    int yq = (idx / TS) % TS;
    int c  = (idx / (TS*TS)) % C;
    int b  = idx / (TS*TS*C);
    float s  = 32.0f / (float)TS;
    float sy = ((float)yq + 0.5f)*s - 0.5f;
    float sx = ((float)xq + 0.5f)*s - 0.5f;
    int y0 = (int)floorf(sy); float fy = sy - (float)y0;
    int x0 = (int)floorf(sx); float fx = sx - (float)x0;
    int y0c = min(31, max(0, y0)),   y1c = min(31, max(0, y0+1));
    int x0c = min(31, max(0, x0)),   x1c = min(31, max(0, x0+1));
    const float* gb = g + (size_t)b*1024*C;
    float p00 = gb[(y0c*32 + x0c)*C + c];
    float p01 = gb[(y0c*32 + x1c)*C + c];
    float p10 = gb[(y1c*32 + x0c)*C + c];
    float p11 = gb[(y1c*32 + x1c)*C + c];
    out[idx] = (1.f-fy)*((1.f-fx)*p00 + fx*p01) + fy*((1.f-fx)*p10 + fx*p11);
}

// ---------------- host launcher ----------------
extern "C" void kernel_launch(void* const* d_in, const int* in_sizes, int n_in,
                              void* d_out, int out_size)
{
    (void)in_sizes; (void)n_in; (void)out_size;
    const float* x       = (const float*)d_in[0];
    const float* patch_w = (const float*)d_in[1];
    const float* patch_b = (const float*)d_in[2];
    const float* pos     = (const float*)d_in[3];
    const float* ln1_w   = (const float*)d_in[4];
    const float* ln1_b   = (const float*)d_in[5];
    const float* qkv_w   = (const float*)d_in[6];
    const float* qkv_b   = (const float*)d_in[7];
    const float* proj_w  = (const float*)d_in[8];
    const float* proj_b  = (const float*)d_in[9];
    const float* ln2_w   = (const float*)d_in[10];
    const float* ln2_b   = (const float*)d_in[11];
    const float* fc1_w   = (const float*)d_in[12];
    const float* fc1_b   = (const float*)d_in[13];
    const float* fc2_w   = (const float*)d_in[14];
    const float* fc2_b   = (const float*)d_in[15];
    const float* norm_w  = (const float*)d_in[16];
    const float* norm_b  = (const float*)d_in[17];
    const float* fpn_w[4] = {(const float*)d_in[18], (const float*)d_in[20],
                             (const float*)d_in[22], (const float*)d_in[24]};
    const float* fpn_b[4] = {(const float*)d_in[19], (const float*)d_in[21],
                             (const float*)d_in[23], (const float*)d_in[25]};
    float* out = (float*)d_out;

    static float *p_xp = nullptr, *p_t, *p_h, *p_qkv, *p_attn, *p_mlp, *p_fpn;
    if (!p_xp) {  // one-time pointer lookup + smem attribute (outside capture)
        cudaGetSymbolAddress((void**)&p_xp,   g_xp);
        cudaGetSymbolAddress((void**)&p_t,    g_t);
        cudaGetSymbolAddress((void**)&p_h,    g_h);
        cudaGetSymbolAddress((void**)&p_qkv,  g_qkv);
        cudaGetSymbolAddress((void**)&p_attn, g_attn);
        cudaGetSymbolAddress((void**)&p_mlp,  g_mlp);
        cudaGetSymbolAddress((void**)&p_fpn,  g_fpn);
        cudaFuncSetAttribute(tcgemm<0>, cudaFuncAttributeMaxDynamicSharedMemorySize, SMEM_TC);
        cudaFuncSetAttribute(tcgemm<1>, cudaFuncAttributeMaxDynamicSharedMemorySize, SMEM_TC);
        cudaFuncSetAttribute(tcgemm<2>, cudaFuncAttributeMaxDynamicSharedMemorySize, SMEM_TC);
        cudaFuncSetAttribute(tcgemm<3>, cudaFuncAttributeMaxDynamicSharedMemorySize, SMEM_TC);
    }

    // patch embed: t = xp @ patch_w + patch_b + pos_embed
    patchify_kernel<<<(RR*DM + 255)/256, 256>>>(x, p_xp);
    tcgemm<3><<<dim3(6, 16), 256, SMEM_TC>>>(p_xp, patch_w, patch_b, pos, p_t, DM, DM);

    static const size_t off[4] = {0, 3145728, 4718592, 5505024};

    for (int i = 0; i < DEPTHL; i++) {
        ln_kernel<<<RR, 256>>>(p_t, ln1_w + i*DM, ln1_b + i*DM, p_h);
        tcgemm<0><<<dim3(18, 16), 256, SMEM_TC>>>(p_h, qkv_w + (size_t)i*DM*3*DM,
                                                  qkv_b + (size_t)i*3*DM, nullptr,
                                                  p_qkv, 3*DM, DM);
        flash_attn_kernel<<<dim3(BT*NHEADS, NT/64), 64>>>(p_qkv, p_attn);
        tcgemm<1><<<dim3(6, 16), 256, SMEM_TC>>>(p_attn, proj_w + (size_t)i*DM*DM,
                                                 proj_b + (size_t)i*DM, p_t, p_t, DM, DM);
        ln_kernel<<<RR, 256>>>(p_t, ln2_w + i*DM, ln2_b + i*DM, p_h);
        tcgemm<2><<<dim3(24, 16), 256, SMEM_TC>>>(p_h, fc1_w + (size_t)i*DM*HIDF,
                                                  fc1_b + (size_t)i*HIDF, nullptr,
                                                  p_mlp, HIDF, DM);
        tcgemm<1><<<dim3(6, 16), 256, SMEM_TC>>>(p_mlp, fc2_w + (size_t)i*HIDF*DM,
                                                 fc2_b + (size_t)i*DM, p_t, p_t, DM, HIDF);

        int e = (i == 3) ? 0 : (i == 6) ? 1 : (i == 9) ? 2 : (i == 11) ? 3 : -1;
        if (e >= 0) {
            int oc = 96 << e, ts = 128 >> e;
            ln_kernel<<<RR, 256>>>(p_t, norm_w, norm_b, p_h);
            sgemm_kernel<0><<<dim3((oc + 127)/128, 32), 128>>>(p_h, fpn_w[e], fpn_b[e],
                                                               nullptr, p_fpn, RR, oc, DM);
            int total = BT*oc*ts*ts;
            fpn_resize_kernel<<<(total + 255)/256, 256>>>(p_fpn, out + off[e], oc, ts);
        }
    }
}

// round 10
// speedup vs baseline: 1.8807x; 1.0758x over previous
#include <cuda_runtime.h>
#include <math.h>
#include <stdint.h>

#define DEPTHL 12
#define DM     768
#define NT     1024
#define BT     2
#define RR     (BT*NT)      // 2048 rows
#define HIDF   3072
#define NHEADS 12
#define DHD    64

// ---------------- scratch (static device globals; no allocation) ----------------
__device__ float g_xp[RR*DM];
__device__ float g_t[RR*DM];
__device__ float g_h[RR*DM];
__device__ float g_qkv[RR*3*DM];
__device__ float g_attn[RR*DM];
__device__ float g_mlp[RR*HIDF];
__device__ float g_fpn[RR*DM];

// ---------------- patchify: x[B,3,512,512] -> xp[B*N, 768] ----------------
__global__ void patchify_kernel(const float* __restrict__ x, float* __restrict__ xp) {
    int idx = blockIdx.x * 256 + threadIdx.x;
    if (idx >= RR*DM) return;
    int col = idx % DM;
    int r   = idx / DM;
    int b   = r >> 10, n = r & 1023;
    int gy  = n >> 5,  gx = n & 31;
    int c   = col >> 8;
    int rem = col & 255;
    int py  = rem >> 4, px = rem & 15;
    xp[idx] = x[((size_t)(b*3 + c)*512 + (gy*16 + py))*512 + (gx*16 + px)];
}

// ================= tf32 mma.sync GEMM v2 ======================================
// C = A[M,K] @ W[K,N] + epilogue.  BM=64, BN=128, BK=32, 256 thr (8 warps 4x2),
// warp tile 16x64.  3-stage cp.async pipeline, fp32 in smem, cvt->tf32 after LDS.
// A smem: [64][36] floats (pad 4).  B smem: k-major [32][136] floats (pad 8).
// MODE 0: +bias   1: +bias+res[r,n]   2: +bias,GELU   3: +bias+res[r&1023,n]

__device__ __forceinline__ uint32_t f2tf32(float f) {
    uint32_t u;
    asm("cvt.rna.tf32.f32 %0, %1;" : "=r"(u) : "f"(f));
    return u;
}
__device__ __forceinline__ void mma_tf32(float* d, const uint32_t* a, const uint32_t* b) {
    asm volatile(
        "mma.sync.aligned.m16n8k8.row.col.f32.tf32.tf32.f32 "
        "{%0,%1,%2,%3}, {%4,%5,%6,%7}, {%8,%9}, {%0,%1,%2,%3};"
        : "+f"(d[0]), "+f"(d[1]), "+f"(d[2]), "+f"(d[3])
        : "r"(a[0]), "r"(a[1]), "r"(a[2]), "r"(a[3]), "r"(b[0]), "r"(b[1]));
}
__device__ __forceinline__ uint32_t smem_u32p(const void* p) {
    uint32_t a;
    asm("{ .reg .u64 t; cvta.to.shared.u64 t, %1; cvt.u32.u64 %0, t; }" : "=r"(a) : "l"(p));
    return a;
}
#define CP16(dst, src) \
    asm volatile("cp.async.cg.shared.global [%0], [%1], 16;" :: "r"(dst), "l"(src))
#define CP_COMMIT() asm volatile("cp.async.commit_group;")
#define CP_WAIT1()  asm volatile("cp.async.wait_group 1;" ::: "memory")

#define ST_FL   6656          // floats per stage: A 64*36=2304 + B 32*136=4352
#define SMEM_TC (3*ST_FL*4)   // 79872 bytes

template<int MODE>
__global__ void __launch_bounds__(256, 2)
tcgemm(const float* __restrict__ A, const float* __restrict__ W,
       const float* __restrict__ bias, const float* __restrict__ res,
       float* __restrict__ C, int Nt, int K)
{
    extern __shared__ float dyn[];
    const int tid = threadIdx.x;
    const int wid = tid >> 5;
    const int lane = tid & 31;
    const int warp_m = wid >> 1;        // 0..3 -> 16-row slices
    const int warp_n = wid & 1;         // 0..1 -> 64-col slices
    const int r = lane >> 2, cq = lane & 3;
    const int m0 = blockIdx.y * 64;
    const int n0 = blockIdx.x * 128;
    const int NC = K >> 5;

    const uint32_t sbase = smem_u32p(dyn);

    // per-thread load coordinates
    int a_row[2], a_kq[2];              // A: 512 chunks of 16B, 2/thread
#pragma unroll
    for (int i = 0; i < 2; i++) {
        int c = tid + i*256;
        a_row[i] = c >> 3; a_kq[i] = (c & 7)*4;
    }
    int b_kr[4], b_nq[4];               // B: 1024 chunks, 4/thread
#pragma unroll
    for (int i = 0; i < 4; i++) {
        int c = tid + i*256;
        b_kr[i] = c >> 5; b_nq[i] = (c & 31)*4;
    }

    auto issue = [&](int kc, int st) {
        const uint32_t sA = sbase + (uint32_t)(st*ST_FL)*4u;
        const uint32_t sB = sA + 2304u*4u;
#pragma unroll
        for (int i = 0; i < 2; i++) {
            const float* src = A + (size_t)(m0 + a_row[i])*K + kc*32 + a_kq[i];
            CP16(sA + (uint32_t)(a_row[i]*36 + a_kq[i])*4u, src);
        }
#pragma unroll
        for (int i = 0; i < 4; i++) {
            const float* src = W + (size_t)(kc*32 + b_kr[i])*Nt + n0 + b_nq[i];
            CP16(sB + (uint32_t)(b_kr[i]*136 + b_nq[i])*4u, src);
        }
        CP_COMMIT();
    };

    float acc[8][4];
#pragma unroll
    for (int nf = 0; nf < 8; nf++)
#pragma unroll
        for (int k = 0; k < 4; k++) acc[nf][k] = 0.f;

    issue(0, 0);
    issue(1, 1);

    for (int kc = 0; kc < NC; kc++) {
        CP_WAIT1();
        __syncthreads();
        if (kc + 2 < NC) issue(kc + 2, (kc + 2) % 3);
        else CP_COMMIT();   // keep group count uniform

        const int st = kc % 3;
        const float* Ab = dyn + st*ST_FL + (warp_m*16)*36;
        const float* Bb = dyn + st*ST_FL + 2304 + warp_n*64;
#pragma unroll
        for (int kk = 0; kk < 4; kk++) {
            const int ko = kk*8;
            uint32_t afr[4];
            {
                int base = r*36 + ko + cq;
                afr[0] = f2tf32(Ab[base]);
                afr[1] = f2tf32(Ab[base + 8*36]);
                afr[2] = f2tf32(Ab[base + 4]);
                afr[3] = f2tf32(Ab[base + 8*36 + 4]);
            }
            uint32_t bfr[8][2];
#pragma unroll
            for (int nf = 0; nf < 8; nf++) {
                int nn = nf*8 + r;
                bfr[nf][0] = f2tf32(Bb[(ko + cq)*136 + nn]);
                bfr[nf][1] = f2tf32(Bb[(ko + cq + 4)*136 + nn]);
            }
#pragma unroll
            for (int nf = 0; nf < 8; nf++)
                mma_tf32(acc[nf], afr, bfr[nf]);
        }
    }

    // epilogue: c0,c1 at (row, col..col+1); c2,c3 at (row+8, ...)
    const int rb = m0 + warp_m*16;
    const int cb = n0 + warp_n*64;
#pragma unroll
    for (int half = 0; half < 2; half++) {
        int row = rb + r + half*8;
        const float* Rrow = nullptr;
        if (MODE == 1) Rrow = res + (size_t)row*Nt;
        if (MODE == 3) Rrow = res + (size_t)(row & (NT-1))*Nt;
        float* Crow = C + (size_t)row*Nt;
#pragma unroll
        for (int nf = 0; nf < 8; nf++) {
            int col = cb + nf*8 + cq*2;
            float v0 = acc[nf][half*2 + 0] + bias[col];
            float v1 = acc[nf][half*2 + 1] + bias[col + 1];
            if (MODE == 1 || MODE == 3) { v0 += Rrow[col]; v1 += Rrow[col+1]; }
            if (MODE == 2) {
                v0 = 0.5f*v0*(1.f + erff(v0*0.70710678118654752f));
                v1 = 0.5f*v1*(1.f + erff(v1*0.70710678118654752f));
            }
            float2 o; o.x = v0; o.y = v1;
            *(float2*)(Crow + col) = o;
        }
    }
}

// ---------------- SIMT SGEMM (FPN heads only) ----------------
template<int MODE>
__global__ void __launch_bounds__(128)
sgemm_kernel(const float* __restrict__ A, const float* __restrict__ W,
             const float* __restrict__ bias, const float* res, float* C,
             int M, int N, int K)
{
    __shared__ float As[2][16][64];
    __shared__ float Bs[2][16][128];
    const int tid = threadIdx.x;
    const int m0  = blockIdx.y * 64;
    const int n0  = blockIdx.x * 128;
    const int tx  = tid & 15, ty = tid >> 4;

    float acc[8][8];
#pragma unroll
    for (int i = 0; i < 8; i++)
#pragma unroll
        for (int j = 0; j < 8; j++) acc[i][j] = 0.f;

    const int KT = K >> 4;
    float4 aReg[2];
    float  bReg[16];

    auto loadG = [&](int kt) {
#pragma unroll
        for (int l = 0; l < 2; l++) {
            int lin = tid*2 + l;
            int arow = lin >> 2, kq = lin & 3;
            aReg[l] = *(const float4*)(A + (size_t)(m0 + arow)*K + kt*16 + kq*4);
        }
#pragma unroll
        for (int l = 0; l < 16; l++) {
            int lin = tid + l*128;
            int kr = lin >> 7, col = lin & 127;
            int n  = n0 + col;
            bReg[l] = (n < N) ? W[(size_t)(kt*16 + kr)*N + n] : 0.f;
        }
    };
    auto storeS = [&](int buf) {
#pragma unroll
        for (int l = 0; l < 2; l++) {
            int lin = tid*2 + l;
            int arow = lin >> 2, kq = lin & 3;
            As[buf][kq*4+0][arow] = aReg[l].x;
            As[buf][kq*4+1][arow] = aReg[l].y;
            As[buf][kq*4+2][arow] = aReg[l].z;
            As[buf][kq*4+3][arow] = aReg[l].w;
        }
#pragma unroll
        for (int l = 0; l < 16; l++) {
            int lin = tid + l*128;
            int kr = lin >> 7, col = lin & 127;
            Bs[buf][kr][col] = bReg[l];
        }
    };

    loadG(0);
    storeS(0);
    __syncthreads();
    int buf = 0;
    for (int kt = 0; kt < KT; kt++) {
        if (kt + 1 < KT) loadG(kt + 1);
#pragma unroll
        for (int k = 0; k < 16; k++) {
            float a[8], bb[8];
            float4 t0 = *(const float4*)&As[buf][k][ty*8];
            float4 t1 = *(const float4*)&As[buf][k][ty*8 + 4];
            a[0]=t0.x; a[1]=t0.y; a[2]=t0.z; a[3]=t0.w;
            a[4]=t1.x; a[5]=t1.y; a[6]=t1.z; a[7]=t1.w;
            float4 u0 = *(const float4*)&Bs[buf][k][tx*8];
            float4 u1 = *(const float4*)&Bs[buf][k][tx*8 + 4];
            bb[0]=u0.x; bb[1]=u0.y; bb[2]=u0.z; bb[3]=u0.w;
            bb[4]=u1.x; bb[5]=u1.y; bb[6]=u1.z; bb[7]=u1.w;
#pragma unroll
            for (int i = 0; i < 8; i++)
#pragma unroll
                for (int j = 0; j < 8; j++)
                    acc[i][j] += a[i]*bb[j];
        }
        if (kt + 1 < KT) storeS(buf ^ 1);
        __syncthreads();
        buf ^= 1;
    }

#pragma unroll
    for (int i = 0; i < 8; i++) {
        int r = m0 + ty*8 + i;
#pragma unroll
        for (int j = 0; j < 8; j++) {
            int n = n0 + tx*8 + j;
            if (n < N) {
                float v = acc[i][j] + bias[n];
                if (MODE == 1) v += res[(size_t)r*N + n];
                if (MODE == 3) v += res[(size_t)(r & (NT-1))*N + n];
                if (MODE == 2) v = 0.5f*v*(1.f + erff(v*0.70710678118654752f));
                C[(size_t)r*N + n] = v;
            }
        }
    }
}

// ---------------- layernorm: row length 768, one block per row ----------------
__global__ void __launch_bounds__(256)
ln_kernel(const float* __restrict__ x, const float* __restrict__ w,
          const float* __restrict__ b, float* __restrict__ y)
{
    __shared__ float red[8];
    __shared__ float sMean, sRstd;
    int r = blockIdx.x, tid = threadIdx.x;
    const float* xr = x + (size_t)r*DM;
    float v0 = xr[tid], v1 = xr[tid+256], v2 = xr[tid+512];

    float s = v0 + v1 + v2;
#pragma unroll
    for (int o = 16; o > 0; o >>= 1) s += __shfl_xor_sync(0xffffffffu, s, o);
    if ((tid & 31) == 0) red[tid >> 5] = s;
    __syncthreads();
    if (tid == 0) {
        float t = 0.f;
#pragma unroll
        for (int i = 0; i < 8; i++) t += red[i];
        sMean = t * (1.f/768.f);
    }
    __syncthreads();
    float mean = sMean;
    float d0 = v0-mean, d1 = v1-mean, d2 = v2-mean;

    float q = d0*d0 + d1*d1 + d2*d2;
#pragma unroll
    for (int o = 16; o > 0; o >>= 1) q += __shfl_xor_sync(0xffffffffu, q, o);
    if ((tid & 31) == 0) red[tid >> 5] = q;
    __syncthreads();
    if (tid == 0) {
        float t = 0.f;
#pragma unroll
        for (int i = 0; i < 8; i++) t += red[i];
        sRstd = rsqrtf(t * (1.f/768.f) + 1e-5f);
    }
    __syncthreads();
    float rstd = sRstd;
    float* yr = y + (size_t)r*DM;
    yr[tid]     = d0*rstd*w[tid]     + b[tid];
    yr[tid+256] = d1*rstd*w[tid+256] + b[tid+256];
    yr[tid+512] = d2*rstd*w[tid+512] + b[tid+512];
}

// ---------------- fused flash attention (fp32, online softmax, 4-key step) ----
// 128 threads/block (4 warps -> all 4 SMSPs), 128 queries per block.
__global__ void __launch_bounds__(128)
flash_attn_kernel(const float* __restrict__ qkv, float* __restrict__ out)
{
    __shared__ float Ks[64][64];
    __shared__ float Vs[64][64];
    const int bh = blockIdx.x;
    const int b  = bh / NHEADS, h = bh % NHEADS;
    const int tid = threadIdx.x;
    const int row = b*NT + blockIdx.y*128 + tid;

    float q[64], o[64];
    const float4* qp = (const float4*)(qkv + (size_t)row*(3*DM) + h*DHD);
#pragma unroll
    for (int i = 0; i < 16; i++) {
        float4 v = qp[i];
        q[4*i]=v.x; q[4*i+1]=v.y; q[4*i+2]=v.z; q[4*i+3]=v.w;
    }
#pragma unroll
    for (int i = 0; i < 64; i++) o[i] = 0.f;
    float m = -3.0e38f, l = 0.f;

    for (int kt = 0; kt < NT/64; kt++) {
        __syncthreads();
        int base = b*NT + kt*64;
        for (int lin = tid; lin < 1024; lin += 128) {
            int j = lin >> 4, qd = lin & 15;
            const float* kr = qkv + (size_t)(base + j)*(3*DM) + h*DHD;
            *(float4*)&Ks[j][qd*4] = *(const float4*)(kr + DM   + qd*4);
            *(float4*)&Vs[j][qd*4] = *(const float4*)(kr + 2*DM + qd*4);
        }
        __syncthreads();
        for (int j0 = 0; j0 < 64; j0 += 4) {
            float s[4];
#pragma unroll
            for (int jj = 0; jj < 4; jj++) {
                float a0=0.f, a1=0.f, a2=0.f, a3=0.f;
#pragma unroll
                for (int d4 = 0; d4 < 16; d4++) {
                    float4 kv = *(const float4*)&Ks[j0+jj][d4*4];
                    a0 += q[d4*4+0]*kv.x;
                    a1 += q[d4*4+1]*kv.y;
                    a2 += q[d4*4+2]*kv.z;
                    a3 += q[d4*4+3]*kv.w;
                }
                s[jj] = ((a0+a1)+(a2+a3)) * 0.125f;
            }
            float smax = fmaxf(fmaxf(s[0],s[1]), fmaxf(s[2],s[3]));
            if (smax > m) {
                float cc = __expf(m - smax);
                m = smax; l *= cc;
#pragma unroll
                for (int d = 0; d < 64; d++) o[d] *= cc;
            }
            float p0 = __expf(s[0]-m), p1 = __expf(s[1]-m);
            float p2 = __expf(s[2]-m), p3 = __expf(s[3]-m);
            l += (p0+p1)+(p2+p3);
#pragma unroll
            for (int d4 = 0; d4 < 16; d4++) {
                float4 v0 = *(const float4*)&Vs[j0  ][d4*4];
                float4 v1 = *(const float4*)&Vs[j0+1][d4*4];
                float4 v2 = *(const float4*)&Vs[j0+2][d4*4];
                float4 v3 = *(const float4*)&Vs[j0+3][d4*4];
                o[d4*4+0] += p0*v0.x + p1*v1.x + p2*v2.x + p3*v3.x;
                o[d4*4+1] += p0*v0.y + p1*v1.y + p2*v2.y + p3*v3.y;
                o[d4*4+2] += p0*v0.z + p1*v1.z + p2*v2.z + p3*v3.z;
                o[d4*4+3] += p0*v0.w + p1*v1.w + p2*v2.w + p3*v3.w;
            }
        }
    }
    float inv = 1.f / l;
    float4* op = (float4*)(out + (size_t)row*DM + h*DHD);
#pragma unroll
    for (int i = 0; i < 16; i++) {
        float4 v;
        v.x=o[4*i]*inv; v.y=o[4*i+1]*inv; v.z=o[4*i+2]*inv; v.w=o[4*i+3]*inv;
        op[i] = v;
    }
}

// ---------------- FPN transpose + clamped bilinear resize (JAX half-pixel) ----
__global__ void fpn_resize_kernel(const float* __restrict__ g, float* __restrict__ out,
                                  int C, int TS)
{
    int idx = blockIdx.x * 256 + threadIdx.x;
    int total = BT*C*TS*TS;
    if (idx >= total) return;
    int xq = idx % TS;
    int yq = (idx / TS) % TS;
    int c  = (idx / (TS*TS)) % C;
    int b  = idx / (TS*TS*C);
    float s  = 32.0f / (float)TS;
    float sy = ((float)yq + 0.5f)*s - 0.5f;
    float sx = ((float)xq + 0.5f)*s - 0.5f;
    int y0 = (int)floorf(sy); float fy = sy - (float)y0;
    int x0 = (int)floorf(sx); float fx = sx - (float)x0;
    int y0c = min(31, max(0, y0)),   y1c = min(31, max(0, y0+1));
    int x0c = min(31, max(0, x0)),   x1c = min(31, max(0, x0+1));
    const float* gb = g + (size_t)b*1024*C;
    float p00 = gb[(y0c*32 + x0c)*C + c];
    float p01 = gb[(y0c*32 + x1c)*C + c];
    float p10 = gb[(y1c*32 + x0c)*C + c];
    float p11 = gb[(y1c*32 + x1c)*C + c];
    out[idx] = (1.f-fy)*((1.f-fx)*p00 + fx*p01) + fy*((1.f-fx)*p10 + fx*p11);
}

// ---------------- host launcher ----------------
extern "C" void kernel_launch(void* const* d_in, const int* in_sizes, int n_in,
                              void* d_out, int out_size)
{
    (void)in_sizes; (void)n_in; (void)out_size;
    const float* x       = (const float*)d_in[0];
    const float* patch_w = (const float*)d_in[1];
    const float* patch_b = (const float*)d_in[2];
    const float* pos     = (const float*)d_in[3];
    const float* ln1_w   = (const float*)d_in[4];
    const float* ln1_b   = (const float*)d_in[5];
    const float* qkv_w   = (const float*)d_in[6];
    const float* qkv_b   = (const float*)d_in[7];
    const float* proj_w  = (const float*)d_in[8];
    const float* proj_b  = (const float*)d_in[9];
    const float* ln2_w   = (const float*)d_in[10];
    const float* ln2_b   = (const float*)d_in[11];
    const float* fc1_w   = (const float*)d_in[12];
    const float* fc1_b   = (const float*)d_in[13];
    const float* fc2_w   = (const float*)d_in[14];
    const float* fc2_b   = (const float*)d_in[15];
    const float* norm_w  = (const float*)d_in[16];
    const float* norm_b  = (const float*)d_in[17];
    const float* fpn_w[4] = {(const float*)d_in[18], (const float*)d_in[20],
                             (const float*)d_in[22], (const float*)d_in[24]};
    const float* fpn_b[4] = {(const float*)d_in[19], (const float*)d_in[21],
                             (const float*)d_in[23], (const float*)d_in[25]};
    float* out = (float*)d_out;

    static float *p_xp = nullptr, *p_t, *p_h, *p_qkv, *p_attn, *p_mlp, *p_fpn;
    if (!p_xp) {  // one-time pointer lookup + smem attribute (outside capture)
        cudaGetSymbolAddress((void**)&p_xp,   g_xp);
        cudaGetSymbolAddress((void**)&p_t,    g_t);
        cudaGetSymbolAddress((void**)&p_h,    g_h);
        cudaGetSymbolAddress((void**)&p_qkv,  g_qkv);
        cudaGetSymbolAddress((void**)&p_attn, g_attn);
        cudaGetSymbolAddress((void**)&p_mlp,  g_mlp);
        cudaGetSymbolAddress((void**)&p_fpn,  g_fpn);
        cudaFuncSetAttribute(tcgemm<0>, cudaFuncAttributeMaxDynamicSharedMemorySize, SMEM_TC);
        cudaFuncSetAttribute(tcgemm<1>, cudaFuncAttributeMaxDynamicSharedMemorySize, SMEM_TC);
        cudaFuncSetAttribute(tcgemm<2>, cudaFuncAttributeMaxDynamicSharedMemorySize, SMEM_TC);
        cudaFuncSetAttribute(tcgemm<3>, cudaFuncAttributeMaxDynamicSharedMemorySize, SMEM_TC);
    }

    // patch embed: t = xp @ patch_w + patch_b + pos_embed
    patchify_kernel<<<(RR*DM + 255)/256, 256>>>(x, p_xp);
    tcgemm<3><<<dim3(6, 32), 256, SMEM_TC>>>(p_xp, patch_w, patch_b, pos, p_t, DM, DM);

    static const size_t off[4] = {0, 3145728, 4718592, 5505024};

    for (int i = 0; i < DEPTHL; i++) {
        ln_kernel<<<RR, 256>>>(p_t, ln1_w + i*DM, ln1_b + i*DM, p_h);
        tcgemm<0><<<dim3(18, 32), 256, SMEM_TC>>>(p_h, qkv_w + (size_t)i*DM*3*DM,
                                                  qkv_b + (size_t)i*3*DM, nullptr,
                                                  p_qkv, 3*DM, DM);
        flash_attn_kernel<<<dim3(BT*NHEADS, NT/128), 128>>>(p_qkv, p_attn);
        tcgemm<1><<<dim3(6, 32), 256, SMEM_TC>>>(p_attn, proj_w + (size_t)i*DM*DM,
                                                 proj_b + (size_t)i*DM, p_t, p_t, DM, DM);
        ln_kernel<<<RR, 256>>>(p_t, ln2_w + i*DM, ln2_b + i*DM, p_h);
        tcgemm<2><<<dim3(24, 32), 256, SMEM_TC>>>(p_h, fc1_w + (size_t)i*DM*HIDF,
                                                  fc1_b + (size_t)i*HIDF, nullptr,
                                                  p_mlp, HIDF, DM);
        tcgemm<1><<<dim3(6, 32), 256, SMEM_TC>>>(p_mlp, fc2_w + (size_t)i*HIDF*DM,
                                                 fc2_b + (size_t)i*DM, p_t, p_t, DM, HIDF);

        int e = (i == 3) ? 0 : (i == 6) ? 1 : (i == 9) ? 2 : (i == 11) ? 3 : -1;
        if (e >= 0) {
            int oc = 96 << e, ts = 128 >> e;
            ln_kernel<<<RR, 256>>>(p_t, norm_w, norm_b, p_h);
            sgemm_kernel<0><<<dim3((oc + 127)/128, 32), 128>>>(p_h, fpn_w[e], fpn_b[e],
                                                               nullptr, p_fpn, RR, oc, DM);
            int total = BT*oc*ts*ts;
            fpn_resize_kernel<<<(total + 255)/256, 256>>>(p_fpn, out + off[e], oc, ts);
        }
    }
}

// round 11
// speedup vs baseline: 2.2088x; 1.1744x over previous
#include <cuda_runtime.h>
#include <math.h>
#include <stdint.h>

#define DEPTHL 12
#define DM     768
#define NT     1024
#define BT     2
#define RR     (BT*NT)      // 2048 rows
#define HIDF   3072
#define NHEADS 12
#define DHD    64

// ---------------- scratch (static device globals; no allocation) ----------------
__device__ float g_xp[RR*DM];
__device__ float g_t[RR*DM];
__device__ float g_h[RR*DM];
__device__ float g_qkv[RR*3*DM];
__device__ float g_attn[RR*DM];
__device__ float g_mlp[RR*HIDF];
__device__ float g_fpn[RR*DM];
// attention split partials: [split][bh][query][64] + (m,l)
__device__ float  g_po[2*24*1024*64];
__device__ float2 g_pml[2*24*1024];

// ---------------- patchify: x[B,3,512,512] -> xp[B*N, 768] ----------------
__global__ void patchify_kernel(const float* __restrict__ x, float* __restrict__ xp) {
    int idx = blockIdx.x * 256 + threadIdx.x;
    if (idx >= RR*DM) return;
    int col = idx % DM;
    int r   = idx / DM;
    int b   = r >> 10, n = r & 1023;
    int gy  = n >> 5,  gx = n & 31;
    int c   = col >> 8;
    int rem = col & 255;
    int py  = rem >> 4, px = rem & 15;
    xp[idx] = x[((size_t)(b*3 + c)*512 + (gy*16 + py))*512 + (gx*16 + px)];
}

// ================= tf32 mma.sync GEMM v3 ======================================
// C = A[M,K] @ W[K,N] + epilogue.  BM=128, BN=128, BK=32, 256 thr, 8 warps 4x2,
// warp tile 32x64 (B fragment feeds 2 mma).  2-stage cp.async, 2 CTAs/SM.
// A smem [128][36] fp32; B smem k-major [32][136] fp32; cvt->tf32 after LDS.
// MODE 0: +bias   1: +bias+res[r,n]   2: +bias,GELU   3: +bias+res[r&1023,n]

__device__ __forceinline__ uint32_t f2tf32(float f) {
    uint32_t u;
    asm("cvt.rna.tf32.f32 %0, %1;" : "=r"(u) : "f"(f));
    return u;
}
__device__ __forceinline__ void mma_tf32(float* d, const uint32_t* a, const uint32_t* b) {
    asm volatile(
        "mma.sync.aligned.m16n8k8.row.col.f32.tf32.tf32.f32 "
        "{%0,%1,%2,%3}, {%4,%5,%6,%7}, {%8,%9}, {%0,%1,%2,%3};"
        : "+f"(d[0]), "+f"(d[1]), "+f"(d[2]), "+f"(d[3])
        : "r"(a[0]), "r"(a[1]), "r"(a[2]), "r"(a[3]), "r"(b[0]), "r"(b[1]));
}
__device__ __forceinline__ uint32_t smem_u32p(const void* p) {
    uint32_t a;
    asm("{ .reg .u64 t; cvta.to.shared.u64 t, %1; cvt.u32.u64 %0, t; }" : "=r"(a) : "l"(p));
    return a;
}
#define CP16(dst, src) \
    asm volatile("cp.async.cg.shared.global [%0], [%1], 16;" :: "r"(dst), "l"(src))
#define CP_COMMIT() asm volatile("cp.async.commit_group;")
#define CP_WAIT1()  asm volatile("cp.async.wait_group 1;" ::: "memory")

#define ASTG 4608                 // 128*36 floats
#define BSTG 4352                 // 32*136 floats
#define STG  (ASTG+BSTG)          // 8960 floats / stage
#define SMEM_TC (2*STG*4)         // 71680 bytes

template<int MODE>
__global__ void __launch_bounds__(256, 2)
tcgemm(const float* __restrict__ A, const float* __restrict__ W,
       const float* __restrict__ bias, const float* __restrict__ res,
       float* __restrict__ C, int Nt, int K)
{
    extern __shared__ float dyn[];
    const int tid = threadIdx.x;
    const int wid = tid >> 5;
    const int lane = tid & 31;
    const int warp_m = wid >> 1;        // 0..3 -> 32-row slices
    const int warp_n = wid & 1;         // 0..1 -> 64-col slices
    const int r = lane >> 2, cq = lane & 3;
    const int m0 = blockIdx.y * 128;
    const int n0 = blockIdx.x * 128;
    const int NC = K >> 5;

    const uint32_t sbase = smem_u32p(dyn);

    // per-thread load coordinates (4 x 16B chunks each for A and B)
    int a_row[4], a_kq[4], b_kr[4], b_nq[4];
#pragma unroll
    for (int i = 0; i < 4; i++) {
        int c = tid + i*256;
        a_row[i] = c >> 3;  a_kq[i] = (c & 7)*4;
        b_kr[i] = c >> 5;   b_nq[i] = (c & 31)*4;
    }

    auto issue = [&](int kc, int st) {
        const uint32_t sA = sbase + (uint32_t)(st*STG)*4u;
        const uint32_t sB = sA + (uint32_t)ASTG*4u;
#pragma unroll
        for (int i = 0; i < 4; i++) {
            const float* src = A + (size_t)(m0 + a_row[i])*K + kc*32 + a_kq[i];
            CP16(sA + (uint32_t)(a_row[i]*36 + a_kq[i])*4u, src);
        }
#pragma unroll
        for (int i = 0; i < 4; i++) {
            const float* src = W + (size_t)(kc*32 + b_kr[i])*Nt + n0 + b_nq[i];
            CP16(sB + (uint32_t)(b_kr[i]*136 + b_nq[i])*4u, src);
        }
        CP_COMMIT();
    };

    float acc[2][8][4];
#pragma unroll
    for (int mf = 0; mf < 2; mf++)
#pragma unroll
        for (int nf = 0; nf < 8; nf++)
#pragma unroll
            for (int k = 0; k < 4; k++) acc[mf][nf][k] = 0.f;

    issue(0, 0);

    for (int kc = 0; kc < NC; kc++) {
        if (kc + 1 < NC) issue(kc + 1, (kc + 1) & 1);
        else CP_COMMIT();            // uniform group count
        CP_WAIT1();
        __syncthreads();

        const int st = kc & 1;
        const float* Ab = dyn + st*STG + (warp_m*32)*36;
        const float* Bb = dyn + st*STG + ASTG + warp_n*64;
#pragma unroll
        for (int kk = 0; kk < 4; kk++) {
            const int ko = kk*8;
            uint32_t afr[2][4];
#pragma unroll
            for (int mf = 0; mf < 2; mf++) {
                int base = (mf*16 + r)*36 + ko + cq;
                afr[mf][0] = f2tf32(Ab[base]);
                afr[mf][1] = f2tf32(Ab[base + 8*36]);
                afr[mf][2] = f2tf32(Ab[base + 4]);
                afr[mf][3] = f2tf32(Ab[base + 8*36 + 4]);
            }
#pragma unroll
            for (int nf = 0; nf < 8; nf++) {
                int nn = nf*8 + r;
                uint32_t b0 = f2tf32(Bb[(ko + cq)*136 + nn]);
                uint32_t b1 = f2tf32(Bb[(ko + cq + 4)*136 + nn]);
                uint32_t bfr[2] = {b0, b1};
                mma_tf32(acc[0][nf], afr[0], bfr);
                mma_tf32(acc[1][nf], afr[1], bfr);
            }
        }
        __syncthreads();
    }

    // epilogue: c0,c1 at (row, col..col+1); c2,c3 at (row+8, ...)
    const int rb = m0 + warp_m*32;
    const int cb = n0 + warp_n*64;
#pragma unroll
    for (int mf = 0; mf < 2; mf++) {
#pragma unroll
        for (int half = 0; half < 2; half++) {
            int row = rb + mf*16 + r + half*8;
            const float* Rrow = nullptr;
            if (MODE == 1) Rrow = res + (size_t)row*Nt;
            if (MODE == 3) Rrow = res + (size_t)(row & (NT-1))*Nt;
            float* Crow = C + (size_t)row*Nt;
#pragma unroll
            for (int nf = 0; nf < 8; nf++) {
                int col = cb + nf*8 + cq*2;
                float v0 = acc[mf][nf][half*2 + 0] + bias[col];
                float v1 = acc[mf][nf][half*2 + 1] + bias[col + 1];
                if (MODE == 1 || MODE == 3) { v0 += Rrow[col]; v1 += Rrow[col+1]; }
                if (MODE == 2) {
                    v0 = 0.5f*v0*(1.f + erff(v0*0.70710678118654752f));
                    v1 = 0.5f*v1*(1.f + erff(v1*0.70710678118654752f));
                }
                float2 o; o.x = v0; o.y = v1;
                *(float2*)(Crow + col) = o;
            }
        }
    }
}

// ---------------- SIMT SGEMM (FPN heads only) ----------------
template<int MODE>
__global__ void __launch_bounds__(128)
sgemm_kernel(const float* __restrict__ A, const float* __restrict__ W,
             const float* __restrict__ bias, const float* res, float* C,
             int M, int N, int K)
{
    __shared__ float As[2][16][64];
    __shared__ float Bs[2][16][128];
    const int tid = threadIdx.x;
    const int m0  = blockIdx.y * 64;
    const int n0  = blockIdx.x * 128;
    const int tx  = tid & 15, ty = tid >> 4;

    float acc[8][8];
#pragma unroll
    for (int i = 0; i < 8; i++)
#pragma unroll
        for (int j = 0; j < 8; j++) acc[i][j] = 0.f;

    const int KT = K >> 4;
    float4 aReg[2];
    float  bReg[16];

    auto loadG = [&](int kt) {
#pragma unroll
        for (int l = 0; l < 2; l++) {
            int lin = tid*2 + l;
            int arow = lin >> 2, kq = lin & 3;
            aReg[l] = *(const float4*)(A + (size_t)(m0 + arow)*K + kt*16 + kq*4);
        }
#pragma unroll
        for (int l = 0; l < 16; l++) {
            int lin = tid + l*128;
            int kr = lin >> 7, col = lin & 127;
            int n  = n0 + col;
            bReg[l] = (n < N) ? W[(size_t)(kt*16 + kr)*N + n] : 0.f;
        }
    };
    auto storeS = [&](int buf) {
#pragma unroll
        for (int l = 0; l < 2; l++) {
            int lin = tid*2 + l;
            int arow = lin >> 2, kq = lin & 3;
            As[buf][kq*4+0][arow] = aReg[l].x;
            As[buf][kq*4+1][arow] = aReg[l].y;
            As[buf][kq*4+2][arow] = aReg[l].z;
            As[buf][kq*4+3][arow] = aReg[l].w;
        }
#pragma unroll
        for (int l = 0; l < 16; l++) {
            int lin = tid + l*128;
            int kr = lin >> 7, col = lin & 127;
            Bs[buf][kr][col] = bReg[l];
        }
    };

    loadG(0);
    storeS(0);
    __syncthreads();
    int buf = 0;
    for (int kt = 0; kt < KT; kt++) {
        if (kt + 1 < KT) loadG(kt + 1);
#pragma unroll
        for (int k = 0; k < 16; k++) {
            float a[8], bb[8];
            float4 t0 = *(const float4*)&As[buf][k][ty*8];
            float4 t1 = *(const float4*)&As[buf][k][ty*8 + 4];
            a[0]=t0.x; a[1]=t0.y; a[2]=t0.z; a[3]=t0.w;
            a[4]=t1.x; a[5]=t1.y; a[6]=t1.z; a[7]=t1.w;
            float4 u0 = *(const float4*)&Bs[buf][k][tx*8];
            float4 u1 = *(const float4*)&Bs[buf][k][tx*8 + 4];
            bb[0]=u0.x; bb[1]=u0.y; bb[2]=u0.z; bb[3]=u0.w;
            bb[4]=u1.x; bb[5]=u1.y; bb[6]=u1.z; bb[7]=u1.w;
#pragma unroll
            for (int i = 0; i < 8; i++)
#pragma unroll
                for (int j = 0; j < 8; j++)
                    acc[i][j] += a[i]*bb[j];
        }
        if (kt + 1 < KT) storeS(buf ^ 1);
        __syncthreads();
        buf ^= 1;
    }

#pragma unroll
    for (int i = 0; i < 8; i++) {
        int r = m0 + ty*8 + i;
#pragma unroll
        for (int j = 0; j < 8; j++) {
            int n = n0 + tx*8 + j;
            if (n < N) {
                float v = acc[i][j] + bias[n];
                if (MODE == 1) v += res[(size_t)r*N + n];
                if (MODE == 3) v += res[(size_t)(r & (NT-1))*N + n];
                if (MODE == 2) v = 0.5f*v*(1.f + erff(v*0.70710678118654752f));
                C[(size_t)r*N + n] = v;
            }
        }
    }
}

// ---------------- layernorm: row length 768, one block per row ----------------
__global__ void __launch_bounds__(256)
ln_kernel(const float* __restrict__ x, const float* __restrict__ w,
          const float* __restrict__ b, float* __restrict__ y)
{
    __shared__ float red[8];
    __shared__ float sMean, sRstd;
    int r = blockIdx.x, tid = threadIdx.x;
    const float* xr = x + (size_t)r*DM;
    float v0 = xr[tid], v1 = xr[tid+256], v2 = xr[tid+512];

    float s = v0 + v1 + v2;
#pragma unroll
    for (int o = 16; o > 0; o >>= 1) s += __shfl_xor_sync(0xffffffffu, s, o);
    if ((tid & 31) == 0) red[tid >> 5] = s;
    __syncthreads();
    if (tid == 0) {
        float t = 0.f;
#pragma unroll
        for (int i = 0; i < 8; i++) t += red[i];
        sMean = t * (1.f/768.f);
    }
    __syncthreads();
    float mean = sMean;
    float d0 = v0-mean, d1 = v1-mean, d2 = v2-mean;

    float q = d0*d0 + d1*d1 + d2*d2;
#pragma unroll
    for (int o = 16; o > 0; o >>= 1) q += __shfl_xor_sync(0xffffffffu, q, o);
    if ((tid & 31) == 0) red[tid >> 5] = q;
    __syncthreads();
    if (tid == 0) {
        float t = 0.f;
#pragma unroll
        for (int i = 0; i < 8; i++) t += red[i];
        sRstd = rsqrtf(t * (1.f/768.f) + 1e-5f);
    }
    __syncthreads();
    float rstd = sRstd;
    float* yr = y + (size_t)r*DM;
    yr[tid]     = d0*rstd*w[tid]     + b[tid];
    yr[tid+256] = d1*rstd*w[tid+256] + b[tid+256];
    yr[tid+512] = d2*rstd*w[tid+512] + b[tid+512];
}

// ---------------- flash attention, 2-way key split ----------------------------
// grid (B*H, NT/128, 2), block 128.  Each block: 128 queries vs 512 keys.
// Writes unnormalized o, plus (m, l) partials.
__global__ void __launch_bounds__(128)
flash_attn_part(const float* __restrict__ qkv,
                float* __restrict__ po, float2* __restrict__ pml)
{
    __shared__ float Ks[64][64];
    __shared__ float Vs[64][64];
    const int bh = blockIdx.x;
    const int b  = bh / NHEADS, h = bh % NHEADS;
    const int z  = blockIdx.z;
    const int tid = threadIdx.x;
    const int qi  = blockIdx.y*128 + tid;       // 0..1023
    const int row = b*NT + qi;

    float q[64], o[64];
    const float4* qp = (const float4*)(qkv + (size_t)row*(3*DM) + h*DHD);
#pragma unroll
    for (int i = 0; i < 16; i++) {
        float4 v = qp[i];
        q[4*i]=v.x; q[4*i+1]=v.y; q[4*i+2]=v.z; q[4*i+3]=v.w;
    }
#pragma unroll
    for (int i = 0; i < 64; i++) o[i] = 0.f;
    float m = -3.0e38f, l = 0.f;

    for (int kt = z*8; kt < z*8 + 8; kt++) {
        __syncthreads();
        int base = b*NT + kt*64;
        for (int lin = tid; lin < 1024; lin += 128) {
            int j = lin >> 4, qd = lin & 15;
            const float* kr = qkv + (size_t)(base + j)*(3*DM) + h*DHD;
            *(float4*)&Ks[j][qd*4] = *(const float4*)(kr + DM   + qd*4);
            *(float4*)&Vs[j][qd*4] = *(const float4*)(kr + 2*DM + qd*4);
        }
        __syncthreads();
        for (int j0 = 0; j0 < 64; j0 += 4) {
            float s[4];
#pragma unroll
            for (int jj = 0; jj < 4; jj++) {
                float a0=0.f, a1=0.f, a2=0.f, a3=0.f;
#pragma unroll
                for (int d4 = 0; d4 < 16; d4++) {
                    float4 kv = *(const float4*)&Ks[j0+jj][d4*4];
                    a0 += q[d4*4+0]*kv.x;
                    a1 += q[d4*4+1]*kv.y;
                    a2 += q[d4*4+2]*kv.z;
                    a3 += q[d4*4+3]*kv.w;
                }
                s[jj] = ((a0+a1)+(a2+a3)) * 0.125f;
            }
            float smax = fmaxf(fmaxf(s[0],s[1]), fmaxf(s[2],s[3]));
            if (smax > m) {
                float cc = __expf(m - smax);
                m = smax; l *= cc;
#pragma unroll
                for (int d = 0; d < 64; d++) o[d] *= cc;
            }
            float p0 = __expf(s[0]-m), p1 = __expf(s[1]-m);
            float p2 = __expf(s[2]-m), p3 = __expf(s[3]-m);
            l += (p0+p1)+(p2+p3);
#pragma unroll
            for (int d4 = 0; d4 < 16; d4++) {
                float4 v0 = *(const float4*)&Vs[j0  ][d4*4];
                float4 v1 = *(const float4*)&Vs[j0+1][d4*4];
                float4 v2 = *(const float4*)&Vs[j0+2][d4*4];
                float4 v3 = *(const float4*)&Vs[j0+3][d4*4];
                o[d4*4+0] += p0*v0.x + p1*v1.x + p2*v2.x + p3*v3.x;
                o[d4*4+1] += p0*v0.y + p1*v1.y + p2*v2.y + p3*v3.y;
                o[d4*4+2] += p0*v0.z + p1*v1.z + p2*v2.z + p3*v3.z;
                o[d4*4+3] += p0*v0.w + p1*v1.w + p2*v2.w + p3*v3.w;
            }
        }
    }
    size_t pidx = ((size_t)(z*24 + bh)*1024 + qi);
    float4* op = (float4*)(po + pidx*64);
#pragma unroll
    for (int i = 0; i < 16; i++) {
        float4 v;
        v.x=o[4*i]; v.y=o[4*i+1]; v.z=o[4*i+2]; v.w=o[4*i+3];
        op[i] = v;
    }
    float2 ml; ml.x = m; ml.y = l;
    pml[pidx] = ml;
}

// combine the two key-split partials -> attn output [row, h*64+d]
__global__ void __launch_bounds__(256)
attn_combine(const float* __restrict__ po, const float2* __restrict__ pml,
             float* __restrict__ out)
{
    int idx = blockIdx.x*256 + threadIdx.x;       // over 24*1024*64
    if (idx >= 24*1024*64) return;
    int d  = idx & 63;
    int qi = (idx >> 6) & 1023;
    int bh = idx >> 16;
    int b = bh / NHEADS, h = bh % NHEADS;
    size_t i0 = (size_t)bh*1024 + qi;
    size_t i1 = (size_t)(24 + bh)*1024 + qi;
    float2 ml0 = pml[i0], ml1 = pml[i1];
    float mstar = fmaxf(ml0.x, ml1.x);
    float c0 = __expf(ml0.x - mstar), c1 = __expf(ml1.x - mstar);
    float denom = ml0.y*c0 + ml1.y*c1;
    float num = po[i0*64 + d]*c0 + po[i1*64 + d]*c1;
    out[(size_t)(b*NT + qi)*DM + h*DHD + d] = num / denom;
}

// ---------------- FPN transpose + clamped bilinear resize (JAX half-pixel) ----
__global__ void fpn_resize_kernel(const float* __restrict__ g, float* __restrict__ out,
                                  int C, int TS)
{
    int idx = blockIdx.x * 256 + threadIdx.x;
    int total = BT*C*TS*TS;
    if (idx >= total) return;
    int xq = idx % TS;
    int yq = (idx / TS) % TS;
    int c  = (idx / (TS*TS)) % C;
    int b  = idx / (TS*TS*C);
    float s  = 32.0f / (float)TS;
    float sy = ((float)yq + 0.5f)*s - 0.5f;
    float sx = ((float)xq + 0.5f)*s - 0.5f;
    int y0 = (int)floorf(sy); float fy = sy - (float)y0;
    int x0 = (int)floorf(sx); float fx = sx - (float)x0;
    int y0c = min(31, max(0, y0)),   y1c = min(31, max(0, y0+1));
    int x0c = min(31, max(0, x0)),   x1c = min(31, max(0, x0+1));
    const float* gb = g + (size_t)b*1024*C;
    float p00 = gb[(y0c*32 + x0c)*C + c];
    float p01 = gb[(y0c*32 + x1c)*C + c];
    float p10 = gb[(y1c*32 + x0c)*C + c];
    float p11 = gb[(y1c*32 + x1c)*C + c];
    out[idx] = (1.f-fy)*((1.f-fx)*p00 + fx*p01) + fy*((1.f-fx)*p10 + fx*p11);
}

// ---------------- host launcher ----------------
extern "C" void kernel_launch(void* const* d_in, const int* in_sizes, int n_in,
                              void* d_out, int out_size)
{
    (void)in_sizes; (void)n_in; (void)out_size;
    const float* x       = (const float*)d_in[0];
    const float* patch_w = (const float*)d_in[1];
    const float* patch_b = (const float*)d_in[2];
    const float* pos     = (const float*)d_in[3];
    const float* ln1_w   = (const float*)d_in[4];
    const float* ln1_b   = (const float*)d_in[5];
    const float* qkv_w   = (const float*)d_in[6];
    const float* qkv_b   = (const float*)d_in[7];
    const float* proj_w  = (const float*)d_in[8];
    const float* proj_b  = (const float*)d_in[9];
    const float* ln2_w   = (const float*)d_in[10];
    const float* ln2_b   = (const float*)d_in[11];
    const float* fc1_w   = (const float*)d_in[12];
    const float* fc1_b   = (const float*)d_in[13];
    const float* fc2_w   = (const float*)d_in[14];
    const float* fc2_b   = (const float*)d_in[15];
    const float* norm_w  = (const float*)d_in[16];
    const float* norm_b  = (const float*)d_in[17];
    const float* fpn_w[4] = {(const float*)d_in[18], (const float*)d_in[20],
                             (const float*)d_in[22], (const float*)d_in[24]};
    const float* fpn_b[4] = {(const float*)d_in[19], (const float*)d_in[21],
                             (const float*)d_in[23], (const float*)d_in[25]};
    float* out = (float*)d_out;

    static float *p_xp = nullptr, *p_t, *p_h, *p_qkv, *p_attn, *p_mlp, *p_fpn, *p_po;
    static float2 *p_pml;
    if (!p_xp) {  // one-time pointer lookup + smem attribute (outside capture)
        cudaGetSymbolAddress((void**)&p_xp,   g_xp);
        cudaGetSymbolAddress((void**)&p_t,    g_t);
        cudaGetSymbolAddress((void**)&p_h,    g_h);
        cudaGetSymbolAddress((void**)&p_qkv,  g_qkv);
        cudaGetSymbolAddress((void**)&p_attn, g_attn);
        cudaGetSymbolAddress((void**)&p_mlp,  g_mlp);
        cudaGetSymbolAddress((void**)&p_fpn,  g_fpn);
        cudaGetSymbolAddress((void**)&p_po,   g_po);
        cudaGetSymbolAddress((void**)&p_pml,  g_pml);
        cudaFuncSetAttribute(tcgemm<0>, cudaFuncAttributeMaxDynamicSharedMemorySize, SMEM_TC);
        cudaFuncSetAttribute(tcgemm<1>, cudaFuncAttributeMaxDynamicSharedMemorySize, SMEM_TC);
        cudaFuncSetAttribute(tcgemm<2>, cudaFuncAttributeMaxDynamicSharedMemorySize, SMEM_TC);
        cudaFuncSetAttribute(tcgemm<3>, cudaFuncAttributeMaxDynamicSharedMemorySize, SMEM_TC);
    }

    // patch embed: t = xp @ patch_w + patch_b + pos_embed
    patchify_kernel<<<(RR*DM + 255)/256, 256>>>(x, p_xp);
    tcgemm<3><<<dim3(6, 16), 256, SMEM_TC>>>(p_xp, patch_w, patch_b, pos, p_t, DM, DM);

    static const size_t off[4] = {0, 3145728, 4718592, 5505024};

    for (int i = 0; i < DEPTHL; i++) {
        ln_kernel<<<RR, 256>>>(p_t, ln1_w + i*DM, ln1_b + i*DM, p_h);
        tcgemm<0><<<dim3(18, 16), 256, SMEM_TC>>>(p_h, qkv_w + (size_t)i*DM*3*DM,
                                                  qkv_b + (size_t)i*3*DM, nullptr,
                                                  p_qkv, 3*DM, DM);
        flash_attn_part<<<dim3(BT*NHEADS, NT/128, 2), 128>>>(p_qkv, p_po, p_pml);
        attn_combine<<<(24*1024*64 + 255)/256, 256>>>(p_po, p_pml, p_attn);
        tcgemm<1><<<dim3(6, 16), 256, SMEM_TC>>>(p_attn, proj_w + (size_t)i*DM*DM,
                                                 proj_b + (size_t)i*DM, p_t, p_t, DM, DM);
        ln_kernel<<<RR, 256>>>(p_t, ln2_w + i*DM, ln2_b + i*DM, p_h);
        tcgemm<2><<<dim3(24, 16), 256, SMEM_TC>>>(p_h, fc1_w + (size_t)i*DM*HIDF,
                                                  fc1_b + (size_t)i*HIDF, nullptr,
                                                  p_mlp, HIDF, DM);
        tcgemm<1><<<dim3(6, 16), 256, SMEM_TC>>>(p_mlp, fc2_w + (size_t)i*HIDF*DM,
                                                 fc2_b + (size_t)i*DM, p_t, p_t, DM, HIDF);

        int e = (i == 3) ? 0 : (i == 6) ? 1 : (i == 9) ? 2 : (i == 11) ? 3 : -1;
        if (e >= 0) {
            int oc = 96 << e, ts = 128 >> e;
            ln_kernel<<<RR, 256>>>(p_t, norm_w, norm_b, p_h);
            sgemm_kernel<0><<<dim3((oc + 127)/128, 32), 128>>>(p_h, fpn_w[e], fpn_b[e],
                                                               nullptr, p_fpn, RR, oc, DM);
            int total = BT*oc*ts*ts;
            fpn_resize_kernel<<<(total + 255)/256, 256>>>(p_fpn, out + off[e], oc, ts);
        }
    }
}

// round 12
// speedup vs baseline: 2.4847x; 1.1249x over previous
#include <cuda_runtime.h>
#include <math.h>
#include <stdint.h>

#define DEPTHL 12
#define DM     768
#define NT     1024
#define BT     2
#define RR     (BT*NT)      // 2048 rows
#define HIDF   3072
#define NHEADS 12
#define DHD    64

// ---------------- scratch (static device globals; no allocation) ----------------
__device__ float g_xp[RR*DM];
__device__ float g_t[RR*DM];
__device__ float g_h[RR*DM];
__device__ float g_qkv[RR*3*DM];
__device__ float g_attn[RR*DM];
__device__ float g_mlp[RR*HIDF];
__device__ float g_fpn[RR*DM];
// attention split partials: [split][bh][query][64] + (m,l)
__device__ float  g_po[2*24*1024*64];
__device__ float2 g_pml[2*24*1024];
// pre-rounded (tf32) weights
__device__ float g_patchw[DM*DM];
__device__ float g_qkvw[DEPTHL*DM*3*DM];
__device__ float g_projw[DEPTHL*DM*DM];
__device__ float g_fc1w[DEPTHL*DM*HIDF];
__device__ float g_fc2w[DEPTHL*HIDF*DM];

// ---------------- f32x2 packed helpers ----------------
__device__ __forceinline__ unsigned long long pack2(float lo, float hi) {
    unsigned long long r;
    asm("mov.b64 %0, {%1, %2};" : "=l"(r) : "f"(lo), "f"(hi));
    return r;
}
#define FMA2(d, a, b, c) \
    asm("fma.rn.f32x2 %0, %1, %2, %3;" : "=l"(d) : "l"(a), "l"(b), "l"(c))
#define MUL2(d, a, b) \
    asm("mul.rn.f32x2 %0, %1, %2;" : "=l"(d) : "l"(a), "l"(b))
#define UNPK2(lo, hi, v) \
    asm("mov.b64 {%0, %1}, %2;" : "=f"(lo), "=f"(hi) : "l"(v))

// ---------------- patchify: x[B,3,512,512] -> xp[B*N, 768] ----------------
__global__ void patchify_kernel(const float* __restrict__ x, float* __restrict__ xp) {
    int idx = blockIdx.x * 256 + threadIdx.x;
    if (idx >= RR*DM) return;
    int col = idx % DM;
    int r   = idx / DM;
    int b   = r >> 10, n = r & 1023;
    int gy  = n >> 5,  gx = n & 31;
    int c   = col >> 8;
    int rem = col & 255;
    int py  = rem >> 4, px = rem & 15;
    xp[idx] = x[((size_t)(b*3 + c)*512 + (gy*16 + py))*512 + (gx*16 + px)];
}

// ---------------- round fp32 -> tf32-in-fp32 (rna), vectorized ----------------
__device__ __forceinline__ uint32_t f2tf32(float f) {
    uint32_t u;
    asm("cvt.rna.tf32.f32 %0, %1;" : "=r"(u) : "f"(f));
    return u;
}
__global__ void round_tf32_kernel(const float* __restrict__ src,
                                  float* __restrict__ dst, int n4) {
    int i = blockIdx.x * 256 + threadIdx.x;
    if (i >= n4) return;
    float4 v = *(const float4*)(src + (size_t)i*4);
    v.x = __uint_as_float(f2tf32(v.x));
    v.y = __uint_as_float(f2tf32(v.y));
    v.z = __uint_as_float(f2tf32(v.z));
    v.w = __uint_as_float(f2tf32(v.w));
    *(float4*)(dst + (size_t)i*4) = v;
}

// ================= tf32 mma.sync GEMM v4 ======================================
// C = A[M,K] @ W[K,N] + epilogue.  BM=128, BN=128, BK=32, 256 thr, 8 warps 4x2,
// warp tile 32x64.  2-stage cp.async, 2 CTAs/SM.  W is PRE-ROUNDED to tf32 bits
// (no cvt on B path); A cvt'd after LDS.
// MODE 0: +bias   1: +bias+res[r,n]   2: +bias,GELU   3: +bias+res[r&1023,n]

__device__ __forceinline__ void mma_tf32(float* d, const uint32_t* a, const uint32_t* b) {
    asm volatile(
        "mma.sync.aligned.m16n8k8.row.col.f32.tf32.tf32.f32 "
        "{%0,%1,%2,%3}, {%4,%5,%6,%7}, {%8,%9}, {%0,%1,%2,%3};"
        : "+f"(d[0]), "+f"(d[1]), "+f"(d[2]), "+f"(d[3])
        : "r"(a[0]), "r"(a[1]), "r"(a[2]), "r"(a[3]), "r"(b[0]), "r"(b[1]));
}
__device__ __forceinline__ uint32_t smem_u32p(const void* p) {
    uint32_t a;
    asm("{ .reg .u64 t; cvta.to.shared.u64 t, %1; cvt.u32.u64 %0, t; }" : "=r"(a) : "l"(p));
    return a;
}
#define CP16(dst, src) \
    asm volatile("cp.async.cg.shared.global [%0], [%1], 16;" :: "r"(dst), "l"(src))
#define CP_COMMIT() asm volatile("cp.async.commit_group;")
#define CP_WAIT1()  asm volatile("cp.async.wait_group 1;" ::: "memory")

#define ASTG 4608                 // 128*36 floats
#define BSTG 4352                 // 32*136 floats
#define STG  (ASTG+BSTG)          // 8960 floats / stage
#define SMEM_TC (2*STG*4)         // 71680 bytes

template<int MODE>
__global__ void __launch_bounds__(256, 2)
tcgemm(const float* __restrict__ A, const float* __restrict__ W,
       const float* __restrict__ bias, const float* __restrict__ res,
       float* __restrict__ C, int Nt, int K)
{
    extern __shared__ float dyn[];
    const int tid = threadIdx.x;
    const int wid = tid >> 5;
    const int lane = tid & 31;
    const int warp_m = wid >> 1;
    const int warp_n = wid & 1;
    const int r = lane >> 2, cq = lane & 3;
    const int m0 = blockIdx.y * 128;
    const int n0 = blockIdx.x * 128;
    const int NC = K >> 5;

    const uint32_t sbase = smem_u32p(dyn);

    int a_row[4], a_kq[4], b_kr[4], b_nq[4];
#pragma unroll
    for (int i = 0; i < 4; i++) {
        int c = tid + i*256;
        a_row[i] = c >> 3;  a_kq[i] = (c & 7)*4;
        b_kr[i] = c >> 5;   b_nq[i] = (c & 31)*4;
    }

    auto issue = [&](int kc, int st) {
        const uint32_t sA = sbase + (uint32_t)(st*STG)*4u;
        const uint32_t sB = sA + (uint32_t)ASTG*4u;
#pragma unroll
        for (int i = 0; i < 4; i++) {
            const float* src = A + (size_t)(m0 + a_row[i])*K + kc*32 + a_kq[i];
            CP16(sA + (uint32_t)(a_row[i]*36 + a_kq[i])*4u, src);
        }
#pragma unroll
        for (int i = 0; i < 4; i++) {
            const float* src = W + (size_t)(kc*32 + b_kr[i])*Nt + n0 + b_nq[i];
            CP16(sB + (uint32_t)(b_kr[i]*136 + b_nq[i])*4u, src);
        }
        CP_COMMIT();
    };

    float acc[2][8][4];
#pragma unroll
    for (int mf = 0; mf < 2; mf++)
#pragma unroll
        for (int nf = 0; nf < 8; nf++)
#pragma unroll
            for (int k = 0; k < 4; k++) acc[mf][nf][k] = 0.f;

    issue(0, 0);

    for (int kc = 0; kc < NC; kc++) {
        if (kc + 1 < NC) issue(kc + 1, (kc + 1) & 1);
        else CP_COMMIT();
        CP_WAIT1();
        __syncthreads();

        const int st = kc & 1;
        const float* Ab = dyn + st*STG + (warp_m*32)*36;
        const uint32_t* Bb = (const uint32_t*)(dyn + st*STG + ASTG) + warp_n*64;
#pragma unroll
        for (int kk = 0; kk < 4; kk++) {
            const int ko = kk*8;
            uint32_t afr[2][4];
#pragma unroll
            for (int mf = 0; mf < 2; mf++) {
                int base = (mf*16 + r)*36 + ko + cq;
                afr[mf][0] = f2tf32(Ab[base]);
                afr[mf][1] = f2tf32(Ab[base + 8*36]);
                afr[mf][2] = f2tf32(Ab[base + 4]);
                afr[mf][3] = f2tf32(Ab[base + 8*36 + 4]);
            }
#pragma unroll
            for (int nf = 0; nf < 8; nf++) {
                int nn = nf*8 + r;
                uint32_t bfr[2];
                bfr[0] = Bb[(ko + cq)*136 + nn];        // pre-rounded bits
                bfr[1] = Bb[(ko + cq + 4)*136 + nn];
                mma_tf32(acc[0][nf], afr[0], bfr);
                mma_tf32(acc[1][nf], afr[1], bfr);
            }
        }
        __syncthreads();
    }

    const int rb = m0 + warp_m*32;
    const int cb = n0 + warp_n*64;
#pragma unroll
    for (int mf = 0; mf < 2; mf++) {
#pragma unroll
        for (int half = 0; half < 2; half++) {
            int row = rb + mf*16 + r + half*8;
            const float* Rrow = nullptr;
            if (MODE == 1) Rrow = res + (size_t)row*Nt;
            if (MODE == 3) Rrow = res + (size_t)(row & (NT-1))*Nt;
            float* Crow = C + (size_t)row*Nt;
#pragma unroll
            for (int nf = 0; nf < 8; nf++) {
                int col = cb + nf*8 + cq*2;
                float v0 = acc[mf][nf][half*2 + 0] + bias[col];
                float v1 = acc[mf][nf][half*2 + 1] + bias[col + 1];
                if (MODE == 1 || MODE == 3) { v0 += Rrow[col]; v1 += Rrow[col+1]; }
                if (MODE == 2) {
                    v0 = 0.5f*v0*(1.f + erff(v0*0.70710678118654752f));
                    v1 = 0.5f*v1*(1.f + erff(v1*0.70710678118654752f));
                }
                float2 o; o.x = v0; o.y = v1;
                *(float2*)(Crow + col) = o;
            }
        }
    }
}

// ---------------- SIMT SGEMM (FPN heads only) ----------------
template<int MODE>
__global__ void __launch_bounds__(128)
sgemm_kernel(const float* __restrict__ A, const float* __restrict__ W,
             const float* __restrict__ bias, const float* res, float* C,
             int M, int N, int K)
{
    __shared__ float As[2][16][64];
    __shared__ float Bs[2][16][128];
    const int tid = threadIdx.x;
    const int m0  = blockIdx.y * 64;
    const int n0  = blockIdx.x * 128;
    const int tx  = tid & 15, ty = tid >> 4;

    float acc[8][8];
#pragma unroll
    for (int i = 0; i < 8; i++)
#pragma unroll
        for (int j = 0; j < 8; j++) acc[i][j] = 0.f;

    const int KT = K >> 4;
    float4 aReg[2];
    float  bReg[16];

    auto loadG = [&](int kt) {
#pragma unroll
        for (int l = 0; l < 2; l++) {
            int lin = tid*2 + l;
            int arow = lin >> 2, kq = lin & 3;
            aReg[l] = *(const float4*)(A + (size_t)(m0 + arow)*K + kt*16 + kq*4);
        }
#pragma unroll
        for (int l = 0; l < 16; l++) {
            int lin = tid + l*128;
            int kr = lin >> 7, col = lin & 127;
            int n  = n0 + col;
            bReg[l] = (n < N) ? W[(size_t)(kt*16 + kr)*N + n] : 0.f;
        }
    };
    auto storeS = [&](int buf) {
#pragma unroll
        for (int l = 0; l < 2; l++) {
            int lin = tid*2 + l;
            int arow = lin >> 2, kq = lin & 3;
            As[buf][kq*4+0][arow] = aReg[l].x;
            As[buf][kq*4+1][arow] = aReg[l].y;
            As[buf][kq*4+2][arow] = aReg[l].z;
            As[buf][kq*4+3][arow] = aReg[l].w;
        }
#pragma unroll
        for (int l = 0; l < 16; l++) {
            int lin = tid + l*128;
            int kr = lin >> 7, col = lin & 127;
            Bs[buf][kr][col] = bReg[l];
        }
    };

    loadG(0);
    storeS(0);
    __syncthreads();
    int buf = 0;
    for (int kt = 0; kt < KT; kt++) {
        if (kt + 1 < KT) loadG(kt + 1);
#pragma unroll
        for (int k = 0; k < 16; k++) {
            float a[8], bb[8];
            float4 t0 = *(const float4*)&As[buf][k][ty*8];
            float4 t1 = *(const float4*)&As[buf][k][ty*8 + 4];
            a[0]=t0.x; a[1]=t0.y; a[2]=t0.z; a[3]=t0.w;
            a[4]=t1.x; a[5]=t1.y; a[6]=t1.z; a[7]=t1.w;
            float4 u0 = *(const float4*)&Bs[buf][k][tx*8];
            float4 u1 = *(const float4*)&Bs[buf][k][tx*8 + 4];
            bb[0]=u0.x; bb[1]=u0.y; bb[2]=u0.z; bb[3]=u0.w;
            bb[4]=u1.x; bb[5]=u1.y; bb[6]=u1.z; bb[7]=u1.w;
#pragma unroll
            for (int i = 0; i < 8; i++)
#pragma unroll
                for (int j = 0; j < 8; j++)
                    acc[i][j] += a[i]*bb[j];
        }
        if (kt + 1 < KT) storeS(buf ^ 1);
        __syncthreads();
        buf ^= 1;
    }

#pragma unroll
    for (int i = 0; i < 8; i++) {
        int r = m0 + ty*8 + i;
#pragma unroll
        for (int j = 0; j < 8; j++) {
            int n = n0 + tx*8 + j;
            if (n < N) {
                float v = acc[i][j] + bias[n];
                if (MODE == 1) v += res[(size_t)r*N + n];
                if (MODE == 3) v += res[(size_t)(r & (NT-1))*N + n];
                if (MODE == 2) v = 0.5f*v*(1.f + erff(v*0.70710678118654752f));
                C[(size_t)r*N + n] = v;
            }
        }
    }
}

// ---------------- layernorm: row length 768, one block per row ----------------
__global__ void __launch_bounds__(256)
ln_kernel(const float* __restrict__ x, const float* __restrict__ w,
          const float* __restrict__ b, float* __restrict__ y)
{
    __shared__ float red[8];
    __shared__ float sMean, sRstd;
    int r = blockIdx.x, tid = threadIdx.x;
    const float* xr = x + (size_t)r*DM;
    float v0 = xr[tid], v1 = xr[tid+256], v2 = xr[tid+512];

    float s = v0 + v1 + v2;
#pragma unroll
    for (int o = 16; o > 0; o >>= 1) s += __shfl_xor_sync(0xffffffffu, s, o);
    if ((tid & 31) == 0) red[tid >> 5] = s;
    __syncthreads();
    if (tid == 0) {
        float t = 0.f;
#pragma unroll
        for (int i = 0; i < 8; i++) t += red[i];
        sMean = t * (1.f/768.f);
    }
    __syncthreads();
    float mean = sMean;
    float d0 = v0-mean, d1 = v1-mean, d2 = v2-mean;

    float q = d0*d0 + d1*d1 + d2*d2;
#pragma unroll
    for (int o = 16; o > 0; o >>= 1) q += __shfl_xor_sync(0xffffffffu, q, o);
    if ((tid & 31) == 0) red[tid >> 5] = q;
    __syncthreads();
    if (tid == 0) {
        float t = 0.f;
#pragma unroll
        for (int i = 0; i < 8; i++) t += red[i];
        sRstd = rsqrtf(t * (1.f/768.f) + 1e-5f);
    }
    __syncthreads();
    float rstd = sRstd;
    float* yr = y + (size_t)r*DM;
    yr[tid]     = d0*rstd*w[tid]     + b[tid];
    yr[tid+256] = d1*rstd*w[tid+256] + b[tid+256];
    yr[tid+512] = d2*rstd*w[tid+512] + b[tid+512];
}

// ---------------- flash attention, 2-way key split, packed f32x2 --------------
// grid (B*H, NT/128, 2), block 128.  Each block: 128 queries vs 512 keys.
__global__ void __launch_bounds__(128)
flash_attn_part(const float* __restrict__ qkv,
                float* __restrict__ po, float2* __restrict__ pml)
{
    __shared__ float Ks[64][64];
    __shared__ float Vs[64][64];
    const int bh = blockIdx.x;
    const int b  = bh / NHEADS, h = bh % NHEADS;
    const int z  = blockIdx.z;
    const int tid = threadIdx.x;
    const int qi  = blockIdx.y*128 + tid;
    const int row = b*NT + qi;

    unsigned long long q2[32], o2[32];
    const ulonglong2* qp = (const ulonglong2*)(qkv + (size_t)row*(3*DM) + h*DHD);
#pragma unroll
    for (int i = 0; i < 16; i++) {
        ulonglong2 t = qp[i];
        q2[2*i] = t.x; q2[2*i+1] = t.y;
    }
#pragma unroll
    for (int i = 0; i < 32; i++) o2[i] = 0ULL;
    float m = -3.0e38f, l = 0.f;

    for (int kt = z*8; kt < z*8 + 8; kt++) {
        __syncthreads();
        int base = b*NT + kt*64;
        for (int lin = tid; lin < 1024; lin += 128) {
            int j = lin >> 4, qd = lin & 15;
            const float* kr = qkv + (size_t)(base + j)*(3*DM) + h*DHD;
            *(float4*)&Ks[j][qd*4] = *(const float4*)(kr + DM   + qd*4);
            *(float4*)&Vs[j][qd*4] = *(const float4*)(kr + 2*DM + qd*4);
        }
        __syncthreads();
        for (int j0 = 0; j0 < 64; j0 += 4) {
            float s[4];
#pragma unroll
            for (int jj = 0; jj < 4; jj++) {
                unsigned long long acc0 = 0ULL, acc1 = 0ULL;
                const ulonglong2* kr2 = (const ulonglong2*)&Ks[j0+jj][0];
#pragma unroll
                for (int i = 0; i < 16; i++) {
                    ulonglong2 kk = kr2[i];
                    FMA2(acc0, q2[2*i],   kk.x, acc0);
                    FMA2(acc1, q2[2*i+1], kk.y, acc1);
                }
                float a0, a1, a2, a3;
                UNPK2(a0, a1, acc0);
                UNPK2(a2, a3, acc1);
                s[jj] = ((a0+a1)+(a2+a3)) * 0.125f;
            }
            float smax = fmaxf(fmaxf(s[0],s[1]), fmaxf(s[2],s[3]));
            if (smax > m) {
                float cc = __expf(m - smax);
                m = smax; l *= cc;
                unsigned long long cc2 = pack2(cc, cc);
#pragma unroll
                for (int d = 0; d < 32; d++) MUL2(o2[d], o2[d], cc2);
            }
            float p0 = __expf(s[0]-m), p1 = __expf(s[1]-m);
            float p2 = __expf(s[2]-m), p3 = __expf(s[3]-m);
            l += (p0+p1)+(p2+p3);
            unsigned long long p0_2 = pack2(p0,p0), p1_2 = pack2(p1,p1);
            unsigned long long p2_2 = pack2(p2,p2), p3_2 = pack2(p3,p3);
            const ulonglong2* v0p = (const ulonglong2*)&Vs[j0  ][0];
            const ulonglong2* v1p = (const ulonglong2*)&Vs[j0+1][0];
            const ulonglong2* v2p = (const ulonglong2*)&Vs[j0+2][0];
            const ulonglong2* v3p = (const ulonglong2*)&Vs[j0+3][0];
#pragma unroll
            for (int i = 0; i < 16; i++) {
                ulonglong2 w0 = v0p[i], w1 = v1p[i], w2 = v2p[i], w3 = v3p[i];
                FMA2(o2[2*i],   p0_2, w0.x, o2[2*i]);
                FMA2(o2[2*i+1], p0_2, w0.y, o2[2*i+1]);
                FMA2(o2[2*i],   p1_2, w1.x, o2[2*i]);
                FMA2(o2[2*i+1], p1_2, w1.y, o2[2*i+1]);
                FMA2(o2[2*i],   p2_2, w2.x, o2[2*i]);
                FMA2(o2[2*i+1], p2_2, w2.y, o2[2*i+1]);
                FMA2(o2[2*i],   p3_2, w3.x, o2[2*i]);
                FMA2(o2[2*i+1], p3_2, w3.y, o2[2*i+1]);
            }
        }
    }
    size_t pidx = ((size_t)(z*24 + bh)*1024 + qi);
    float4* op = (float4*)(po + pidx*64);
#pragma unroll
    for (int i = 0; i < 16; i++) {
        float4 v;
        UNPK2(v.x, v.y, o2[2*i]);
        UNPK2(v.z, v.w, o2[2*i+1]);
        op[i] = v;
    }
    float2 ml; ml.x = m; ml.y = l;
    pml[pidx] = ml;
}

// combine the two key-split partials -> attn output [row, h*64+d]
__global__ void __launch_bounds__(256)
attn_combine(const float* __restrict__ po, const float2* __restrict__ pml,
             float* __restrict__ out)
{
    int idx = blockIdx.x*256 + threadIdx.x;       // over 24*1024*64
    if (idx >= 24*1024*64) return;
    int d  = idx & 63;
    int qi = (idx >> 6) & 1023;
    int bh = idx >> 16;
    int b = bh / NHEADS, h = bh % NHEADS;
    size_t i0 = (size_t)bh*1024 + qi;
    size_t i1 = (size_t)(24 + bh)*1024 + qi;
    float2 ml0 = pml[i0], ml1 = pml[i1];
    float mstar = fmaxf(ml0.x, ml1.x);
    float c0 = __expf(ml0.x - mstar), c1 = __expf(ml1.x - mstar);
    float denom = ml0.y*c0 + ml1.y*c1;
    float num = po[i0*64 + d]*c0 + po[i1*64 + d]*c1;
    out[(size_t)(b*NT + qi)*DM + h*DHD + d] = num / denom;
}

// ---------------- FPN transpose + clamped bilinear resize (JAX half-pixel) ----
__global__ void fpn_resize_kernel(const float* __restrict__ g, float* __restrict__ out,
                                  int C, int TS)
{
    int idx = blockIdx.x * 256 + threadIdx.x;
    int total = BT*C*TS*TS;
    if (idx >= total) return;
    int xq = idx % TS;
    int yq = (idx / TS) % TS;
    int c  = (idx / (TS*TS)) % C;
    int b  = idx / (TS*TS*C);
    float s  = 32.0f / (float)TS;
    float sy = ((float)yq + 0.5f)*s - 0.5f;
    float sx = ((float)xq + 0.5f)*s - 0.5f;
    int y0 = (int)floorf(sy); float fy = sy - (float)y0;
    int x0 = (int)floorf(sx); float fx = sx - (float)x0;
    int y0c = min(31, max(0, y0)),   y1c = min(31, max(0, y0+1));
    int x0c = min(31, max(0, x0)),   x1c = min(31, max(0, x0+1));
    const float* gb = g + (size_t)b*1024*C;
    float p00 = gb[(y0c*32 + x0c)*C + c];
    float p01 = gb[(y0c*32 + x1c)*C + c];
    float p10 = gb[(y1c*32 + x0c)*C + c];
    float p11 = gb[(y1c*32 + x1c)*C + c];
    out[idx] = (1.f-fy)*((1.f-fx)*p00 + fx*p01) + fy*((1.f-fx)*p10 + fx*p11);
}

// ---------------- host launcher ----------------
extern "C" void kernel_launch(void* const* d_in, const int* in_sizes, int n_in,
                              void* d_out, int out_size)
{
    (void)in_sizes; (void)n_in; (void)out_size;
    const float* x       = (const float*)d_in[0];
    const float* patch_w = (const float*)d_in[1];
    const float* patch_b = (const float*)d_in[2];
    const float* pos     = (const float*)d_in[3];
    const float* ln1_w   = (const float*)d_in[4];
    const float* ln1_b   = (const float*)d_in[5];
    const float* qkv_w   = (const float*)d_in[6];
    const float* qkv_b   = (const float*)d_in[7];
    const float* proj_w  = (const float*)d_in[8];
    const float* proj_b  = (const float*)d_in[9];
    const float* ln2_w   = (const float*)d_in[10];
    const float* ln2_b   = (const float*)d_in[11];
    const float* fc1_w   = (const float*)d_in[12];
    const float* fc1_b   = (const float*)d_in[13];
    const float* fc2_w   = (const float*)d_in[14];
    const float* fc2_b   = (const float*)d_in[15];
    const float* norm_w  = (const float*)d_in[16];
    const float* norm_b  = (const float*)d_in[17];
    const float* fpn_w[4] = {(const float*)d_in[18], (const float*)d_in[20],
                             (const float*)d_in[22], (const float*)d_in[24]};
    const float* fpn_b[4] = {(const float*)d_in[19], (const float*)d_in[21],
                             (const float*)d_in[23], (const float*)d_in[25]};
    float* out = (float*)d_out;

    static float *p_xp = nullptr, *p_t, *p_h, *p_qkv, *p_attn, *p_mlp, *p_fpn, *p_po;
    static float2 *p_pml;
    static float *p_patchw, *p_qkvw, *p_projw, *p_fc1w, *p_fc2w;
    if (!p_xp) {  // one-time pointer lookup + smem attribute (outside capture)
        cudaGetSymbolAddress((void**)&p_xp,   g_xp);
        cudaGetSymbolAddress((void**)&p_t,    g_t);
        cudaGetSymbolAddress((void**)&p_h,    g_h);
        cudaGetSymbolAddress((void**)&p_qkv,  g_qkv);
        cudaGetSymbolAddress((void**)&p_attn, g_attn);
        cudaGetSymbolAddress((void**)&p_mlp,  g_mlp);
        cudaGetSymbolAddress((void**)&p_fpn,  g_fpn);
        cudaGetSymbolAddress((void**)&p_po,   g_po);
        cudaGetSymbolAddress((void**)&p_pml,  g_pml);
        cudaGetSymbolAddress((void**)&p_patchw, g_patchw);
        cudaGetSymbolAddress((void**)&p_qkvw,   g_qkvw);
        cudaGetSymbolAddress((void**)&p_projw,  g_projw);
        cudaGetSymbolAddress((void**)&p_fc1w,   g_fc1w);
        cudaGetSymbolAddress((void**)&p_fc2w,   g_fc2w);
        cudaFuncSetAttribute(tcgemm<0>, cudaFuncAttributeMaxDynamicSharedMemorySize, SMEM_TC);
        cudaFuncSetAttribute(tcgemm<1>, cudaFuncAttributeMaxDynamicSharedMemorySize, SMEM_TC);
        cudaFuncSetAttribute(tcgemm<2>, cudaFuncAttributeMaxDynamicSharedMemorySize, SMEM_TC);
        cudaFuncSetAttribute(tcgemm<3>, cudaFuncAttributeMaxDynamicSharedMemorySize, SMEM_TC);
    }

    // pre-round all transformer weights to tf32 (once per call)
    {
        int n;
        n = DM*DM/4;              round_tf32_kernel<<<(n+255)/256, 256>>>(patch_w, p_patchw, n);
        n = DEPTHL*DM*3*DM/4;     round_tf32_kernel<<<(n+255)/256, 256>>>(qkv_w,   p_qkvw,   n);
        n = DEPTHL*DM*DM/4;       round_tf32_kernel<<<(n+255)/256, 256>>>(proj_w,  p_projw,  n);
        n = DEPTHL*DM*HIDF/4;     round_tf32_kernel<<<(n+255)/256, 256>>>(fc1_w,   p_fc1w,   n);
        n = DEPTHL*HIDF*DM/4;     round_tf32_kernel<<<(n+255)/256, 256>>>(fc2_w,   p_fc2w,   n);
    }

    // patch embed: t = xp @ patch_w + patch_b + pos_embed
    patchify_kernel<<<(RR*DM + 255)/256, 256>>>(x, p_xp);
    tcgemm<3><<<dim3(6, 16), 256, SMEM_TC>>>(p_xp, p_patchw, patch_b, pos, p_t, DM, DM);

    static const size_t off[4] = {0, 3145728, 4718592, 5505024};

    for (int i = 0; i < DEPTHL; i++) {
        ln_kernel<<<RR, 256>>>(p_t, ln1_w + i*DM, ln1_b + i*DM, p_h);
        tcgemm<0><<<dim3(18, 16), 256, SMEM_TC>>>(p_h, p_qkvw + (size_t)i*DM*3*DM,
                                                  qkv_b + (size_t)i*3*DM, nullptr,
                                                  p_qkv, 3*DM, DM);
        flash_attn_part<<<dim3(BT*NHEADS, NT/128, 2), 128>>>(p_qkv, p_po, p_pml);
        attn_combine<<<(24*1024*64 + 255)/256, 256>>>(p_po, p_pml, p_attn);
        tcgemm<1><<<dim3(6, 16), 256, SMEM_TC>>>(p_attn, p_projw + (size_t)i*DM*DM,
                                                 proj_b + (size_t)i*DM, p_t, p_t, DM, DM);
        ln_kernel<<<RR, 256>>>(p_t, ln2_w + i*DM, ln2_b + i*DM, p_h);
        tcgemm<2><<<dim3(24, 16), 256, SMEM_TC>>>(p_h, p_fc1w + (size_t)i*DM*HIDF,
                                                  fc1_b + (size_t)i*HIDF, nullptr,
                                                  p_mlp, HIDF, DM);
        tcgemm<1><<<dim3(6, 16), 256, SMEM_TC>>>(p_mlp, p_fc2w + (size_t)i*HIDF*DM,
                                                 fc2_b + (size_t)i*DM, p_t, p_t, DM, HIDF);

        int e = (i == 3) ? 0 : (i == 6) ? 1 : (i == 9) ? 2 : (i == 11) ? 3 : -1;
        if (e >= 0) {
            int oc = 96 << e, ts = 128 >> e;
            ln_kernel<<<RR, 256>>>(p_t, norm_w, norm_b, p_h);
            sgemm_kernel<0><<<dim3((oc + 127)/128, 32), 128>>>(p_h, fpn_w[e], fpn_b[e],
                                                               nullptr, p_fpn, RR, oc, DM);
            int total = BT*oc*ts*ts;
            fpn_resize_kernel<<<(total + 255)/256, 256>>>(p_fpn, out + off[e], oc, ts);
        }
    }
}

// round 13
// speedup vs baseline: 2.5376x; 1.0213x over previous
#include <cuda_runtime.h>
#include <math.h>
#include <stdint.h>

#define DEPTHL 12
#define DM     768
#define NT     1024
#define BT     2
#define RR     (BT*NT)      // 2048 rows
#define HIDF   3072
#define NHEADS 12
#define DHD    64
#define NSPL   4            // attention key splits

// ---------------- scratch (static device globals; no allocation) ----------------
__device__ float g_xp[RR*DM];
__device__ float g_t[RR*DM];
__device__ float g_h[RR*DM];
__device__ float g_qkv[RR*3*DM];
__device__ float g_attn[RR*DM];
__device__ float g_mlp[RR*HIDF];
__device__ float g_fpn[RR*DM];
// attention split partials: [split][bh][query][64] + (m,l)
__device__ float  g_po[NSPL*24*1024*64];
__device__ float2 g_pml[NSPL*24*1024];
// pre-rounded (tf32) weights
__device__ float g_patchw[DM*DM];
__device__ float g_qkvw[DEPTHL*DM*3*DM];
__device__ float g_projw[DEPTHL*DM*DM];
__device__ float g_fc1w[DEPTHL*DM*HIDF];
__device__ float g_fc2w[DEPTHL*HIDF*DM];

// ---------------- f32x2 packed helpers ----------------
__device__ __forceinline__ unsigned long long pack2(float lo, float hi) {
    unsigned long long r;
    asm("mov.b64 %0, {%1, %2};" : "=l"(r) : "f"(lo), "f"(hi));
    return r;
}
#define FMA2(d, a, b, c) \
    asm("fma.rn.f32x2 %0, %1, %2, %3;" : "=l"(d) : "l"(a), "l"(b), "l"(c))
#define MUL2(d, a, b) \
    asm("mul.rn.f32x2 %0, %1, %2;" : "=l"(d) : "l"(a), "l"(b))
#define UNPK2(lo, hi, v) \
    asm("mov.b64 {%0, %1}, %2;" : "=f"(lo), "=f"(hi) : "l"(v))

__device__ __forceinline__ uint32_t f2tf32(float f) {
    uint32_t u;
    asm("cvt.rna.tf32.f32 %0, %1;" : "=r"(u) : "f"(f));
    return u;
}
__device__ __forceinline__ float rtf(float f) { return __uint_as_float(f2tf32(f)); }

// ---------------- patchify: x[B,3,512,512] -> xp[B*N, 768] (tf32-rounded) -----
__global__ void patchify_kernel(const float* __restrict__ x, float* __restrict__ xp) {
    int idx = blockIdx.x * 256 + threadIdx.x;
    if (idx >= RR*DM) return;
    int col = idx % DM;
    int r   = idx / DM;
    int b   = r >> 10, n = r & 1023;
    int gy  = n >> 5,  gx = n & 31;
    int c   = col >> 8;
    int rem = col & 255;
    int py  = rem >> 4, px = rem & 15;
    xp[idx] = rtf(x[((size_t)(b*3 + c)*512 + (gy*16 + py))*512 + (gx*16 + px)]);
}

// ---------------- round fp32 -> tf32-in-fp32 (rna), vectorized ----------------
__global__ void round_tf32_kernel(const float* __restrict__ src,
                                  float* __restrict__ dst, int n4) {
    int i = blockIdx.x * 256 + threadIdx.x;
    if (i >= n4) return;
    float4 v = *(const float4*)(src + (size_t)i*4);
    v.x = rtf(v.x); v.y = rtf(v.y); v.z = rtf(v.z); v.w = rtf(v.w);
    *(float4*)(dst + (size_t)i*4) = v;
}

// ================= tf32 mma.sync GEMM v5 ======================================
// C = A[M,K] @ W[K,N] + epilogue.  BM=128, BN=128, BK=32, 256 thr, 8 warps 4x2,
// warp tile 32x64.  2-stage cp.async, 2 CTAs/SM.  BOTH operands pre-rounded to
// tf32 bits by their producers -> zero cvt in the hot loop.
// MODE 0: +bias   1: +bias+res[r,n]   2: +bias,GELU(tf32-rounded out)
// MODE 3: +bias+res[r&1023,n]

__device__ __forceinline__ void mma_tf32(float* d, const uint32_t* a, const uint32_t* b) {
    asm volatile(
        "mma.sync.aligned.m16n8k8.row.col.f32.tf32.tf32.f32 "
        "{%0,%1,%2,%3}, {%4,%5,%6,%7}, {%8,%9}, {%0,%1,%2,%3};"
        : "+f"(d[0]), "+f"(d[1]), "+f"(d[2]), "+f"(d[3])
        : "r"(a[0]), "r"(a[1]), "r"(a[2]), "r"(a[3]), "r"(b[0]), "r"(b[1]));
}
__device__ __forceinline__ uint32_t smem_u32p(const void* p) {
    uint32_t a;
    asm("{ .reg .u64 t; cvta.to.shared.u64 t, %1; cvt.u32.u64 %0, t; }" : "=r"(a) : "l"(p));
    return a;
}
#define CP16(dst, src) \
    asm volatile("cp.async.cg.shared.global [%0], [%1], 16;" :: "r"(dst), "l"(src))
#define CP_COMMIT() asm volatile("cp.async.commit_group;")
#define CP_WAIT1()  asm volatile("cp.async.wait_group 1;" ::: "memory")

#define ASTG 4608                 // 128*36 floats
#define BSTG 4352                 // 32*136 floats
#define STG  (ASTG+BSTG)          // 8960 floats / stage
#define SMEM_TC (2*STG*4)         // 71680 bytes

template<int MODE>
__global__ void __launch_bounds__(256, 2)
tcgemm(const float* __restrict__ A, const float* __restrict__ W,
       const float* __restrict__ bias, const float* __restrict__ res,
       float* __restrict__ C, int Nt, int K)
{
    extern __shared__ float dyn[];
    const int tid = threadIdx.x;
    const int wid = tid >> 5;
    const int lane = tid & 31;
    const int warp_m = wid >> 1;
    const int warp_n = wid & 1;
    const int r = lane >> 2, cq = lane & 3;
    const int m0 = blockIdx.y * 128;
    const int n0 = blockIdx.x * 128;
    const int NC = K >> 5;

    const uint32_t sbase = smem_u32p(dyn);

    int a_row[4], a_kq[4], b_kr[4], b_nq[4];
#pragma unroll
    for (int i = 0; i < 4; i++) {
        int c = tid + i*256;
        a_row[i] = c >> 3;  a_kq[i] = (c & 7)*4;
        b_kr[i] = c >> 5;   b_nq[i] = (c & 31)*4;
    }

    auto issue = [&](int kc, int st) {
        const uint32_t sA = sbase + (uint32_t)(st*STG)*4u;
        const uint32_t sB = sA + (uint32_t)ASTG*4u;
#pragma unroll
        for (int i = 0; i < 4; i++) {
            const float* src = A + (size_t)(m0 + a_row[i])*K + kc*32 + a_kq[i];
            CP16(sA + (uint32_t)(a_row[i]*36 + a_kq[i])*4u, src);
        }
#pragma unroll
        for (int i = 0; i < 4; i++) {
            const float* src = W + (size_t)(kc*32 + b_kr[i])*Nt + n0 + b_nq[i];
            CP16(sB + (uint32_t)(b_kr[i]*136 + b_nq[i])*4u, src);
        }
        CP_COMMIT();
    };

    float acc[2][8][4];
#pragma unroll
    for (int mf = 0; mf < 2; mf++)
#pragma unroll
        for (int nf = 0; nf < 8; nf++)
#pragma unroll
            for (int k = 0; k < 4; k++) acc[mf][nf][k] = 0.f;

    issue(0, 0);

    for (int kc = 0; kc < NC; kc++) {
        if (kc + 1 < NC) issue(kc + 1, (kc + 1) & 1);
        else CP_COMMIT();
        CP_WAIT1();
        __syncthreads();

        const int st = kc & 1;
        const uint32_t* Ab = (const uint32_t*)(dyn + st*STG) + (warp_m*32)*36;
        const uint32_t* Bb = (const uint32_t*)(dyn + st*STG + ASTG) + warp_n*64;
#pragma unroll
        for (int kk = 0; kk < 4; kk++) {
            const int ko = kk*8;
            uint32_t afr[2][4];
#pragma unroll
            for (int mf = 0; mf < 2; mf++) {
                int base = (mf*16 + r)*36 + ko + cq;
                afr[mf][0] = Ab[base];
                afr[mf][1] = Ab[base + 8*36];
                afr[mf][2] = Ab[base + 4];
                afr[mf][3] = Ab[base + 8*36 + 4];
            }
#pragma unroll
            for (int nf = 0; nf < 8; nf++) {
                int nn = nf*8 + r;
                uint32_t bfr[2];
                bfr[0] = Bb[(ko + cq)*136 + nn];
                bfr[1] = Bb[(ko + cq + 4)*136 + nn];
                mma_tf32(acc[0][nf], afr[0], bfr);
                mma_tf32(acc[1][nf], afr[1], bfr);
            }
        }
        __syncthreads();
    }

    const int rb = m0 + warp_m*32;
    const int cb = n0 + warp_n*64;
#pragma unroll
    for (int mf = 0; mf < 2; mf++) {
#pragma unroll
        for (int half = 0; half < 2; half++) {
            int row = rb + mf*16 + r + half*8;
            const float* Rrow = nullptr;
            if (MODE == 1) Rrow = res + (size_t)row*Nt;
            if (MODE == 3) Rrow = res + (size_t)(row & (NT-1))*Nt;
            float* Crow = C + (size_t)row*Nt;
#pragma unroll
            for (int nf = 0; nf < 8; nf++) {
                int col = cb + nf*8 + cq*2;
                float v0 = acc[mf][nf][half*2 + 0] + bias[col];
                float v1 = acc[mf][nf][half*2 + 1] + bias[col + 1];
                if (MODE == 1 || MODE == 3) { v0 += Rrow[col]; v1 += Rrow[col+1]; }
                if (MODE == 2) {
                    v0 = rtf(0.5f*v0*(1.f + erff(v0*0.70710678118654752f)));
                    v1 = rtf(0.5f*v1*(1.f + erff(v1*0.70710678118654752f)));
                }
                float2 o; o.x = v0; o.y = v1;
                *(float2*)(Crow + col) = o;
            }
        }
    }
}

// ---------------- SIMT SGEMM (FPN heads only) ----------------
template<int MODE>
__global__ void __launch_bounds__(128)
sgemm_kernel(const float* __restrict__ A, const float* __restrict__ W,
             const float* __restrict__ bias, const float* res, float* C,
             int M, int N, int K)
{
    __shared__ float As[2][16][64];
    __shared__ float Bs[2][16][128];
    const int tid = threadIdx.x;
    const int m0  = blockIdx.y * 64;
    const int n0  = blockIdx.x * 128;
    const int tx  = tid & 15, ty = tid >> 4;

    float acc[8][8];
#pragma unroll
    for (int i = 0; i < 8; i++)
#pragma unroll
        for (int j = 0; j < 8; j++) acc[i][j] = 0.f;

    const int KT = K >> 4;
    float4 aReg[2];
    float  bReg[16];

    auto loadG = [&](int kt) {
#pragma unroll
        for (int l = 0; l < 2; l++) {
            int lin = tid*2 + l;
            int arow = lin >> 2, kq = lin & 3;
            aReg[l] = *(const float4*)(A + (size_t)(m0 + arow)*K + kt*16 + kq*4);
        }
#pragma unroll
        for (int l = 0; l < 16; l++) {
            int lin = tid + l*128;
            int kr = lin >> 7, col = lin & 127;
            int n  = n0 + col;
            bReg[l] = (n < N) ? W[(size_t)(kt*16 + kr)*N + n] : 0.f;
        }
    };
    auto storeS = [&](int buf) {
#pragma unroll
        for (int l = 0; l < 2; l++) {
            int lin = tid*2 + l;
            int arow = lin >> 2, kq = lin & 3;
            As[buf][kq*4+0][arow] = aReg[l].x;
            As[buf][kq*4+1][arow] = aReg[l].y;
            As[buf][kq*4+2][arow] = aReg[l].z;
            As[buf][kq*4+3][arow] = aReg[l].w;
        }
#pragma unroll
        for (int l = 0; l < 16; l++) {
            int lin = tid + l*128;
            int kr = lin >> 7, col = lin & 127;
            Bs[buf][kr][col] = bReg[l];
        }
    };

    loadG(0);
    storeS(0);
    __syncthreads();
    int buf = 0;
    for (int kt = 0; kt < KT; kt++) {
        if (kt + 1 < KT) loadG(kt + 1);
#pragma unroll
        for (int k = 0; k < 16; k++) {
            float a[8], bb[8];
            float4 t0 = *(const float4*)&As[buf][k][ty*8];
            float4 t1 = *(const float4*)&As[buf][k][ty*8 + 4];
            a[0]=t0.x; a[1]=t0.y; a[2]=t0.z; a[3]=t0.w;
            a[4]=t1.x; a[5]=t1.y; a[6]=t1.z; a[7]=t1.w;
            float4 u0 = *(const float4*)&Bs[buf][k][tx*8];
            float4 u1 = *(const float4*)&Bs[buf][k][tx*8 + 4];
            bb[0]=u0.x; bb[1]=u0.y; bb[2]=u0.z; bb[3]=u0.w;
            bb[4]=u1.x; bb[5]=u1.y; bb[6]=u1.z; bb[7]=u1.w;
#pragma unroll
            for (int i = 0; i < 8; i++)
#pragma unroll
                for (int j = 0; j < 8; j++)
                    acc[i][j] += a[i]*bb[j];
        }
        if (kt + 1 < KT) storeS(buf ^ 1);
        __syncthreads();
        buf ^= 1;
    }

#pragma unroll
    for (int i = 0; i < 8; i++) {
        int r = m0 + ty*8 + i;
#pragma unroll
        for (int j = 0; j < 8; j++) {
            int n = n0 + tx*8 + j;
            if (n < N) {
                float v = acc[i][j] + bias[n];
                if (MODE == 1) v += res[(size_t)r*N + n];
                if (MODE == 3) v += res[(size_t)(r & (NT-1))*N + n];
                if (MODE == 2) v = 0.5f*v*(1.f + erff(v*0.70710678118654752f));
                C[(size_t)r*N + n] = v;
            }
        }
    }
}

// ---------------- layernorm (tf32-rounded output; feeds GEMM A) ---------------
__global__ void __launch_bounds__(256)
ln_kernel(const float* __restrict__ x, const float* __restrict__ w,
          const float* __restrict__ b, float* __restrict__ y)
{
    __shared__ float red[8];
    __shared__ float sMean, sRstd;
    int r = blockIdx.x, tid = threadIdx.x;
    const float* xr = x + (size_t)r*DM;
    float v0 = xr[tid], v1 = xr[tid+256], v2 = xr[tid+512];

    float s = v0 + v1 + v2;
#pragma unroll
    for (int o = 16; o > 0; o >>= 1) s += __shfl_xor_sync(0xffffffffu, s, o);
    if ((tid & 31) == 0) red[tid >> 5] = s;
    __syncthreads();
    if (tid == 0) {
        float t = 0.f;
#pragma unroll
        for (int i = 0; i < 8; i++) t += red[i];
        sMean = t * (1.f/768.f);
    }
    __syncthreads();
    float mean = sMean;
    float d0 = v0-mean, d1 = v1-mean, d2 = v2-mean;

    float q = d0*d0 + d1*d1 + d2*d2;
#pragma unroll
    for (int o = 16; o > 0; o >>= 1) q += __shfl_xor_sync(0xffffffffu, q, o);
    if ((tid & 31) == 0) red[tid >> 5] = q;
    __syncthreads();
    if (tid == 0) {
        float t = 0.f;
#pragma unroll
        for (int i = 0; i < 8; i++) t += red[i];
        sRstd = rsqrtf(t * (1.f/768.f) + 1e-5f);
    }
    __syncthreads();
    float rstd = sRstd;
    float* yr = y + (size_t)r*DM;
    yr[tid]     = rtf(d0*rstd*w[tid]     + b[tid]);
    yr[tid+256] = rtf(d1*rstd*w[tid+256] + b[tid+256]);
    yr[tid+512] = rtf(d2*rstd*w[tid+512] + b[tid+512]);
}

// LN for FPN head (feeds SIMT sgemm — keep full fp32)
__global__ void __launch_bounds__(256)
ln_kernel_fp(const float* __restrict__ x, const float* __restrict__ w,
             const float* __restrict__ b, float* __restrict__ y)
{
    __shared__ float red[8];
    __shared__ float sMean, sRstd;
    int r = blockIdx.x, tid = threadIdx.x;
    const float* xr = x + (size_t)r*DM;
    float v0 = xr[tid], v1 = xr[tid+256], v2 = xr[tid+512];
    float s = v0 + v1 + v2;
#pragma unroll
    for (int o = 16; o > 0; o >>= 1) s += __shfl_xor_sync(0xffffffffu, s, o);
    if ((tid & 31) == 0) red[tid >> 5] = s;
    __syncthreads();
    if (tid == 0) {
        float t = 0.f;
#pragma unroll
        for (int i = 0; i < 8; i++) t += red[i];
        sMean = t * (1.f/768.f);
    }
    __syncthreads();
    float mean = sMean;
    float d0 = v0-mean, d1 = v1-mean, d2 = v2-mean;
    float q = d0*d0 + d1*d1 + d2*d2;
#pragma unroll
    for (int o = 16; o > 0; o >>= 1) q += __shfl_xor_sync(0xffffffffu, q, o);
    if ((tid & 31) == 0) red[tid >> 5] = q;
    __syncthreads();
    if (tid == 0) {
        float t = 0.f;
#pragma unroll
        for (int i = 0; i < 8; i++) t += red[i];
        sRstd = rsqrtf(t * (1.f/768.f) + 1e-5f);
    }
    __syncthreads();
    float rstd = sRstd;
    float* yr = y + (size_t)r*DM;
    yr[tid]     = d0*rstd*w[tid]     + b[tid];
    yr[tid+256] = d1*rstd*w[tid+256] + b[tid+256];
    yr[tid+512] = d2*rstd*w[tid+512] + b[tid+512];
}

// ---------------- flash attention, 4-way key split, packed f32x2 --------------
// grid (B*H, NT/128, NSPL), block 128.  Each block: 128 queries vs 256 keys.
__global__ void __launch_bounds__(128)
flash_attn_part(const float* __restrict__ qkv,
                float* __restrict__ po, float2* __restrict__ pml)
{
    __shared__ float Ks[64][64];
    __shared__ float Vs[64][64];
    const int bh = blockIdx.x;
    const int b  = bh / NHEADS, h = bh % NHEADS;
    const int z  = blockIdx.z;
    const int tid = threadIdx.x;
    const int qi  = blockIdx.y*128 + tid;
    const int row = b*NT + qi;

    unsigned long long q2[32], o2[32];
    const ulonglong2* qp = (const ulonglong2*)(qkv + (size_t)row*(3*DM) + h*DHD);
#pragma unroll
    for (int i = 0; i < 16; i++) {
        ulonglong2 t = qp[i];
        q2[2*i] = t.x; q2[2*i+1] = t.y;
    }
#pragma unroll
    for (int i = 0; i < 32; i++) o2[i] = 0ULL;
    float m = -3.0e38f, l = 0.f;

    const int KT_PER = (NT/64)/NSPL;   // 4
    for (int kt = z*KT_PER; kt < z*KT_PER + KT_PER; kt++) {
        __syncthreads();
        int base = b*NT + kt*64;
        for (int lin = tid; lin < 1024; lin += 128) {
            int j = lin >> 4, qd = lin & 15;
            const float* kr = qkv + (size_t)(base + j)*(3*DM) + h*DHD;
            *(float4*)&Ks[j][qd*4] = *(const float4*)(kr + DM   + qd*4);
            *(float4*)&Vs[j][qd*4] = *(const float4*)(kr + 2*DM + qd*4);
        }
        __syncthreads();
        for (int j0 = 0; j0 < 64; j0 += 4) {
            float s[4];
#pragma unroll
            for (int jj = 0; jj < 4; jj++) {
                unsigned long long acc0 = 0ULL, acc1 = 0ULL;
                const ulonglong2* kr2 = (const ulonglong2*)&Ks[j0+jj][0];
#pragma unroll
                for (int i = 0; i < 16; i++) {
                    ulonglong2 kk = kr2[i];
                    FMA2(acc0, q2[2*i],   kk.x, acc0);
                    FMA2(acc1, q2[2*i+1], kk.y, acc1);
                }
                float a0, a1, a2, a3;
                UNPK2(a0, a1, acc0);
                UNPK2(a2, a3, acc1);
                s[jj] = ((a0+a1)+(a2+a3)) * 0.125f;
            }
            float smax = fmaxf(fmaxf(s[0],s[1]), fmaxf(s[2],s[3]));
            if (smax > m) {
                float cc = __expf(m - smax);
                m = smax; l *= cc;
                unsigned long long cc2 = pack2(cc, cc);
#pragma unroll
                for (int d = 0; d < 32; d++) MUL2(o2[d], o2[d], cc2);
            }
            float p0 = __expf(s[0]-m), p1 = __expf(s[1]-m);
            float p2 = __expf(s[2]-m), p3 = __expf(s[3]-m);
            l += (p0+p1)+(p2+p3);
            unsigned long long p0_2 = pack2(p0,p0), p1_2 = pack2(p1,p1);
            unsigned long long p2_2 = pack2(p2,p2), p3_2 = pack2(p3,p3);
            const ulonglong2* v0p = (const ulonglong2*)&Vs[j0  ][0];
            const ulonglong2* v1p = (const ulonglong2*)&Vs[j0+1][0];
            const ulonglong2* v2p = (const ulonglong2*)&Vs[j0+2][0];
            const ulonglong2* v3p = (const ulonglong2*)&Vs[j0+3][0];
#pragma unroll
            for (int i = 0; i < 16; i++) {
                ulonglong2 w0 = v0p[i], w1 = v1p[i], w2 = v2p[i], w3 = v3p[i];
                FMA2(o2[2*i],   p0_2, w0.x, o2[2*i]);
                FMA2(o2[2*i+1], p0_2, w0.y, o2[2*i+1]);
                FMA2(o2[2*i],   p1_2, w1.x, o2[2*i]);
                FMA2(o2[2*i+1], p1_2, w1.y, o2[2*i+1]);
                FMA2(o2[2*i],   p2_2, w2.x, o2[2*i]);
                FMA2(o2[2*i+1], p2_2, w2.y, o2[2*i+1]);
                FMA2(o2[2*i],   p3_2, w3.x, o2[2*i]);
                FMA2(o2[2*i+1], p3_2, w3.y, o2[2*i+1]);
            }
        }
    }
    size_t pidx = ((size_t)(z*24 + bh)*1024 + qi);
    float4* op = (float4*)(po + pidx*64);
#pragma unroll
    for (int i = 0; i < 16; i++) {
        float4 v;
        UNPK2(v.x, v.y, o2[2*i]);
        UNPK2(v.z, v.w, o2[2*i+1]);
        op[i] = v;
    }
    float2 ml; ml.x = m; ml.y = l;
    pml[pidx] = ml;
}

// combine NSPL key-split partials -> attn output (tf32-rounded; feeds proj A)
__global__ void __launch_bounds__(256)
attn_combine(const float* __restrict__ po, const float2* __restrict__ pml,
             float* __restrict__ out)
{
    int idx = blockIdx.x*256 + threadIdx.x;       // over 24*1024*64
    if (idx >= 24*1024*64) return;
    int d  = idx & 63;
    int qi = (idx >> 6) & 1023;
    int bh = idx >> 16;
    int b = bh / NHEADS, h = bh % NHEADS;
    float mstar = -3.0e38f;
    float2 ml[NSPL];
#pragma unroll
    for (int z = 0; z < NSPL; z++) {
        ml[z] = pml[(size_t)(z*24 + bh)*1024 + qi];
        mstar = fmaxf(mstar, ml[z].x);
    }
    float denom = 0.f, num = 0.f;
#pragma unroll
    for (int z = 0; z < NSPL; z++) {
        float c = __expf(ml[z].x - mstar);
        denom += ml[z].y * c;
        num   += po[((size_t)(z*24 + bh)*1024 + qi)*64 + d] * c;
    }
    out[(size_t)(b*NT + qi)*DM + h*DHD + d] = rtf(num / denom);
}

// ---------------- FPN transpose + clamped bilinear resize (JAX half-pixel) ----
__global__ void fpn_resize_kernel(const float* __restrict__ g, float* __restrict__ out,
                                  int C, int TS)
{
    int idx = blockIdx.x * 256 + threadIdx.x;
    int total = BT*C*TS*TS;
    if (idx >= total) return;
    int xq = idx % TS;
    int yq = (idx / TS) % TS;
    int c  = (idx / (TS*TS)) % C;
    int b  = idx / (TS*TS*C);
    float s  = 32.0f / (float)TS;
    float sy = ((float)yq + 0.5f)*s - 0.5f;
    float sx = ((float)xq + 0.5f)*s - 0.5f;
    int y0 = (int)floorf(sy); float fy = sy - (float)y0;
    int x0 = (int)floorf(sx); float fx = sx - (float)x0;
    int y0c = min(31, max(0, y0)),   y1c = min(31, max(0, y0+1));
    int x0c = min(31, max(0, x0)),   x1c = min(31, max(0, x0+1));
    const float* gb = g + (size_t)b*1024*C;
    float p00 = gb[(y0c*32 + x0c)*C + c];
    float p01 = gb[(y0c*32 + x1c)*C + c];
    float p10 = gb[(y1c*32 + x0c)*C + c];
    float p11 = gb[(y1c*32 + x1c)*C + c];
    out[idx] = (1.f-fy)*((1.f-fx)*p00 + fx*p01) + fy*((1.f-fx)*p10 + fx*p11);
}

// ---------------- host launcher ----------------
extern "C" void kernel_launch(void* const* d_in, const int* in_sizes, int n_in,
                              void* d_out, int out_size)
{
    (void)in_sizes; (void)n_in; (void)out_size;
    const float* x       = (const float*)d_in[0];
    const float* patch_w = (const float*)d_in[1];
    const float* patch_b = (const float*)d_in[2];
    const float* pos     = (const float*)d_in[3];
    const float* ln1_w   = (const float*)d_in[4];
    const float* ln1_b   = (const float*)d_in[5];
    const float* qkv_w   = (const float*)d_in[6];
    const float* qkv_b   = (const float*)d_in[7];
    const float* proj_w  = (const float*)d_in[8];
    const float* proj_b  = (const float*)d_in[9];
    const float* ln2_w   = (const float*)d_in[10];
    const float* ln2_b   = (const float*)d_in[11];
    const float* fc1_w   = (const float*)d_in[12];
    const float* fc1_b   = (const float*)d_in[13];
    const float* fc2_w   = (const float*)d_in[14];
    const float* fc2_b   = (const float*)d_in[15];
    const float* norm_w  = (const float*)d_in[16];
    const float* norm_b  = (const float*)d_in[17];
    const float* fpn_w[4] = {(const float*)d_in[18], (const float*)d_in[20],
                             (const float*)d_in[22], (const float*)d_in[24]};
    const float* fpn_b[4] = {(const float*)d_in[19], (const float*)d_in[21],
                             (const float*)d_in[23], (const float*)d_in[25]};
    float* out = (float*)d_out;

    static float *p_xp = nullptr, *p_t, *p_h, *p_qkv, *p_attn, *p_mlp, *p_fpn, *p_po;
    static float2 *p_pml;
    static float *p_patchw, *p_qkvw, *p_projw, *p_fc1w, *p_fc2w;
    if (!p_xp) {  // one-time pointer lookup + smem attribute (outside capture)
        cudaGetSymbolAddress((void**)&p_xp,   g_xp);
        cudaGetSymbolAddress((void**)&p_t,    g_t);
        cudaGetSymbolAddress((void**)&p_h,    g_h);
        cudaGetSymbolAddress((void**)&p_qkv,  g_qkv);
        cudaGetSymbolAddress((void**)&p_attn, g_attn);
        cudaGetSymbolAddress((void**)&p_mlp,  g_mlp);
        cudaGetSymbolAddress((void**)&p_fpn,  g_fpn);
        cudaGetSymbolAddress((void**)&p_po,   g_po);
        cudaGetSymbolAddress((void**)&p_pml,  g_pml);
        cudaGetSymbolAddress((void**)&p_patchw, g_patchw);
        cudaGetSymbolAddress((void**)&p_qkvw,   g_qkvw);
        cudaGetSymbolAddress((void**)&p_projw,  g_projw);
        cudaGetSymbolAddress((void**)&p_fc1w,   g_fc1w);
        cudaGetSymbolAddress((void**)&p_fc2w,   g_fc2w);
        cudaFuncSetAttribute(tcgemm<0>, cudaFuncAttributeMaxDynamicSharedMemorySize, SMEM_TC);
        cudaFuncSetAttribute(tcgemm<1>, cudaFuncAttributeMaxDynamicSharedMemorySize, SMEM_TC);
        cudaFuncSetAttribute(tcgemm<2>, cudaFuncAttributeMaxDynamicSharedMemorySize, SMEM_TC);
        cudaFuncSetAttribute(tcgemm<3>, cudaFuncAttributeMaxDynamicSharedMemorySize, SMEM_TC);
    }

    // pre-round all transformer weights to tf32 (once per call)
    {
        int n;
        n = DM*DM/4;              round_tf32_kernel<<<(n+255)/256, 256>>>(patch_w, p_patchw, n);
        n = DEPTHL*DM*3*DM/4;     round_tf32_kernel<<<(n+255)/256, 256>>>(qkv_w,   p_qkvw,   n);
        n = DEPTHL*DM*DM/4;       round_tf32_kernel<<<(n+255)/256, 256>>>(proj_w,  p_projw,  n);
        n = DEPTHL*DM*HIDF/4;     round_tf32_kernel<<<(n+255)/256, 256>>>(fc1_w,   p_fc1w,   n);
        n = DEPTHL*HIDF*DM/4;     round_tf32_kernel<<<(n+255)/256, 256>>>(fc2_w,   p_fc2w,   n);
    }

    // patch embed: t = xp @ patch_w + patch_b + pos_embed
    patchify_kernel<<<(RR*DM + 255)/256, 256>>>(x, p_xp);
    tcgemm<3><<<dim3(6, 16), 256, SMEM_TC>>>(p_xp, p_patchw, patch_b, pos, p_t, DM, DM);

    static const size_t off[4] = {0, 3145728, 4718592, 5505024};

    for (int i = 0; i < DEPTHL; i++) {
        ln_kernel<<<RR, 256>>>(p_t, ln1_w + i*DM, ln1_b + i*DM, p_h);
        tcgemm<0><<<dim3(18, 16), 256, SMEM_TC>>>(p_h, p_qkvw + (size_t)i*DM*3*DM,
                                                  qkv_b + (size_t)i*3*DM, nullptr,
                                                  p_qkv, 3*DM, DM);
        flash_attn_part<<<dim3(BT*NHEADS, NT/128, NSPL), 128>>>(p_qkv, p_po, p_pml);
        attn_combine<<<(24*1024*64 + 255)/256, 256>>>(p_po, p_pml, p_attn);
        tcgemm<1><<<dim3(6, 16), 256, SMEM_TC>>>(p_attn, p_projw + (size_t)i*DM*DM,
                                                 proj_b + (size_t)i*DM, p_t, p_t, DM, DM);
        ln_kernel<<<RR, 256>>>(p_t, ln2_w + i*DM, ln2_b + i*DM, p_h);
        tcgemm<2><<<dim3(24, 16), 256, SMEM_TC>>>(p_h, p_fc1w + (size_t)i*DM*HIDF,
                                                  fc1_b + (size_t)i*HIDF, nullptr,
                                                  p_mlp, HIDF, DM);
        tcgemm<1><<<dim3(6, 16), 256, SMEM_TC>>>(p_mlp, p_fc2w + (size_t)i*HIDF*DM,
                                                 fc2_b + (size_t)i*DM, p_t, p_t, DM, HIDF);

        int e = (i == 3) ? 0 : (i == 6) ? 1 : (i == 9) ? 2 : (i == 11) ? 3 : -1;
        if (e >= 0) {
            int oc = 96 << e, ts = 128 >> e;
            ln_kernel_fp<<<RR, 256>>>(p_t, norm_w, norm_b, p_fpn);
            sgemm_kernel<0><<<dim3((oc + 127)/128, 32), 128>>>(p_fpn, fpn_w[e], fpn_b[e],
                                                               nullptr, p_h, RR, oc, DM);
            int total = BT*oc*ts*ts;
            fpn_resize_kernel<<<(total + 255)/256, 256>>>(p_h, out + off[e], oc, ts);
        }
    }
}

// round 16
// speedup vs baseline: 3.8057x; 1.4998x over previous
#include <cuda_runtime.h>
#include <math.h>
#include <stdint.h>

#define DEPTHL 12
#define DM     768
#define NT     1024
#define BT     2
#define RR     (BT*NT)      // 2048 rows
#define HIDF   3072
#define NHEADS 12
#define DHD    64

// ---------------- scratch (static device globals; no allocation) ----------------
__device__ float g_xp[RR*DM];
__device__ float g_t[RR*DM];
__device__ float g_h[RR*DM];
__device__ float g_qkv[RR*3*DM];
__device__ float g_attn[RR*DM];
__device__ float g_mlp[RR*HIDF];
__device__ float g_fpn[RR*DM];
// pre-rounded (tf32) weights
__device__ float g_patchw[DM*DM];
__device__ float g_qkvw[DEPTHL*DM*3*DM];
__device__ float g_projw[DEPTHL*DM*DM];
__device__ float g_fc1w[DEPTHL*DM*HIDF];
__device__ float g_fc2w[DEPTHL*HIDF*DM];

__device__ __forceinline__ uint32_t f2tf32(float f) {
    uint32_t u;
    asm("cvt.rna.tf32.f32 %0, %1;" : "=r"(u) : "f"(f));
    return u;
}
__device__ __forceinline__ float rtf(float f) { return __uint_as_float(f2tf32(f)); }

// ---------------- patchify: x[B,3,512,512] -> xp[B*N, 768] (tf32-rounded) -----
__global__ void patchify_kernel(const float* __restrict__ x, float* __restrict__ xp) {
    int idx = blockIdx.x * 256 + threadIdx.x;
    if (idx >= RR*DM) return;
    int col = idx % DM;
    int r   = idx / DM;
    int b   = r >> 10, n = r & 1023;
    int gy  = n >> 5,  gx = n & 31;
    int c   = col >> 8;
    int rem = col & 255;
    int py  = rem >> 4, px = rem & 15;
    xp[idx] = rtf(x[((size_t)(b*3 + c)*512 + (gy*16 + py))*512 + (gx*16 + px)]);
}

// ---------------- round fp32 -> tf32-in-fp32 (rna), vectorized ----------------
__global__ void round_tf32_kernel(const float* __restrict__ src,
                                  float* __restrict__ dst, int n4) {
    int i = blockIdx.x * 256 + threadIdx.x;
    if (i >= n4) return;
    float4 v = *(const float4*)(src + (size_t)i*4);
    v.x = rtf(v.x); v.y = rtf(v.y); v.z = rtf(v.z); v.w = rtf(v.w);
    *(float4*)(dst + (size_t)i*4) = v;
}

// ================= tf32 mma.sync GEMM =========================================
// C = A[M,K] @ W[K,N] + epilogue.  BM=128, BN=128, BK=32, 256 thr, 8 warps 4x2,
// warp tile 32x64.  2-stage cp.async, 2 CTAs/SM.  Operands pre-rounded.
// MODE 0: +bias                      1: +bias+res[r,n]
// MODE 2: +bias, GELU (tf32 out)     3: +bias+res[r&1023,n]
// MODE 5: +bias, x0.125 for col<768, tf32 out  (QKV for mma attention)

__device__ __forceinline__ void mma_tf32(float* d, const uint32_t* a, const uint32_t* b) {
    asm volatile(
        "mma.sync.aligned.m16n8k8.row.col.f32.tf32.tf32.f32 "
        "{%0,%1,%2,%3}, {%4,%5,%6,%7}, {%8,%9}, {%0,%1,%2,%3};"
        : "+f"(d[0]), "+f"(d[1]), "+f"(d[2]), "+f"(d[3])
        : "r"(a[0]), "r"(a[1]), "r"(a[2]), "r"(a[3]), "r"(b[0]), "r"(b[1]));
}
__device__ __forceinline__ uint32_t smem_u32p(const void* p) {
    uint32_t a;
    asm("{ .reg .u64 t; cvta.to.shared.u64 t, %1; cvt.u32.u64 %0, t; }" : "=r"(a) : "l"(p));
    return a;
}
#define CP16(dst, src) \
    asm volatile("cp.async.cg.shared.global [%0], [%1], 16;" :: "r"(dst), "l"(src))
#define CP_COMMIT() asm volatile("cp.async.commit_group;")
#define CP_WAIT1()  asm volatile("cp.async.wait_group 1;" ::: "memory")
#define CP_WAIT0()  asm volatile("cp.async.wait_group 0;" ::: "memory")

#define ASTG 4608                 // 128*36 floats
#define BSTG 4352                 // 32*136 floats
#define STG  (ASTG+BSTG)          // 8960 floats / stage
#define SMEM_TC (2*STG*4)         // 71680 bytes

template<int MODE>
__global__ void __launch_bounds__(256, 2)
tcgemm(const float* __restrict__ A, const float* __restrict__ W,
       const float* __restrict__ bias, const float* __restrict__ res,
       float* __restrict__ C, int Nt, int K)
{
    extern __shared__ float dyn[];
    const int tid = threadIdx.x;
    const int wid = tid >> 5;
    const int lane = tid & 31;
    const int warp_m = wid >> 1;
    const int warp_n = wid & 1;
    const int r = lane >> 2, cq = lane & 3;
    const int m0 = blockIdx.y * 128;
    const int n0 = blockIdx.x * 128;
    const int NC = K >> 5;

    const uint32_t sbase = smem_u32p(dyn);

    int a_row[4], a_kq[4], b_kr[4], b_nq[4];
#pragma unroll
    for (int i = 0; i < 4; i++) {
        int c = tid + i*256;
        a_row[i] = c >> 3;  a_kq[i] = (c & 7)*4;
        b_kr[i] = c >> 5;   b_nq[i] = (c & 31)*4;
    }

    auto issue = [&](int kc, int st) {
        const uint32_t sA = sbase + (uint32_t)(st*STG)*4u;
        const uint32_t sB = sA + (uint32_t)ASTG*4u;
#pragma unroll
        for (int i = 0; i < 4; i++) {
            const float* src = A + (size_t)(m0 + a_row[i])*K + kc*32 + a_kq[i];
            CP16(sA + (uint32_t)(a_row[i]*36 + a_kq[i])*4u, src);
        }
#pragma unroll
        for (int i = 0; i < 4; i++) {
            const float* src = W + (size_t)(kc*32 + b_kr[i])*Nt + n0 + b_nq[i];
            CP16(sB + (uint32_t)(b_kr[i]*136 + b_nq[i])*4u, src);
        }
        CP_COMMIT();
    };

    float acc[2][8][4];
#pragma unroll
    for (int mf = 0; mf < 2; mf++)
#pragma unroll
        for (int nf = 0; nf < 8; nf++)
#pragma unroll
            for (int k = 0; k < 4; k++) acc[mf][nf][k] = 0.f;

    issue(0, 0);

    for (int kc = 0; kc < NC; kc++) {
        if (kc + 1 < NC) issue(kc + 1, (kc + 1) & 1);
        else CP_COMMIT();
        CP_WAIT1();
        __syncthreads();

        const int st = kc & 1;
        const uint32_t* Ab = (const uint32_t*)(dyn + st*STG) + (warp_m*32)*36;
        const uint32_t* Bb = (const uint32_t*)(dyn + st*STG + ASTG) + warp_n*64;
#pragma unroll
        for (int kk = 0; kk < 4; kk++) {
            const int ko = kk*8;
            uint32_t afr[2][4];
#pragma unroll
            for (int mf = 0; mf < 2; mf++) {
                int base = (mf*16 + r)*36 + ko + cq;
                afr[mf][0] = Ab[base];
                afr[mf][1] = Ab[base + 8*36];
                afr[mf][2] = Ab[base + 4];
                afr[mf][3] = Ab[base + 8*36 + 4];
            }
#pragma unroll
            for (int nf = 0; nf < 8; nf++) {
                int nn = nf*8 + r;
                uint32_t bfr[2];
                bfr[0] = Bb[(ko + cq)*136 + nn];
                bfr[1] = Bb[(ko + cq + 4)*136 + nn];
                mma_tf32(acc[0][nf], afr[0], bfr);
                mma_tf32(acc[1][nf], afr[1], bfr);
            }
        }
        __syncthreads();
    }

    const int rb = m0 + warp_m*32;
    const int cb = n0 + warp_n*64;
#pragma unroll
    for (int mf = 0; mf < 2; mf++) {
#pragma unroll
        for (int half = 0; half < 2; half++) {
            int row = rb + mf*16 + r + half*8;
            const float* Rrow = nullptr;
            if (MODE == 1) Rrow = res + (size_t)row*Nt;
            if (MODE == 3) Rrow = res + (size_t)(row & (NT-1))*Nt;
            float* Crow = C + (size_t)row*Nt;
#pragma unroll
            for (int nf = 0; nf < 8; nf++) {
                int col = cb + nf*8 + cq*2;
                float v0 = acc[mf][nf][half*2 + 0] + bias[col];
                float v1 = acc[mf][nf][half*2 + 1] + bias[col + 1];
                if (MODE == 1 || MODE == 3) { v0 += Rrow[col]; v1 += Rrow[col+1]; }
                if (MODE == 2) {
                    v0 = rtf(0.5f*v0*(1.f + erff(v0*0.70710678118654752f)));
                    v1 = rtf(0.5f*v1*(1.f + erff(v1*0.70710678118654752f)));
                }
                if (MODE == 5) {
                    float sc = (col < DM) ? 0.125f : 1.0f;   // scale q by 1/sqrt(dh)
                    v0 = rtf(v0*sc);
                    v1 = rtf(v1*sc);
                }
                float2 o; o.x = v0; o.y = v1;
                *(float2*)(Crow + col) = o;
            }
        }
    }
}

// ================= MMA flash attention ========================================
// grid (B*H, NT/128), block 128 (4 warps x 32 queries).  Full 1024 keys/CTA.
// Q,K,V pre-rounded tf32 (QKV GEMM MODE 5; q pre-scaled by 0.125).
// smem: Qs[128][68] | Ks[64][68] | Vs[64][68] | Ps[4][32][68]
#define AQ_OFF 0
#define AK_OFF 8704
#define AV_OFF 13056
#define AP_OFF 17408
#define SMEM_AT ((17408 + 8704)*4)    // 104448 bytes

__global__ void __launch_bounds__(128)
attn_mma(const float* __restrict__ qkv, float* __restrict__ out)
{
    extern __shared__ float dyn[];
    const int bh = blockIdx.x;
    const int b  = bh / NHEADS, h = bh % NHEADS;
    const int qt = blockIdx.y;
    const int tid = threadIdx.x;
    const int wid = tid >> 5;
    const int lane = tid & 31;
    const int r = lane >> 2, cq = lane & 3;

    const uint32_t sbase = smem_u32p(dyn);

    // ---- load Q tile (128 q-rows x 64 floats = 2048 x 16B chunks) ----
#pragma unroll
    for (int i = 0; i < 16; i++) {
        int c = tid + i*128;
        int row = c >> 4, q4 = (c & 15)*4;
        const float* src = qkv + (size_t)(b*NT + qt*128 + row)*(3*DM) + h*DHD + q4;
        CP16(sbase + (uint32_t)(AQ_OFF + row*68 + q4)*4u, src);
    }
    CP_COMMIT();
    CP_WAIT0();
    __syncthreads();

    float o[2][8][4];
#pragma unroll
    for (int mf = 0; mf < 2; mf++)
#pragma unroll
        for (int nf = 0; nf < 8; nf++)
#pragma unroll
            for (int k = 0; k < 4; k++) o[mf][nf][k] = 0.f;
    float m[2][2]  = {{-3.0e38f,-3.0e38f},{-3.0e38f,-3.0e38f}};
    float lp[2][2] = {{0.f,0.f},{0.f,0.f}};

    const uint32_t* Qw = (const uint32_t*)dyn + AQ_OFF + (wid*32)*68;
    const uint32_t* Ks = (const uint32_t*)dyn + AK_OFF;
    const uint32_t* Vs = (const uint32_t*)dyn + AV_OFF;
    float*          Pw = dyn + AP_OFF + wid*(32*68);
    const uint32_t* Pu = (const uint32_t*)Pw;

    for (int kt = 0; kt < 16; kt++) {
        // ---- load K tile (64 keys x 64 floats = 1024 chunks) ----
#pragma unroll
        for (int i = 0; i < 8; i++) {
            int c = tid + i*128;
            int j = c >> 4, q4 = (c & 15)*4;
            const float* src = qkv + (size_t)(b*NT + kt*64 + j)*(3*DM) + DM + h*DHD + q4;
            CP16(sbase + (uint32_t)(AK_OFF + j*68 + q4)*4u, src);
        }
        // ---- load V tile (64 keys x 64 floats = 1024 chunks) ----
#pragma unroll
        for (int i = 0; i < 8; i++) {
            int c = tid + i*128;
            int j = c >> 4, q4 = (c & 15)*4;
            const float* src = qkv + (size_t)(b*NT + kt*64 + j)*(3*DM) + 2*DM + h*DHD + q4;
            CP16(sbase + (uint32_t)(AV_OFF + j*68 + q4)*4u, src);
        }
        CP_COMMIT();
        CP_WAIT0();
        __syncthreads();

        // ---- S = Q @ K^T  (32x64 per warp) ----
        float s[2][8][4];
#pragma unroll
        for (int mf = 0; mf < 2; mf++)
#pragma unroll
            for (int nf = 0; nf < 8; nf++)
#pragma unroll
                for (int k = 0; k < 4; k++) s[mf][nf][k] = 0.f;
#pragma unroll
        for (int ks = 0; ks < 8; ks++) {
            const int ko = ks*8;
            uint32_t afr[2][4];
#pragma unroll
            for (int mf = 0; mf < 2; mf++) {
                int base = (mf*16 + r)*68 + ko + cq;
                afr[mf][0] = Qw[base];
                afr[mf][1] = Qw[base + 8*68];
                afr[mf][2] = Qw[base + 4];
                afr[mf][3] = Qw[base + 8*68 + 4];
            }
#pragma unroll
            for (int nf = 0; nf < 8; nf++) {
                int nn = nf*8 + r;
                uint32_t bfr[2];
                bfr[0] = Ks[nn*68 + ko + cq];
                bfr[1] = Ks[nn*68 + ko + cq + 4];
                mma_tf32(s[0][nf], afr[0], bfr);
                mma_tf32(s[1][nf], afr[1], bfr);
            }
        }

        // ---- online softmax (rows: mf*16 + r + half*8; cols: nf*8 + 2cq+{0,1}) ----
#pragma unroll
        for (int mf = 0; mf < 2; mf++) {
#pragma unroll
            for (int half = 0; half < 2; half++) {
                float vmax = -3.0e38f;
#pragma unroll
                for (int nf = 0; nf < 8; nf++)
                    vmax = fmaxf(vmax, fmaxf(s[mf][nf][half*2], s[mf][nf][half*2+1]));
                vmax = fmaxf(vmax, __shfl_xor_sync(0xffffffffu, vmax, 1));
                vmax = fmaxf(vmax, __shfl_xor_sync(0xffffffffu, vmax, 2));
                float mnew = fmaxf(m[mf][half], vmax);
                float cc = __expf(m[mf][half] - mnew);
                m[mf][half] = mnew;
                lp[mf][half] *= cc;
#pragma unroll
                for (int nf = 0; nf < 8; nf++) {
                    o[mf][nf][half*2]   *= cc;
                    o[mf][nf][half*2+1] *= cc;
                    float p0 = rtf(__expf(s[mf][nf][half*2]   - mnew));
                    float p1 = rtf(__expf(s[mf][nf][half*2+1] - mnew));
                    lp[mf][half] += p0 + p1;
                    float2 pv; pv.x = p0; pv.y = p1;
                    *(float2*)(Pw + (mf*16 + r + half*8)*68 + nf*8 + 2*cq) = pv;
                }
            }
        }
        __syncwarp();

        // ---- O += P @ V ----
#pragma unroll
        for (int ks = 0; ks < 8; ks++) {
            const int ko = ks*8;
            uint32_t afr[2][4];
#pragma unroll
            for (int mf = 0; mf < 2; mf++) {
                int base = (mf*16 + r)*68 + ko + cq;
                afr[mf][0] = Pu[base];
                afr[mf][1] = Pu[base + 8*68];
                afr[mf][2] = Pu[base + 4];
                afr[mf][3] = Pu[base + 8*68 + 4];
            }
#pragma unroll
            for (int nf = 0; nf < 8; nf++) {
                int nn = nf*8 + r;
                uint32_t bfr[2];
                bfr[0] = Vs[(ko + cq)*68 + nn];
                bfr[1] = Vs[(ko + cq + 4)*68 + nn];
                mma_tf32(o[0][nf], afr[0], bfr);
                mma_tf32(o[1][nf], afr[1], bfr);
            }
        }
        __syncthreads();    // PV done before next tile overwrites K/V
    }

    // ---- finalize: normalize rows and write (tf32-rounded; feeds proj A) ----
#pragma unroll
    for (int mf = 0; mf < 2; mf++) {
#pragma unroll
        for (int half = 0; half < 2; half++) {
            float t = lp[mf][half];
            t += __shfl_xor_sync(0xffffffffu, t, 1);
            t += __shfl_xor_sync(0xffffffffu, t, 2);
            float inv = 1.f / t;
            int row_g = b*NT + qt*128 + wid*32 + mf*16 + r + half*8;
            float* orow = out + (size_t)row_g*DM + h*DHD;
#pragma unroll
            for (int nf = 0; nf < 8; nf++) {
                float2 v;
                v.x = rtf(o[mf][nf][half*2]   * inv);
                v.y = rtf(o[mf][nf][half*2+1] * inv);
                *(float2*)(orow + nf*8 + 2*cq) = v;
            }
        }
    }
}

// ---------------- SIMT SGEMM (FPN heads only) ----------------
template<int MODE>
__global__ void __launch_bounds__(128)
sgemm_kernel(const float* __restrict__ A, const float* __restrict__ W,
             const float* __restrict__ bias, const float* res, float* C,
             int M, int N, int K)
{
    __shared__ float As[2][16][64];
    __shared__ float Bs[2][16][128];
    const int tid = threadIdx.x;
    const int m0  = blockIdx.y * 64;
    const int n0  = blockIdx.x * 128;
    const int tx  = tid & 15, ty = tid >> 4;

    float acc[8][8];
#pragma unroll
    for (int i = 0; i < 8; i++)
#pragma unroll
        for (int j = 0; j < 8; j++) acc[i][j] = 0.f;

    const int KT = K >> 4;
    float4 aReg[2];
    float  bReg[16];

    auto loadG = [&](int kt) {
#pragma unroll
        for (int l = 0; l < 2; l++) {
            int lin = tid*2 + l;
            int arow = lin >> 2, kq = lin & 3;
            aReg[l] = *(const float4*)(A + (size_t)(m0 + arow)*K + kt*16 + kq*4);
        }
#pragma unroll
        for (int l = 0; l < 16; l++) {
            int lin = tid + l*128;
            int kr = lin >> 7, col = lin & 127;
            int n  = n0 + col;
            bReg[l] = (n < N) ? W[(size_t)(kt*16 + kr)*N + n] : 0.f;
        }
    };
    auto storeS = [&](int buf) {
#pragma unroll
        for (int l = 0; l < 2; l++) {
            int lin = tid*2 + l;
            int arow = lin >> 2, kq = lin & 3;
            As[buf][kq*4+0][arow] = aReg[l].x;
            As[buf][kq*4+1][arow] = aReg[l].y;
            As[buf][kq*4+2][arow] = aReg[l].z;
            As[buf][kq*4+3][arow] = aReg[l].w;
        }
#pragma unroll
        for (int l = 0; l < 16; l++) {
            int lin = tid + l*128;
            int kr = lin >> 7, col = lin & 127;
            Bs[buf][kr][col] = bReg[l];
        }
    };

    loadG(0);
    storeS(0);
    __syncthreads();
    int buf = 0;
    for (int kt = 0; kt < KT; kt++) {
        if (kt + 1 < KT) loadG(kt + 1);
#pragma unroll
        for (int k = 0; k < 16; k++) {
            float a[8], bb[8];
            float4 t0 = *(const float4*)&As[buf][k][ty*8];
            float4 t1 = *(const float4*)&As[buf][k][ty*8 + 4];
            a[0]=t0.x; a[1]=t0.y; a[2]=t0.z; a[3]=t0.w;
            a[4]=t1.x; a[5]=t1.y; a[6]=t1.z; a[7]=t1.w;
            float4 u0 = *(const float4*)&Bs[buf][k][tx*8];
            float4 u1 = *(const float4*)&Bs[buf][k][tx*8 + 4];
            bb[0]=u0.x; bb[1]=u0.y; bb[2]=u0.z; bb[3]=u0.w;
            bb[4]=u1.x; bb[5]=u1.y; bb[6]=u1.z; bb[7]=u1.w;
#pragma unroll
            for (int i = 0; i < 8; i++)
#pragma unroll
                for (int j = 0; j < 8; j++)
                    acc[i][j] += a[i]*bb[j];
        }
        if (kt + 1 < KT) storeS(buf ^ 1);
        __syncthreads();
        buf ^= 1;
    }

#pragma unroll
    for (int i = 0; i < 8; i++) {
        int r = m0 + ty*8 + i;
#pragma unroll
        for (int j = 0; j < 8; j++) {
            int n = n0 + tx*8 + j;
            if (n < N) {
                float v = acc[i][j] + bias[n];
                if (MODE == 1) v += res[(size_t)r*N + n];
                if (MODE == 3) v += res[(size_t)(r & (NT-1))*N + n];
                if (MODE == 2) v = 0.5f*v*(1.f + erff(v*0.70710678118654752f));
                C[(size_t)r*N + n] = v;
            }
        }
    }
}

// ---------------- layernorm (tf32-rounded output; feeds GEMM A) ---------------
__global__ void __launch_bounds__(256)
ln_kernel(const float* __restrict__ x, const float* __restrict__ w,
          const float* __restrict__ b, float* __restrict__ y)
{
    __shared__ float red[8];
    __shared__ float sMean, sRstd;
    int r = blockIdx.x, tid = threadIdx.x;
    const float* xr = x + (size_t)r*DM;
    float v0 = xr[tid], v1 = xr[tid+256], v2 = xr[tid+512];

    float s = v0 + v1 + v2;
#pragma unroll
    for (int o = 16; o > 0; o >>= 1) s += __shfl_xor_sync(0xffffffffu, s, o);
    if ((tid & 31) == 0) red[tid >> 5] = s;
    __syncthreads();
    if (tid == 0) {
        float t = 0.f;
#pragma unroll
        for (int i = 0; i < 8; i++) t += red[i];
        sMean = t * (1.f/768.f);
    }
    __syncthreads();
    float mean = sMean;
    float d0 = v0-mean, d1 = v1-mean, d2 = v2-mean;

    float q = d0*d0 + d1*d1 + d2*d2;
#pragma unroll
    for (int o = 16; o > 0; o >>= 1) q += __shfl_xor_sync(0xffffffffu, q, o);
    if ((tid & 31) == 0) red[tid >> 5] = q;
    __syncthreads();
    if (tid == 0) {
        float t = 0.f;
#pragma unroll
        for (int i = 0; i < 8; i++) t += red[i];
        sRstd = rsqrtf(t * (1.f/768.f) + 1e-5f);
    }
    __syncthreads();
    float rstd = sRstd;
    float* yr = y + (size_t)r*DM;
    yr[tid]     = rtf(d0*rstd*w[tid]     + b[tid]);
    yr[tid+256] = rtf(d1*rstd*w[tid+256] + b[tid+256]);
    yr[tid+512] = rtf(d2*rstd*w[tid+512] + b[tid+512]);
}

// LN for FPN head (feeds SIMT sgemm — keep full fp32)
__global__ void __launch_bounds__(256)
ln_kernel_fp(const float* __restrict__ x, const float* __restrict__ w,
             const float* __restrict__ b, float* __restrict__ y)
{
    __shared__ float red[8];
    __shared__ float sMean, sRstd;
    int r = blockIdx.x, tid = threadIdx.x;
    const float* xr = x + (size_t)r*DM;
    float v0 = xr[tid], v1 = xr[tid+256], v2 = xr[tid+512];
    float s = v0 + v1 + v2;
#pragma unroll
    for (int o = 16; o > 0; o >>= 1) s += __shfl_xor_sync(0xffffffffu, s, o);
    if ((tid & 31) == 0) red[tid >> 5] = s;
    __syncthreads();
    if (tid == 0) {
        float t = 0.f;
#pragma unroll
        for (int i = 0; i < 8; i++) t += red[i];
        sMean = t * (1.f/768.f);
    }
    __syncthreads();
    float mean = sMean;
    float d0 = v0-mean, d1 = v1-mean, d2 = v2-mean;
    float q = d0*d0 + d1*d1 + d2*d2;
#pragma unroll
    for (int o = 16; o > 0; o >>= 1) q += __shfl_xor_sync(0xffffffffu, q, o);
    if ((tid & 31) == 0) red[tid >> 5] = q;
    __syncthreads();
    if (tid == 0) {
        float t = 0.f;
#pragma unroll
        for (int i = 0; i < 8; i++) t += red[i];
        sRstd = rsqrtf(t * (1.f/768.f) + 1e-5f);
    }
    __syncthreads();
    float rstd = sRstd;
    float* yr = y + (size_t)r*DM;
    yr[tid]     = d0*rstd*w[tid]     + b[tid];
    yr[tid+256] = d1*rstd*w[tid+256] + b[tid+256];
    yr[tid+512] = d2*rstd*w[tid+512] + b[tid+512];
}

// ---------------- FPN transpose + clamped bilinear resize (JAX half-pixel) ----
__global__ void fpn_resize_kernel(const float* __restrict__ g, float* __restrict__ out,
                                  int C, int TS)
{
    int idx = blockIdx.x * 256 + threadIdx.x;
    int total = BT*C*TS*TS;
    if (idx >= total) return;
    int xq = idx % TS;
    int yq = (idx / TS) % TS;
    int c  = (idx / (TS*TS)) % C;
    int b  = idx / (TS*TS*C);
    float s  = 32.0f / (float)TS;
    float sy = ((float)yq + 0.5f)*s - 0.5f;
    float sx = ((float)xq + 0.5f)*s - 0.5f;
    int y0 = (int)floorf(sy); float fy = sy - (float)y0;
    int x0 = (int)floorf(sx); float fx = sx - (float)x0;
    int y0c = min(31, max(0, y0)),   y1c = min(31, max(0, y0+1));
    int x0c = min(31, max(0, x0)),   x1c = min(31, max(0, x0+1));
    const float* gb = g + (size_t)b*1024*C;
    float p00 = gb[(y0c*32 + x0c)*C + c];
    float p01 = gb[(y0c*32 + x1c)*C + c];
    float p10 = gb[(y1c*32 + x0c)*C + c];
    float p11 = gb[(y1c*32 + x1c)*C + c];
    out[idx] = (1.f-fy)*((1.f-fx)*p00 + fx*p01) + fy*((1.f-fx)*p10 + fx*p11);
}

// ---------------- host launcher ----------------
extern "C" void kernel_launch(void* const* d_in, const int* in_sizes, int n_in,
                              void* d_out, int out_size)
{
    (void)in_sizes; (void)n_in; (void)out_size;
    const float* x       = (const float*)d_in[0];
    const float* patch_w = (const float*)d_in[1];
    const float* patch_b = (const float*)d_in[2];
    const float* pos     = (const float*)d_in[3];
    const float* ln1_w   = (const float*)d_in[4];
    const float* ln1_b   = (const float*)d_in[5];
    const float* qkv_w   = (const float*)d_in[6];
    const float* qkv_b   = (const float*)d_in[7];
    const float* proj_w  = (const float*)d_in[8];
    const float* proj_b  = (const float*)d_in[9];
    const float* ln2_w   = (const float*)d_in[10];
    const float* ln2_b   = (const float*)d_in[11];
    const float* fc1_w   = (const float*)d_in[12];
    const float* fc1_b   = (const float*)d_in[13];
    const float* fc2_w   = (const float*)d_in[14];
    const float* fc2_b   = (const float*)d_in[15];
    const float* norm_w  = (const float*)d_in[16];
    const float* norm_b  = (const float*)d_in[17];
    const float* fpn_w[4] = {(const float*)d_in[18], (const float*)d_in[20],
                             (const float*)d_in[22], (const float*)d_in[24]};
    const float* fpn_b[4] = {(const float*)d_in[19], (const float*)d_in[21],
                             (const float*)d_in[23], (const float*)d_in[25]};
    float* out = (float*)d_out;

    static float *p_xp = nullptr, *p_t, *p_h, *p_qkv, *p_attn, *p_mlp, *p_fpn;
    static float *p_patchw, *p_qkvw, *p_projw, *p_fc1w, *p_fc2w;
    if (!p_xp) {  // one-time pointer lookup + smem attributes (outside capture)
        cudaGetSymbolAddress((void**)&p_xp,   g_xp);
        cudaGetSymbolAddress((void**)&p_t,    g_t);
        cudaGetSymbolAddress((void**)&p_h,    g_h);
        cudaGetSymbolAddress((void**)&p_qkv,  g_qkv);
        cudaGetSymbolAddress((void**)&p_attn, g_attn);
        cudaGetSymbolAddress((void**)&p_mlp,  g_mlp);
        cudaGetSymbolAddress((void**)&p_fpn,  g_fpn);
        cudaGetSymbolAddress((void**)&p_patchw, g_patchw);
        cudaGetSymbolAddress((void**)&p_qkvw,   g_qkvw);
        cudaGetSymbolAddress((void**)&p_projw,  g_projw);
        cudaGetSymbolAddress((void**)&p_fc1w,   g_fc1w);
        cudaGetSymbolAddress((void**)&p_fc2w,   g_fc2w);
        cudaFuncSetAttribute(tcgemm<0>, cudaFuncAttributeMaxDynamicSharedMemorySize, SMEM_TC);
        cudaFuncSetAttribute(tcgemm<1>, cudaFuncAttributeMaxDynamicSharedMemorySize, SMEM_TC);
        cudaFuncSetAttribute(tcgemm<2>, cudaFuncAttributeMaxDynamicSharedMemorySize, SMEM_TC);
        cudaFuncSetAttribute(tcgemm<3>, cudaFuncAttributeMaxDynamicSharedMemorySize, SMEM_TC);
        cudaFuncSetAttribute(tcgemm<5>, cudaFuncAttributeMaxDynamicSharedMemorySize, SMEM_TC);
        cudaFuncSetAttribute(attn_mma,  cudaFuncAttributeMaxDynamicSharedMemorySize, SMEM_AT);
    }

    // pre-round all transformer weights to tf32 (once per call)
    {
        int n;
        n = DM*DM/4;              round_tf32_kernel<<<(n+255)/256, 256>>>(patch_w, p_patchw, n);
        n = DEPTHL*DM*3*DM/4;     round_tf32_kernel<<<(n+255)/256, 256>>>(qkv_w,   p_qkvw,   n);
        n = DEPTHL*DM*DM/4;       round_tf32_kernel<<<(n+255)/256, 256>>>(proj_w,  p_projw,  n);
        n = DEPTHL*DM*HIDF/4;     round_tf32_kernel<<<(n+255)/256, 256>>>(fc1_w,   p_fc1w,   n);
        n = DEPTHL*HIDF*DM/4;     round_tf32_kernel<<<(n+255)/256, 256>>>(fc2_w,   p_fc2w,   n);
    }

    // patch embed: t = xp @ patch_w + patch_b + pos_embed
    patchify_kernel<<<(RR*DM + 255)/256, 256>>>(x, p_xp);
    tcgemm<3><<<dim3(6, 16), 256, SMEM_TC>>>(p_xp, p_patchw, patch_b, pos, p_t, DM, DM);

    static const size_t off[4] = {0, 3145728, 4718592, 5505024};

    for (int i = 0; i < DEPTHL; i++) {
        ln_kernel<<<RR, 256>>>(p_t, ln1_w + i*DM, ln1_b + i*DM, p_h);
        tcgemm<5><<<dim3(18, 16), 256, SMEM_TC>>>(p_h, p_qkvw + (size_t)i*DM*3*DM,
                                                  qkv_b + (size_t)i*3*DM, nullptr,
                                                  p_qkv, 3*DM, DM);
        attn_mma<<<dim3(BT*NHEADS, NT/128), 128, SMEM_AT>>>(p_qkv, p_attn);
        tcgemm<1><<<dim3(6, 16), 256, SMEM_TC>>>(p_attn, p_projw + (size_t)i*DM*DM,
                                                 proj_b + (size_t)i*DM, p_t, p_t, DM, DM);
        ln_kernel<<<RR, 256>>>(p_t, ln2_w + i*DM, ln2_b + i*DM, p_h);
        tcgemm<2><<<dim3(24, 16), 256, SMEM_TC>>>(p_h, p_fc1w + (size_t)i*DM*HIDF,
                                                  fc1_b + (size_t)i*HIDF, nullptr,
                                                  p_mlp, HIDF, DM);
        tcgemm<1><<<dim3(6, 16), 256, SMEM_TC>>>(p_mlp, p_fc2w + (size_t)i*HIDF*DM,
                                                 fc2_b + (size_t)i*DM, p_t, p_t, DM, HIDF);

        int e = (i == 3) ? 0 : (i == 6) ? 1 : (i == 9) ? 2 : (i == 11) ? 3 : -1;
        if (e >= 0) {
            int oc = 96 << e, ts = 128 >> e;
            ln_kernel_fp<<<RR, 256>>>(p_t, norm_w, norm_b, p_fpn);
            sgemm_kernel<0><<<dim3((oc + 127)/128, 32), 128>>>(p_fpn, fpn_w[e], fpn_b[e],
                                                               nullptr, p_h, RR, oc, DM);
            int total = BT*oc*ts*ts;
            fpn_resize_kernel<<<(total + 255)/256, 256>>>(p_h, out + off[e], oc, ts);
        }
    }
}

// round 17
// speedup vs baseline: 4.0680x; 1.0689x over previous
#include <cuda_runtime.h>
#include <math.h>
#include <stdint.h>

#define DEPTHL 12
#define DM     768
#define NT     1024
#define BT     2
#define RR     (BT*NT)      // 2048 rows
#define HIDF   3072
#define NHEADS 12
#define DHD    64

// ---------------- scratch (static device globals; no allocation) ----------------
__device__ float g_xp[RR*DM];
__device__ float g_t[RR*DM];
__device__ float g_h[RR*DM];
__device__ float g_qkv[RR*3*DM];
__device__ float g_attn[RR*DM];
__device__ float g_mlp[RR*HIDF];
__device__ float g_fpn[RR*DM];
__device__ float g_split[4*RR*DM];   // split-K partials (up to 4 splits of N=768)
// pre-rounded (tf32) weights
__device__ float g_patchw[DM*DM];
__device__ float g_qkvw[DEPTHL*DM*3*DM];
__device__ float g_projw[DEPTHL*DM*DM];
__device__ float g_fc1w[DEPTHL*DM*HIDF];
__device__ float g_fc2w[DEPTHL*HIDF*DM];

__device__ __forceinline__ uint32_t f2tf32(float f) {
    uint32_t u;
    asm("cvt.rna.tf32.f32 %0, %1;" : "=r"(u) : "f"(f));
    return u;
}
__device__ __forceinline__ float rtf(float f) { return __uint_as_float(f2tf32(f)); }

// ---------------- patchify: x[B,3,512,512] -> xp[B*N, 768] (tf32-rounded) -----
__global__ void patchify_kernel(const float* __restrict__ x, float* __restrict__ xp) {
    int idx = blockIdx.x * 256 + threadIdx.x;
    if (idx >= RR*DM) return;
    int col = idx % DM;
    int r   = idx / DM;
    int b   = r >> 10, n = r & 1023;
    int gy  = n >> 5,  gx = n & 31;
    int c   = col >> 8;
    int rem = col & 255;
    int py  = rem >> 4, px = rem & 15;
    xp[idx] = rtf(x[((size_t)(b*3 + c)*512 + (gy*16 + py))*512 + (gx*16 + px)]);
}

// ---------------- round fp32 -> tf32-in-fp32 (rna), vectorized ----------------
__global__ void round_tf32_kernel(const float* __restrict__ src,
                                  float* __restrict__ dst, int n4) {
    int i = blockIdx.x * 256 + threadIdx.x;
    if (i >= n4) return;
    float4 v = *(const float4*)(src + (size_t)i*4);
    v.x = rtf(v.x); v.y = rtf(v.y); v.z = rtf(v.z); v.w = rtf(v.w);
    *(float4*)(dst + (size_t)i*4) = v;
}

// ================= tf32 mma.sync GEMM =========================================
// C = A[M,Kslice] @ W[Kslice,N] (slice z of K) + epilogue.
// BM=128, BN=128, BK=32, 256 thr, 8 warps 4x2, warp tile 32x64.
// 2-stage cp.async, 2 CTAs/SM.  Operands pre-rounded tf32.
// lda = A row stride.  blockIdx.z = K-split index (A += z*K cols, W += z*K rows).
// MODE 0: +bias                      1: +bias+res[r,n]
// MODE 2: +bias, GELU (tf32 out)     3: +bias+res[r&1023,n]
// MODE 4: raw partial -> C + z*RR*Nt (no bias/res)
// MODE 5: +bias, x0.125 for col<768, tf32 out  (QKV for mma attention)

__device__ __forceinline__ void mma_tf32(float* d, const uint32_t* a, const uint32_t* b) {
    asm volatile(
        "mma.sync.aligned.m16n8k8.row.col.f32.tf32.tf32.f32 "
        "{%0,%1,%2,%3}, {%4,%5,%6,%7}, {%8,%9}, {%0,%1,%2,%3};"
        : "+f"(d[0]), "+f"(d[1]), "+f"(d[2]), "+f"(d[3])
        : "r"(a[0]), "r"(a[1]), "r"(a[2]), "r"(a[3]), "r"(b[0]), "r"(b[1]));
}
__device__ __forceinline__ uint32_t smem_u32p(const void* p) {
    uint32_t a;
    asm("{ .reg .u64 t; cvta.to.shared.u64 t, %1; cvt.u32.u64 %0, t; }" : "=r"(a) : "l"(p));
    return a;
}
#define CP16(dst, src) \
    asm volatile("cp.async.cg.shared.global [%0], [%1], 16;" :: "r"(dst), "l"(src))
#define CP_COMMIT() asm volatile("cp.async.commit_group;")
#define CP_WAIT1()  asm volatile("cp.async.wait_group 1;" ::: "memory")
#define CP_WAIT0()  asm volatile("cp.async.wait_group 0;" ::: "memory")

#define ASTG 4608                 // 128*36 floats
#define BSTG 4352                 // 32*136 floats
#define STG  (ASTG+BSTG)          // 8960 floats / stage
#define SMEM_TC (2*STG*4)         // 71680 bytes

template<int MODE>
__global__ void __launch_bounds__(256, 2)
tcgemm(const float* __restrict__ A, const float* __restrict__ W,
       const float* __restrict__ bias, const float* __restrict__ res,
       float* __restrict__ C, int Nt, int K, int lda)
{
    extern __shared__ float dyn[];
    const int tid = threadIdx.x;
    const int wid = tid >> 5;
    const int lane = tid & 31;
    const int warp_m = wid >> 1;
    const int warp_n = wid & 1;
    const int r = lane >> 2, cq = lane & 3;
    const int m0 = blockIdx.y * 128;
    const int n0 = blockIdx.x * 128;
    const int NC = K >> 5;
    const int z  = blockIdx.z;

    A += (size_t)z * K;                 // column offset into A
    W += (size_t)z * K * Nt;            // row offset into W
    if (MODE == 4) C += (size_t)z * RR * Nt;

    const uint32_t sbase = smem_u32p(dyn);

    int a_row[4], a_kq[4], b_kr[4], b_nq[4];
#pragma unroll
    for (int i = 0; i < 4; i++) {
        int c = tid + i*256;
        a_row[i] = c >> 3;  a_kq[i] = (c & 7)*4;
        b_kr[i] = c >> 5;   b_nq[i] = (c & 31)*4;
    }

    auto issue = [&](int kc, int st) {
        const uint32_t sA = sbase + (uint32_t)(st*STG)*4u;
        const uint32_t sB = sA + (uint32_t)ASTG*4u;
#pragma unroll
        for (int i = 0; i < 4; i++) {
            const float* src = A + (size_t)(m0 + a_row[i])*lda + kc*32 + a_kq[i];
            CP16(sA + (uint32_t)(a_row[i]*36 + a_kq[i])*4u, src);
        }
#pragma unroll
        for (int i = 0; i < 4; i++) {
            const float* src = W + (size_t)(kc*32 + b_kr[i])*Nt + n0 + b_nq[i];
            CP16(sB + (uint32_t)(b_kr[i]*136 + b_nq[i])*4u, src);
        }
        CP_COMMIT();
    };

    float acc[2][8][4];
#pragma unroll
    for (int mf = 0; mf < 2; mf++)
#pragma unroll
        for (int nf = 0; nf < 8; nf++)
#pragma unroll
            for (int k = 0; k < 4; k++) acc[mf][nf][k] = 0.f;

    issue(0, 0);

    for (int kc = 0; kc < NC; kc++) {
        if (kc + 1 < NC) issue(kc + 1, (kc + 1) & 1);
        else CP_COMMIT();
        CP_WAIT1();
        __syncthreads();

        const int st = kc & 1;
        const uint32_t* Ab = (const uint32_t*)(dyn + st*STG) + (warp_m*32)*36;
        const uint32_t* Bb = (const uint32_t*)(dyn + st*STG + ASTG) + warp_n*64;
#pragma unroll
        for (int kk = 0; kk < 4; kk++) {
            const int ko = kk*8;
            uint32_t afr[2][4];
#pragma unroll
            for (int mf = 0; mf < 2; mf++) {
                int base = (mf*16 + r)*36 + ko + cq;
                afr[mf][0] = Ab[base];
                afr[mf][1] = Ab[base + 8*36];
                afr[mf][2] = Ab[base + 4];
                afr[mf][3] = Ab[base + 8*36 + 4];
            }
#pragma unroll
            for (int nf = 0; nf < 8; nf++) {
                int nn = nf*8 + r;
                uint32_t bfr[2];
                bfr[0] = Bb[(ko + cq)*136 + nn];
                bfr[1] = Bb[(ko + cq + 4)*136 + nn];
                mma_tf32(acc[0][nf], afr[0], bfr);
                mma_tf32(acc[1][nf], afr[1], bfr);
            }
        }
        __syncthreads();
    }

    const int rb = m0 + warp_m*32;
    const int cb = n0 + warp_n*64;
#pragma unroll
    for (int mf = 0; mf < 2; mf++) {
#pragma unroll
        for (int half = 0; half < 2; half++) {
            int row = rb + mf*16 + r + half*8;
            const float* Rrow = nullptr;
            if (MODE == 1) Rrow = res + (size_t)row*Nt;
            if (MODE == 3) Rrow = res + (size_t)(row & (NT-1))*Nt;
            float* Crow = C + (size_t)row*Nt;
#pragma unroll
            for (int nf = 0; nf < 8; nf++) {
                int col = cb + nf*8 + cq*2;
                float v0 = acc[mf][nf][half*2 + 0];
                float v1 = acc[mf][nf][half*2 + 1];
                if (MODE != 4) { v0 += bias[col]; v1 += bias[col + 1]; }
                if (MODE == 1 || MODE == 3) { v0 += Rrow[col]; v1 += Rrow[col+1]; }
                if (MODE == 2) {
                    v0 = rtf(0.5f*v0*(1.f + erff(v0*0.70710678118654752f)));
                    v1 = rtf(0.5f*v1*(1.f + erff(v1*0.70710678118654752f)));
                }
                if (MODE == 5) {
                    float sc = (col < DM) ? 0.125f : 1.0f;   // scale q by 1/sqrt(dh)
                    v0 = rtf(v0*sc);
                    v1 = rtf(v1*sc);
                }
                float2 o; o.x = v0; o.y = v1;
                *(float2*)(Crow + col) = o;
            }
        }
    }
}

// ---- combine split-K partials: C = res + bias + sum_z partial[z] -------------
template<int NS>
__global__ void __launch_bounds__(256)
combineK(const float* __restrict__ scr, const float* __restrict__ bias,
         const float* __restrict__ res, float* __restrict__ C, int Nt)
{
    int i = blockIdx.x*256 + threadIdx.x;        // float4 index over RR*Nt/4
    int total = RR*Nt/4;
    if (i >= total) return;
    int col = (i*4) % Nt;
    float4 a = *(const float4*)(scr + (size_t)i*4);
#pragma unroll
    for (int z = 1; z < NS; z++) {
        float4 p = *(const float4*)(scr + (size_t)z*RR*Nt + (size_t)i*4);
        a.x += p.x; a.y += p.y; a.z += p.z; a.w += p.w;
    }
    float4 rv = *(const float4*)(res + (size_t)i*4);
    a.x += rv.x + bias[col];
    a.y += rv.y + bias[col+1];
    a.z += rv.z + bias[col+2];
    a.w += rv.w + bias[col+3];
    *(float4*)(C + (size_t)i*4) = a;
}

// ================= MMA flash attention ========================================
// grid (B*H, NT/128), block 128 (4 warps x 32 queries).  Full 1024 keys/CTA.
// Q,K,V pre-rounded tf32 (QKV GEMM MODE 5; q pre-scaled by 0.125).
// smem: Qs[128][68] | Ks[64][68] | Vs[64][68] | Ps[4][32][68]
#define AQ_OFF 0
#define AK_OFF 8704
#define AV_OFF 13056
#define AP_OFF 17408
#define SMEM_AT ((17408 + 8704)*4)    // 104448 bytes

__global__ void __launch_bounds__(128)
attn_mma(const float* __restrict__ qkv, float* __restrict__ out)
{
    extern __shared__ float dyn[];
    const int bh = blockIdx.x;
    const int b  = bh / NHEADS, h = bh % NHEADS;
    const int qt = blockIdx.y;
    const int tid = threadIdx.x;
    const int wid = tid >> 5;
    const int lane = tid & 31;
    const int r = lane >> 2, cq = lane & 3;

    const uint32_t sbase = smem_u32p(dyn);

    // ---- load Q tile (128 q-rows x 64 floats = 2048 x 16B chunks) ----
#pragma unroll
    for (int i = 0; i < 16; i++) {
        int c = tid + i*128;
        int row = c >> 4, q4 = (c & 15)*4;
        const float* src = qkv + (size_t)(b*NT + qt*128 + row)*(3*DM) + h*DHD + q4;
        CP16(sbase + (uint32_t)(AQ_OFF + row*68 + q4)*4u, src);
    }
    CP_COMMIT();
    CP_WAIT0();
    __syncthreads();

    float o[2][8][4];
#pragma unroll
    for (int mf = 0; mf < 2; mf++)
#pragma unroll
        for (int nf = 0; nf < 8; nf++)
#pragma unroll
            for (int k = 0; k < 4; k++) o[mf][nf][k] = 0.f;
    float m[2][2]  = {{-3.0e38f,-3.0e38f},{-3.0e38f,-3.0e38f}};
    float lp[2][2] = {{0.f,0.f},{0.f,0.f}};

    const uint32_t* Qw = (const uint32_t*)dyn + AQ_OFF + (wid*32)*68;
    const uint32_t* Ks = (const uint32_t*)dyn + AK_OFF;
    const uint32_t* Vs = (const uint32_t*)dyn + AV_OFF;
    float*          Pw = dyn + AP_OFF + wid*(32*68);
    const uint32_t* Pu = (const uint32_t*)Pw;

    for (int kt = 0; kt < 16; kt++) {
        // ---- load K tile (64 keys x 64 floats = 1024 chunks) ----
#pragma unroll
        for (int i = 0; i < 8; i++) {
            int c = tid + i*128;
            int j = c >> 4, q4 = (c & 15)*4;
            const float* src = qkv + (size_t)(b*NT + kt*64 + j)*(3*DM) + DM + h*DHD + q4;
            CP16(sbase + (uint32_t)(AK_OFF + j*68 + q4)*4u, src);
        }
        // ---- load V tile (64 keys x 64 floats = 1024 chunks) ----
#pragma unroll
        for (int i = 0; i < 8; i++) {
            int c = tid + i*128;
            int j = c >> 4, q4 = (c & 15)*4;
            const float* src = qkv + (size_t)(b*NT + kt*64 + j)*(3*DM) + 2*DM + h*DHD + q4;
            CP16(sbase + (uint32_t)(AV_OFF + j*68 + q4)*4u, src);
        }
        CP_COMMIT();
        CP_WAIT0();
        __syncthreads();

        // ---- S = Q @ K^T  (32x64 per warp) ----
        float s[2][8][4];
#pragma unroll
        for (int mf = 0; mf < 2; mf++)
#pragma unroll
            for (int nf = 0; nf < 8; nf++)
#pragma unroll
                for (int k = 0; k < 4; k++) s[mf][nf][k] = 0.f;
#pragma unroll
        for (int ks = 0; ks < 8; ks++) {
            const int ko = ks*8;
            uint32_t afr[2][4];
#pragma unroll
            for (int mf = 0; mf < 2; mf++) {
                int base = (mf*16 + r)*68 + ko + cq;
                afr[mf][0] = Qw[base];
                afr[mf][1] = Qw[base + 8*68];
                afr[mf][2] = Qw[base + 4];
                afr[mf][3] = Qw[base + 8*68 + 4];
            }
#pragma unroll
            for (int nf = 0; nf < 8; nf++) {
                int nn = nf*8 + r;
                uint32_t bfr[2];
                bfr[0] = Ks[nn*68 + ko + cq];
                bfr[1] = Ks[nn*68 + ko + cq + 4];
                mma_tf32(s[0][nf], afr[0], bfr);
                mma_tf32(s[1][nf], afr[1], bfr);
            }
        }

        // ---- online softmax (rows: mf*16 + r + half*8; cols: nf*8 + 2cq+{0,1}) ----
#pragma unroll
        for (int mf = 0; mf < 2; mf++) {
#pragma unroll
            for (int half = 0; half < 2; half++) {
                float vmax = -3.0e38f;
#pragma unroll
                for (int nf = 0; nf < 8; nf++)
                    vmax = fmaxf(vmax, fmaxf(s[mf][nf][half*2], s[mf][nf][half*2+1]));
                vmax = fmaxf(vmax, __shfl_xor_sync(0xffffffffu, vmax, 1));
                vmax = fmaxf(vmax, __shfl_xor_sync(0xffffffffu, vmax, 2));
                float mnew = fmaxf(m[mf][half], vmax);
                float cc = __expf(m[mf][half] - mnew);
                m[mf][half] = mnew;
                lp[mf][half] *= cc;
#pragma unroll
                for (int nf = 0; nf < 8; nf++) {
                    o[mf][nf][half*2]   *= cc;
                    o[mf][nf][half*2+1] *= cc;
                    float p0 = rtf(__expf(s[mf][nf][half*2]   - mnew));
                    float p1 = rtf(__expf(s[mf][nf][half*2+1] - mnew));
                    lp[mf][half] += p0 + p1;
                    float2 pv; pv.x = p0; pv.y = p1;
                    *(float2*)(Pw + (mf*16 + r + half*8)*68 + nf*8 + 2*cq) = pv;
                }
            }
        }
        __syncwarp();

        // ---- O += P @ V ----
#pragma unroll
        for (int ks = 0; ks < 8; ks++) {
            const int ko = ks*8;
            uint32_t afr[2][4];
#pragma unroll
            for (int mf = 0; mf < 2; mf++) {
                int base = (mf*16 + r)*68 + ko + cq;
                afr[mf][0] = Pu[base];
                afr[mf][1] = Pu[base + 8*68];
                afr[mf][2] = Pu[base + 4];
                afr[mf][3] = Pu[base + 8*68 + 4];
            }
#pragma unroll
            for (int nf = 0; nf < 8; nf++) {
                int nn = nf*8 + r;
                uint32_t bfr[2];
                bfr[0] = Vs[(ko + cq)*68 + nn];
                bfr[1] = Vs[(ko + cq + 4)*68 + nn];
                mma_tf32(o[0][nf], afr[0], bfr);
                mma_tf32(o[1][nf], afr[1], bfr);
            }
        }
        __syncthreads();    // PV done before next tile overwrites K/V
    }

    // ---- finalize: normalize rows and write (tf32-rounded; feeds proj A) ----
#pragma unroll
    for (int mf = 0; mf < 2; mf++) {
#pragma unroll
        for (int half = 0; half < 2; half++) {
            float t = lp[mf][half];
            t += __shfl_xor_sync(0xffffffffu, t, 1);
            t += __shfl_xor_sync(0xffffffffu, t, 2);
            float inv = 1.f / t;
            int row_g = b*NT + qt*128 + wid*32 + mf*16 + r + half*8;
            float* orow = out + (size_t)row_g*DM + h*DHD;
#pragma unroll
            for (int nf = 0; nf < 8; nf++) {
                float2 v;
                v.x = rtf(o[mf][nf][half*2]   * inv);
                v.y = rtf(o[mf][nf][half*2+1] * inv);
                *(float2*)(orow + nf*8 + 2*cq) = v;
            }
        }
    }
}

// ---------------- SIMT SGEMM (FPN heads only) ----------------
template<int MODE>
__global__ void __launch_bounds__(128)
sgemm_kernel(const float* __restrict__ A, const float* __restrict__ W,
             const float* __restrict__ bias, const float* res, float* C,
             int M, int N, int K)
{
    __shared__ float As[2][16][64];
    __shared__ float Bs[2][16][128];
    const int tid = threadIdx.x;
    const int m0  = blockIdx.y * 64;
    const int n0  = blockIdx.x * 128;
    const int tx  = tid & 15, ty = tid >> 4;

    float acc[8][8];
#pragma unroll
    for (int i = 0; i < 8; i++)
#pragma unroll
        for (int j = 0; j < 8; j++) acc[i][j] = 0.f;

    const int KT = K >> 4;
    float4 aReg[2];
    float  bReg[16];

    auto loadG = [&](int kt) {
#pragma unroll
        for (int l = 0; l < 2; l++) {
            int lin = tid*2 + l;
            int arow = lin >> 2, kq = lin & 3;
            aReg[l] = *(const float4*)(A + (size_t)(m0 + arow)*K + kt*16 + kq*4);
        }
#pragma unroll
        for (int l = 0; l < 16; l++) {
            int lin = tid + l*128;
            int kr = lin >> 7, col = lin & 127;
            int n  = n0 + col;
            bReg[l] = (n < N) ? W[(size_t)(kt*16 + kr)*N + n] : 0.f;
        }
    };
    auto storeS = [&](int buf) {
#pragma unroll
        for (int l = 0; l < 2; l++) {
            int lin = tid*2 + l;
            int arow = lin >> 2, kq = lin & 3;
            As[buf][kq*4+0][arow] = aReg[l].x;
            As[buf][kq*4+1][arow] = aReg[l].y;
            As[buf][kq*4+2][arow] = aReg[l].z;
            As[buf][kq*4+3][arow] = aReg[l].w;
        }
#pragma unroll
        for (int l = 0; l < 16; l++) {
            int lin = tid + l*128;
            int kr = lin >> 7, col = lin & 127;
            Bs[buf][kr][col] = bReg[l];
        }
    };

    loadG(0);
    storeS(0);
    __syncthreads();
    int buf = 0;
    for (int kt = 0; kt < KT; kt++) {
        if (kt + 1 < KT) loadG(kt + 1);
#pragma unroll
        for (int k = 0; k < 16; k++) {
            float a[8], bb[8];
            float4 t0 = *(const float4*)&As[buf][k][ty*8];
            float4 t1 = *(const float4*)&As[buf][k][ty*8 + 4];
            a[0]=t0.x; a[1]=t0.y; a[2]=t0.z; a[3]=t0.w;
            a[4]=t1.x; a[5]=t1.y; a[6]=t1.z; a[7]=t1.w;
            float4 u0 = *(const float4*)&Bs[buf][k][tx*8];
            float4 u1 = *(const float4*)&Bs[buf][k][tx*8 + 4];
            bb[0]=u0.x; bb[1]=u0.y; bb[2]=u0.z; bb[3]=u0.w;
            bb[4]=u1.x; bb[5]=u1.y; bb[6]=u1.z; bb[7]=u1.w;
#pragma unroll
            for (int i = 0; i < 8; i++)
#pragma unroll
                for (int j = 0; j < 8; j++)
                    acc[i][j] += a[i]*bb[j];
        }
        if (kt + 1 < KT) storeS(buf ^ 1);
        __syncthreads();
        buf ^= 1;
    }

#pragma unroll
    for (int i = 0; i < 8; i++) {
        int r = m0 + ty*8 + i;
#pragma unroll
        for (int j = 0; j < 8; j++) {
            int n = n0 + tx*8 + j;
            if (n < N) {
                float v = acc[i][j] + bias[n];
                if (MODE == 1) v += res[(size_t)r*N + n];
                if (MODE == 3) v += res[(size_t)(r & (NT-1))*N + n];
                if (MODE == 2) v = 0.5f*v*(1.f + erff(v*0.70710678118654752f));
                C[(size_t)r*N + n] = v;
            }
        }
    }
}

// ---------------- layernorm (tf32-rounded output; feeds GEMM A) ---------------
__global__ void __launch_bounds__(256)
ln_kernel(const float* __restrict__ x, const float* __restrict__ w,
          const float* __restrict__ b, float* __restrict__ y)
{
    __shared__ float red[8];
    __shared__ float sMean, sRstd;
    int r = blockIdx.x, tid = threadIdx.x;
    const float* xr = x + (size_t)r*DM;
    float v0 = xr[tid], v1 = xr[tid+256], v2 = xr[tid+512];

    float s = v0 + v1 + v2;
#pragma unroll
    for (int o = 16; o > 0; o >>= 1) s += __shfl_xor_sync(0xffffffffu, s, o);
    if ((tid & 31) == 0) red[tid >> 5] = s;
    __syncthreads();
    if (tid == 0) {
        float t = 0.f;
#pragma unroll
        for (int i = 0; i < 8; i++) t += red[i];
        sMean = t * (1.f/768.f);
    }
    __syncthreads();
    float mean = sMean;
    float d0 = v0-mean, d1 = v1-mean, d2 = v2-mean;

    float q = d0*d0 + d1*d1 + d2*d2;
#pragma unroll
    for (int o = 16; o > 0; o >>= 1) q += __shfl_xor_sync(0xffffffffu, q, o);
    if ((tid & 31) == 0) red[tid >> 5] = q;
    __syncthreads();
    if (tid == 0) {
        float t = 0.f;
#pragma unroll
        for (int i = 0; i < 8; i++) t += red[i];
        sRstd = rsqrtf(t * (1.f/768.f) + 1e-5f);
    }
    __syncthreads();
    float rstd = sRstd;
    float* yr = y + (size_t)r*DM;
    yr[tid]     = rtf(d0*rstd*w[tid]     + b[tid]);
    yr[tid+256] = rtf(d1*rstd*w[tid+256] + b[tid+256]);
    yr[tid+512] = rtf(d2*rstd*w[tid+512] + b[tid+512]);
}

// LN for FPN head (feeds SIMT sgemm — keep full fp32)
__global__ void __launch_bounds__(256)
ln_kernel_fp(const float* __restrict__ x, const float* __restrict__ w,
             const float* __restrict__ b, float* __restrict__ y)
{
    __shared__ float red[8];
    __shared__ float sMean, sRstd;
    int r = blockIdx.x, tid = threadIdx.x;
    const float* xr = x + (size_t)r*DM;
    float v0 = xr[tid], v1 = xr[tid+256], v2 = xr[tid+512];
    float s = v0 + v1 + v2;
#pragma unroll
    for (int o = 16; o > 0; o >>= 1) s += __shfl_xor_sync(0xffffffffu, s, o);
    if ((tid & 31) == 0) red[tid >> 5] = s;
    __syncthreads();
    if (tid == 0) {
        float t = 0.f;
#pragma unroll
        for (int i = 0; i < 8; i++) t += red[i];
        sMean = t * (1.f/768.f);
    }
    __syncthreads();
    float mean = sMean;
    float d0 = v0-mean, d1 = v1-mean, d2 = v2-mean;
    float q = d0*d0 + d1*d1 + d2*d2;
#pragma unroll
    for (int o = 16; o > 0; o >>= 1) q += __shfl_xor_sync(0xffffffffu, q, o);
    if ((tid & 31) == 0) red[tid >> 5] = q;
    __syncthreads();
    if (tid == 0) {
        float t = 0.f;
#pragma unroll
        for (int i = 0; i < 8; i++) t += red[i];
        sRstd = rsqrtf(t * (1.f/768.f) + 1e-5f);
    }
    __syncthreads();
    float rstd = sRstd;
    float* yr = y + (size_t)r*DM;
    yr[tid]     = d0*rstd*w[tid]     + b[tid];
    yr[tid+256] = d1*rstd*w[tid+256] + b[tid+256];
    yr[tid+512] = d2*rstd*w[tid+512] + b[tid+512];
}

// ---------------- FPN transpose + clamped bilinear resize (JAX half-pixel) ----
__global__ void fpn_resize_kernel(const float* __restrict__ g, float* __restrict__ out,
                                  int C, int TS)
{
    int idx = blockIdx.x * 256 + threadIdx.x;
    int total = BT*C*TS*TS;
    if (idx >= total) return;
    int xq = idx % TS;
    int yq = (idx / TS) % TS;
    int c  = (idx / (TS*TS)) % C;
    int b  = idx / (TS*TS*C);
    float s  = 32.0f / (float)TS;
    float sy = ((float)yq + 0.5f)*s - 0.5f;
    float sx = ((float)xq + 0.5f)*s - 0.5f;
    int y0 = (int)floorf(sy); float fy = sy - (float)y0;
    int x0 = (int)floorf(sx); float fx = sx - (float)x0;
    int y0c = min(31, max(0, y0)),   y1c = min(31, max(0, y0+1));
    int x0c = min(31, max(0, x0)),   x1c = min(31, max(0, x0+1));
    const float* gb = g + (size_t)b*1024*C;
    float p00 = gb[(y0c*32 + x0c)*C + c];
    float p01 = gb[(y0c*32 + x1c)*C + c];
    float p10 = gb[(y1c*32 + x0c)*C + c];
    float p11 = gb[(y1c*32 + x1c)*C + c];
    out[idx] = (1.f-fy)*((1.f-fx)*p00 + fx*p01) + fy*((1.f-fx)*p10 + fx*p11);
}

// ---------------- host launcher ----------------
extern "C" void kernel_launch(void* const* d_in, const int* in_sizes, int n_in,
                              void* d_out, int out_size)
{
    (void)in_sizes; (void)n_in; (void)out_size;
    const float* x       = (const float*)d_in[0];
    const float* patch_w = (const float*)d_in[1];
    const float* patch_b = (const float*)d_in[2];
    const float* pos     = (const float*)d_in[3];
    const float* ln1_w   = (const float*)d_in[4];
    const float* ln1_b   = (const float*)d_in[5];
    const float* qkv_w   = (const float*)d_in[6];
    const float* qkv_b   = (const float*)d_in[7];
    const float* proj_w  = (const float*)d_in[8];
    const float* proj_b  = (const float*)d_in[9];
    const float* ln2_w   = (const float*)d_in[10];
    const float* ln2_b   = (const float*)d_in[11];
    const float* fc1_w   = (const float*)d_in[12];
    const float* fc1_b   = (const float*)d_in[13];
    const float* fc2_w   = (const float*)d_in[14];
    const float* fc2_b   = (const float*)d_in[15];
    const float* norm_w  = (const float*)d_in[16];
    const float* norm_b  = (const float*)d_in[17];
    const float* fpn_w[4] = {(const float*)d_in[18], (const float*)d_in[20],
                             (const float*)d_in[22], (const float*)d_in[24]};
    const float* fpn_b[4] = {(const float*)d_in[19], (const float*)d_in[21],
                             (const float*)d_in[23], (const float*)d_in[25]};
    float* out = (float*)d_out;

    static float *p_xp = nullptr, *p_t, *p_h, *p_qkv, *p_attn, *p_mlp, *p_fpn, *p_split;
    static float *p_patchw, *p_qkvw, *p_projw, *p_fc1w, *p_fc2w;
    if (!p_xp) {  // one-time pointer lookup + smem attributes (outside capture)
        cudaGetSymbolAddress((void**)&p_xp,   g_xp);
        cudaGetSymbolAddress((void**)&p_t,    g_t);
        cudaGetSymbolAddress((void**)&p_h,    g_h);
        cudaGetSymbolAddress((void**)&p_qkv,  g_qkv);
        cudaGetSymbolAddress((void**)&p_attn, g_attn);
        cudaGetSymbolAddress((void**)&p_mlp,  g_mlp);
        cudaGetSymbolAddress((void**)&p_fpn,  g_fpn);
        cudaGetSymbolAddress((void**)&p_split, g_split);
        cudaGetSymbolAddress((void**)&p_patchw, g_patchw);
        cudaGetSymbolAddress((void**)&p_qkvw,   g_qkvw);
        cudaGetSymbolAddress((void**)&p_projw,  g_projw);
        cudaGetSymbolAddress((void**)&p_fc1w,   g_fc1w);
        cudaGetSymbolAddress((void**)&p_fc2w,   g_fc2w);
        cudaFuncSetAttribute(tcgemm<0>, cudaFuncAttributeMaxDynamicSharedMemorySize, SMEM_TC);
        cudaFuncSetAttribute(tcgemm<1>, cudaFuncAttributeMaxDynamicSharedMemorySize, SMEM_TC);
        cudaFuncSetAttribute(tcgemm<2>, cudaFuncAttributeMaxDynamicSharedMemorySize, SMEM_TC);
        cudaFuncSetAttribute(tcgemm<3>, cudaFuncAttributeMaxDynamicSharedMemorySize, SMEM_TC);
        cudaFuncSetAttribute(tcgemm<4>, cudaFuncAttributeMaxDynamicSharedMemorySize, SMEM_TC);
        cudaFuncSetAttribute(tcgemm<5>, cudaFuncAttributeMaxDynamicSharedMemorySize, SMEM_TC);
        cudaFuncSetAttribute(attn_mma,  cudaFuncAttributeMaxDynamicSharedMemorySize, SMEM_AT);
    }

    // pre-round all transformer weights to tf32 (once per call)
    {
        int n;
        n = DM*DM/4;              round_tf32_kernel<<<(n+255)/256, 256>>>(patch_w, p_patchw, n);
        n = DEPTHL*DM*3*DM/4;     round_tf32_kernel<<<(n+255)/256, 256>>>(qkv_w,   p_qkvw,   n);
        n = DEPTHL*DM*DM/4;       round_tf32_kernel<<<(n+255)/256, 256>>>(proj_w,  p_projw,  n);
        n = DEPTHL*DM*HIDF/4;     round_tf32_kernel<<<(n+255)/256, 256>>>(fc1_w,   p_fc1w,   n);
        n = DEPTHL*HIDF*DM/4;     round_tf32_kernel<<<(n+255)/256, 256>>>(fc2_w,   p_fc2w,   n);
    }

    // patch embed: t = xp @ patch_w + patch_b + pos_embed
    patchify_kernel<<<(RR*DM + 255)/256, 256>>>(x, p_xp);
    tcgemm<3><<<dim3(6, 16), 256, SMEM_TC>>>(p_xp, p_patchw, patch_b, pos, p_t, DM, DM, DM);

    static const size_t off[4] = {0, 3145728, 4718592, 5505024};
    const int NC4 = (RR*DM/4 + 255)/256;

    for (int i = 0; i < DEPTHL; i++) {
        ln_kernel<<<RR, 256>>>(p_t, ln1_w + i*DM, ln1_b + i*DM, p_h);
        tcgemm<5><<<dim3(18, 16), 256, SMEM_TC>>>(p_h, p_qkvw + (size_t)i*DM*3*DM,
                                                  qkv_b + (size_t)i*3*DM, nullptr,
                                                  p_qkv, 3*DM, DM, DM);
        attn_mma<<<dim3(BT*NHEADS, NT/128), 128, SMEM_AT>>>(p_qkv, p_attn);
        // proj: split-K x2 (Kslice=384) -> partials -> combine(+bias+res) into p_t
        tcgemm<4><<<dim3(6, 16, 2), 256, SMEM_TC>>>(p_attn, p_projw + (size_t)i*DM*DM,
                                                    nullptr, nullptr,
                                                    p_split, DM, 384, DM);
        combineK<2><<<NC4, 256>>>(p_split, proj_b + (size_t)i*DM, p_t, p_t, DM);
        ln_kernel<<<RR, 256>>>(p_t, ln2_w + i*DM, ln2_b + i*DM, p_h);
        tcgemm<2><<<dim3(24, 16), 256, SMEM_TC>>>(p_h, p_fc1w + (size_t)i*DM*HIDF,
                                                  fc1_b + (size_t)i*HIDF, nullptr,
                                                  p_mlp, HIDF, DM, DM);
        // fc2: split-K x4 (Kslice=768) -> partials -> combine(+bias+res) into p_t
        tcgemm<4><<<dim3(6, 16, 4), 256, SMEM_TC>>>(p_mlp, p_fc2w + (size_t)i*HIDF*DM,
                                                    nullptr, nullptr,
                                                    p_split, DM, 768, HIDF);
        combineK<4><<<NC4, 256>>>(p_split, fc2_b + (size_t)i*DM, p_t, p_t, DM);

        int e = (i == 3) ? 0 : (i == 6) ? 1 : (i == 9) ? 2 : (i == 11) ? 3 : -1;
        if (e >= 0) {
            int oc = 96 << e, ts = 128 >> e;
            ln_kernel_fp<<<RR, 256>>>(p_t, norm_w, norm_b, p_fpn);
            sgemm_kernel<0><<<dim3((oc + 127)/128, 32), 128>>>(p_fpn, fpn_w[e], fpn_b[e],
                                                               nullptr, p_h, RR, oc, DM);
            int total = BT*oc*ts*ts;
            fpn_resize_kernel<<<(total + 255)/256, 256>>>(p_h, out + off[e], oc, ts);
        }
    }
}